// round 1
// baseline (speedup 1.0000x reference)
#include <cuda_runtime.h>

#define BB 2
#define TT 4096
#define HH 16
#define DD 128
#define HDIM 2048
#define O3 6144
#define NCH 64
#define CH 64

// ---------------- scratch (static device globals; no runtime allocation) ----
static __device__ float g_qkv[(size_t)BB * TT * O3];          // (bt, o)
static __device__ float g_q[(size_t)BB * HH * TT * DD];       // (b,h,t,d)
static __device__ float g_k[(size_t)BB * HH * TT * DD];
static __device__ float g_v[(size_t)BB * HH * TT * DD];
static __device__ float g_o[(size_t)BB * HH * TT * DD];
static __device__ float g_gate[(size_t)BB * TT * HDIM];       // (bt, hd) sigmoid'ed
static __device__ float g_on[(size_t)BB * TT * HDIM];         // normalized+gated o
static __device__ float g_U[(size_t)BB * HH * NCH * DD * DD]; // per-chunk KV outer
static __device__ float g_S[(size_t)BB * HH * NCH * DD * DD]; // scanned state

__device__ __forceinline__ float head_slope(int h) {
    // match reference: f32(alibi) promoted to f64, * scale, cast back to f32
    float a = (float)exp2(-0.5 * (double)(h + 1));
    return (float)(-(double)a * (1.0 - 11.0 / 31.0 + 1e-5));
}

// ---------------- fp32 SGEMM, C[M,N] = A[M,K] * B[N,K]^T (NT), act: 0=none 1=sigmoid
__global__ void __launch_bounds__(256) sgemm_nt(const float* __restrict__ A,
                                                const float* __restrict__ Bm,
                                                float* __restrict__ C,
                                                int M, int N, int K, int act) {
    __shared__ __align__(16) float As[16 * 132];
    __shared__ __align__(16) float Bs[16 * 132];
    const int tid = threadIdx.x;
    const int tx = tid & 15, ty = tid >> 4;
    const float* Ab = A + (size_t)blockIdx.y * 128 * K;
    const float* Bb = Bm + (size_t)blockIdx.x * 128 * K;

    float acc[8][8];
#pragma unroll
    for (int i = 0; i < 8; i++)
#pragma unroll
        for (int j = 0; j < 8; j++) acc[i][j] = 0.f;

    for (int kt = 0; kt < K; kt += 16) {
#pragma unroll
        for (int l = 0; l < 2; l++) {
            int idx = tid + l * 256;          // 512 float4s (128 rows x 4)
            int row = idx >> 2;
            int c0 = (idx & 3) << 2;
            float4 a = *(const float4*)(Ab + (size_t)row * K + kt + c0);
            float4 b = *(const float4*)(Bb + (size_t)row * K + kt + c0);
            As[(c0 + 0) * 132 + row] = a.x;
            As[(c0 + 1) * 132 + row] = a.y;
            As[(c0 + 2) * 132 + row] = a.z;
            As[(c0 + 3) * 132 + row] = a.w;
            Bs[(c0 + 0) * 132 + row] = b.x;
            Bs[(c0 + 1) * 132 + row] = b.y;
            Bs[(c0 + 2) * 132 + row] = b.z;
            Bs[(c0 + 3) * 132 + row] = b.w;
        }
        __syncthreads();
#pragma unroll
        for (int kk = 0; kk < 16; kk++) {
            float a[8], b[8];
            *(float4*)(a) = *(const float4*)&As[kk * 132 + ty * 8];
            *(float4*)(a + 4) = *(const float4*)&As[kk * 132 + ty * 8 + 4];
            *(float4*)(b) = *(const float4*)&Bs[kk * 132 + tx * 8];
            *(float4*)(b + 4) = *(const float4*)&Bs[kk * 132 + tx * 8 + 4];
#pragma unroll
            for (int i = 0; i < 8; i++)
#pragma unroll
                for (int j = 0; j < 8; j++) acc[i][j] += a[i] * b[j];
        }
        __syncthreads();
    }

#pragma unroll
    for (int i = 0; i < 8; i++) {
        float* Cr = C + (size_t)(blockIdx.y * 128 + ty * 8 + i) * N + blockIdx.x * 128 + tx * 8;
        float v[8];
#pragma unroll
        for (int j = 0; j < 8; j++) {
            float x = acc[i][j];
            v[j] = act ? (1.f / (1.f + expf(-x))) : x;
        }
        *(float4*)(Cr) = make_float4(v[0], v[1], v[2], v[3]);
        *(float4*)(Cr + 4) = make_float4(v[4], v[5], v[6], v[7]);
    }
}

// ---------------- split qkv + per-head rmsnorm + rope; one warp per (b,t,h) --
__global__ void __launch_bounds__(128) k_norm_rope(const float* __restrict__ qw,
                                                   const float* __restrict__ kw,
                                                   const int* __restrict__ pos) {
    int warp = blockIdx.x * 4 + (threadIdx.x >> 5);
    int lane = threadIdx.x & 31;
    int h = warp & (HH - 1);
    int bt = warp >> 4;
    size_t base = (size_t)bt * O3 + h * DD + lane * 4;

    float4 q4 = *(const float4*)(g_qkv + base);
    float4 k4 = *(const float4*)(g_qkv + base + HDIM);
    float4 v4 = *(const float4*)(g_qkv + base + 2 * HDIM);
    float qv[4] = {q4.x, q4.y, q4.z, q4.w};
    float kv[4] = {k4.x, k4.y, k4.z, k4.w};

    float sq = qv[0] * qv[0] + qv[1] * qv[1] + qv[2] * qv[2] + qv[3] * qv[3];
    float sk = kv[0] * kv[0] + kv[1] * kv[1] + kv[2] * kv[2] + kv[3] * kv[3];
#pragma unroll
    for (int off = 16; off > 0; off >>= 1) {
        sq += __shfl_xor_sync(0xffffffffu, sq, off);
        sk += __shfl_xor_sync(0xffffffffu, sk, off);
    }
    float rq = rsqrtf(sq * (1.f / DD) + 1e-6f);
    float rk = rsqrtf(sk * (1.f / DD) + 1e-6f);
    float4 wq = *(const float4*)(qw + lane * 4);
    float4 wk = *(const float4*)(kw + lane * 4);
    float wqa[4] = {wq.x, wq.y, wq.z, wq.w};
    float wka[4] = {wk.x, wk.y, wk.z, wk.w};
#pragma unroll
    for (int j = 0; j < 4; j++) {
        qv[j] = qv[j] * rq * wqa[j];
        kv[j] = kv[j] * rk * wka[j];
    }

    // rope on dims [0,64): lane<16. partner float4 at lane^8
    float p = (float)pos[bt];
    float qp[4], kp[4];
#pragma unroll
    for (int j = 0; j < 4; j++) {
        qp[j] = __shfl_xor_sync(0xffffffffu, qv[j], 8);
        kp[j] = __shfl_xor_sync(0xffffffffu, kv[j], 8);
    }
    if (lane < 16) {
        float sgn = (lane < 8) ? -1.f : 1.f;
        int jb = (lane & 7) * 4;
#pragma unroll
        for (int j = 0; j < 4; j++) {
            float inv = exp2f(-(float)(jb + j) * 0.4152410118609203f); // log2(1e4)/32
            float ang = p * inv;
            float sn, cs;
            sincosf(ang, &sn, &cs);
            qv[j] = qv[j] * cs + sgn * qp[j] * sn;
            kv[j] = kv[j] * cs + sgn * kp[j] * sn;
        }
    }

    int b = bt >> 12, t = bt & (TT - 1);
    size_t ob = ((size_t)(b * HH + h) * TT + t) * DD + lane * 4;
    const float qscale = 0.08838834764831845f; // D^-0.5, folded here
    *(float4*)(g_q + ob) = make_float4(qv[0] * qscale, qv[1] * qscale, qv[2] * qscale, qv[3] * qscale);
    *(float4*)(g_k + ob) = make_float4(kv[0], kv[1], kv[2], kv[3]);
    *(float4*)(g_v + ob) = v4;
}

// ---------------- pass A: per (b,h,c): att(masked), intra = att@v, U = (k*kdec)^T v
#define QK_P 68
__global__ void __launch_bounds__(256, 1) k_chunk_local() {
    extern __shared__ __align__(16) float sm[];
    float* qsT = sm;                 // [128][68]  (d-major)
    float* ksT = qsT + 128 * QK_P;   // [128][68]
    float* vs = ksT + 128 * QK_P;    // [64][128]
    float* att = vs + 64 * 128;      // [64][65]
    float* kdec = att + 64 * 65;     // [64]

    const int tid = threadIdx.x;
    const int c = blockIdx.x & (NCH - 1);
    const int bh = blockIdx.x >> 6;
    const int h = bh & (HH - 1);
    const float slope = head_slope(h);
    const size_t tbase = ((size_t)bh * TT + c * CH) * DD;

#pragma unroll
    for (int l = 0; l < 8; l++) {
        int idx = tid + l * 256;      // 2048 float4: 64 rows x 32
        int row = idx >> 5;
        int c0 = (idx & 31) << 2;
        float4 a = *(const float4*)(g_q + tbase + row * DD + c0);
        float4 b = *(const float4*)(g_k + tbase + row * DD + c0);
        float4 vv = *(const float4*)(g_v + tbase + row * DD + c0);
        qsT[(c0 + 0) * QK_P + row] = a.x;
        qsT[(c0 + 1) * QK_P + row] = a.y;
        qsT[(c0 + 2) * QK_P + row] = a.z;
        qsT[(c0 + 3) * QK_P + row] = a.w;
        ksT[(c0 + 0) * QK_P + row] = b.x;
        ksT[(c0 + 1) * QK_P + row] = b.y;
        ksT[(c0 + 2) * QK_P + row] = b.z;
        ksT[(c0 + 3) * QK_P + row] = b.w;
        *(float4*)&vs[row * DD + c0] = vv;
    }
    if (tid < 64) kdec[tid] = expf(slope * (float)(63 - tid));
    __syncthreads();

    const int tx = tid & 15, ty = tid >> 4;

    // --- att[i][j] = (q_i . k_j) * mask ---
    {
        float accA[4][4];
#pragma unroll
        for (int i = 0; i < 4; i++)
#pragma unroll
            for (int j = 0; j < 4; j++) accA[i][j] = 0.f;
#pragma unroll 4
        for (int d = 0; d < 128; d++) {
            float a[4], b[4];
            *(float4*)a = *(const float4*)&qsT[d * QK_P + 4 * ty];
            *(float4*)b = *(const float4*)&ksT[d * QK_P + 4 * tx];
#pragma unroll
            for (int i = 0; i < 4; i++)
#pragma unroll
                for (int j = 0; j < 4; j++) accA[i][j] += a[i] * b[j];
        }
#pragma unroll
        for (int i = 0; i < 4; i++)
#pragma unroll
            for (int j = 0; j < 4; j++) {
                int ri = 4 * ty + i, cj = 4 * tx + j;
                float m = (ri >= cj) ? expf(slope * (float)(ri - cj)) : 0.f;
                att[ri * 65 + cj] = accA[i][j] * m;
            }
    }
    __syncthreads();

    // --- intra[i][e] = sum_j att[i][j] * v[j][e] -> g_o ---
    {
        float accI[4][8];
#pragma unroll
        for (int i = 0; i < 4; i++)
#pragma unroll
            for (int j = 0; j < 8; j++) accI[i][j] = 0.f;
#pragma unroll 2
        for (int j = 0; j < 64; j++) {
            float a[4];
#pragma unroll
            for (int r = 0; r < 4; r++) a[r] = att[(4 * ty + r) * 65 + j];
            float b[8];
            *(float4*)(b) = *(const float4*)&vs[j * DD + 8 * tx];
            *(float4*)(b + 4) = *(const float4*)&vs[j * DD + 8 * tx + 4];
#pragma unroll
            for (int r = 0; r < 4; r++)
#pragma unroll
                for (int e = 0; e < 8; e++) accI[r][e] += a[r] * b[e];
        }
#pragma unroll
        for (int r = 0; r < 4; r++) {
            float* dst = g_o + tbase + (size_t)(4 * ty + r) * DD + 8 * tx;
            *(float4*)(dst) = make_float4(accI[r][0], accI[r][1], accI[r][2], accI[r][3]);
            *(float4*)(dst + 4) = make_float4(accI[r][4], accI[r][5], accI[r][6], accI[r][7]);
        }
    }

    // --- U[d][e] = sum_i kdec[i]*k[i][d]*v[i][e] ---
    {
        float accU[8][8];
#pragma unroll
        for (int i = 0; i < 8; i++)
#pragma unroll
            for (int j = 0; j < 8; j++) accU[i][j] = 0.f;
#pragma unroll 2
        for (int i = 0; i < 64; i++) {
            float kd = kdec[i];
            float a[8];
#pragma unroll
            for (int r = 0; r < 8; r++) a[r] = ksT[(8 * ty + r) * QK_P + i];
            float b[8];
            *(float4*)(b) = *(const float4*)&vs[i * DD + 8 * tx];
            *(float4*)(b + 4) = *(const float4*)&vs[i * DD + 8 * tx + 4];
#pragma unroll
            for (int e = 0; e < 8; e++) b[e] *= kd;
#pragma unroll
            for (int r = 0; r < 8; r++)
#pragma unroll
                for (int e = 0; e < 8; e++) accU[r][e] += a[r] * b[e];
        }
        size_t ub = ((size_t)bh * NCH + c) * (DD * DD);
#pragma unroll
        for (int r = 0; r < 8; r++) {
            float* dst = g_U + ub + (size_t)(8 * ty + r) * DD + 8 * tx;
            *(float4*)(dst) = make_float4(accU[r][0], accU[r][1], accU[r][2], accU[r][3]);
            *(float4*)(dst + 4) = make_float4(accU[r][4], accU[r][5], accU[r][6], accU[r][7]);
        }
    }
}

// ---------------- pass B: decayed prefix scan of U over chunks -> S_c ---------
__global__ void __launch_bounds__(256) k_scan() {
    int g = blockIdx.x * 256 + threadIdx.x; // 32 * 16384 threads
    int bh = g >> 14;
    int de = g & 16383;
    float chdec = expf(head_slope(bh & (HH - 1)) * 64.f);
    size_t base = (size_t)bh * NCH * (DD * DD) + de;
    float s = 0.f;
    for (int c = 0; c < NCH; c++) {
        size_t idx = base + (size_t)c * (DD * DD);
        g_S[idx] = s;
        s = s * chdec + g_U[idx];
    }
}

// ---------------- pass C: inter = (q * qdec) @ S_c, accumulate into g_o -------
__global__ void __launch_bounds__(256, 1) k_inter() {
    extern __shared__ __align__(16) float sm2[];
    float* qs = sm2;            // [64][132]
    float* Ss = qs + 64 * 132;  // [128][128]
    const int tid = threadIdx.x;
    const int c = blockIdx.x & (NCH - 1);
    const int bh = blockIdx.x >> 6;
    const float slope = head_slope(bh & (HH - 1));
    const size_t tbase = ((size_t)bh * TT + c * CH) * DD;
    const size_t sbase = ((size_t)bh * NCH + c) * (DD * DD);

#pragma unroll
    for (int l = 0; l < 8; l++) {
        int idx = tid + l * 256;
        int row = idx >> 5;
        int c0 = (idx & 31) << 2;
        *(float4*)&qs[row * 132 + c0] = *(const float4*)(g_q + tbase + row * DD + c0);
    }
#pragma unroll
    for (int l = 0; l < 16; l++) {
        int idx = tid + l * 256; // 4096 float4s
        *(float4*)&Ss[idx * 4] = *(const float4*)(g_S + sbase + (size_t)idx * 4);
    }
    __syncthreads();

    const int tx = tid & 15, ty = tid >> 4;
    float acc[4][8];
#pragma unroll
    for (int i = 0; i < 4; i++)
#pragma unroll
        for (int j = 0; j < 8; j++) acc[i][j] = 0.f;
#pragma unroll 2
    for (int d = 0; d < 128; d++) {
        float a[4];
#pragma unroll
        for (int r = 0; r < 4; r++) a[r] = qs[(4 * ty + r) * 132 + d];
        float b[8];
        *(float4*)(b) = *(const float4*)&Ss[d * DD + 8 * tx];
        *(float4*)(b + 4) = *(const float4*)&Ss[d * DD + 8 * tx + 4];
#pragma unroll
        for (int r = 0; r < 4; r++)
#pragma unroll
            for (int e = 0; e < 8; e++) acc[r][e] += a[r] * b[e];
    }
#pragma unroll
    for (int r = 0; r < 4; r++) {
        int i = 4 * ty + r;
        float qd = expf(slope * (float)(i + 1));
        float* dst = g_o + tbase + (size_t)i * DD + 8 * tx;
        float4 c0 = *(float4*)(dst);
        float4 c1 = *(float4*)(dst + 4);
        c0.x += acc[r][0] * qd; c0.y += acc[r][1] * qd;
        c0.z += acc[r][2] * qd; c0.w += acc[r][3] * qd;
        c1.x += acc[r][4] * qd; c1.y += acc[r][5] * qd;
        c1.z += acc[r][6] * qd; c1.w += acc[r][7] * qd;
        *(float4*)(dst) = c0;
        *(float4*)(dst + 4) = c1;
    }
}

// ---------------- group rmsnorm * g_norm_w * gate -> g_on ---------------------
__global__ void __launch_bounds__(128) k_gnorm_gate(const float* __restrict__ gnw) {
    int warp = blockIdx.x * 4 + (threadIdx.x >> 5);
    int lane = threadIdx.x & 31;
    int h = warp & (HH - 1);
    int bt = warp >> 4;
    int b = bt >> 12, t = bt & (TT - 1);
    size_t ob = ((size_t)(b * HH + h) * TT + t) * DD + lane * 4;
    float4 x4 = *(const float4*)(g_o + ob);
    float x[4] = {x4.x, x4.y, x4.z, x4.w};
    float ss = x[0] * x[0] + x[1] * x[1] + x[2] * x[2] + x[3] * x[3];
#pragma unroll
    for (int off = 16; off > 0; off >>= 1) ss += __shfl_xor_sync(0xffffffffu, ss, off);
    float r = rsqrtf(ss * (1.f / DD) + 1e-6f);
    float4 w = *(const float4*)(gnw + h * DD + lane * 4);
    size_t gb = (size_t)bt * HDIM + h * DD + lane * 4;
    float4 g = *(const float4*)(g_gate + gb);
    *(float4*)(g_on + gb) =
        make_float4(x[0] * r * w.x * g.x, x[1] * r * w.y * g.y,
                    x[2] * r * w.z * g.z, x[3] * r * w.w * g.w);
}

// -----------------------------------------------------------------------------
extern "C" void kernel_launch(void* const* d_in, const int* in_sizes, int n_in,
                              void* d_out, int out_size) {
    const float* hidden = (const float*)d_in[0];
    const float* w_qkv = (const float*)d_in[1];
    const float* q_ln_w = (const float*)d_in[2];
    const float* k_ln_w = (const float*)d_in[3];
    const float* g_norm_w = (const float*)d_in[4];
    const float* w_g_proj = (const float*)d_in[5];
    const float* w_dense = (const float*)d_in[6];
    const int* pos = (const int*)d_in[7];
    float* out = (float*)d_out;

    void *p_qkv, *p_gate, *p_on;
    cudaGetSymbolAddress(&p_qkv, g_qkv);
    cudaGetSymbolAddress(&p_gate, g_gate);
    cudaGetSymbolAddress(&p_on, g_on);

    const int smem3 = (128 * QK_P * 2 + 64 * 128 + 64 * 65 + 64) * 4;  // 119296
    const int smem5 = (64 * 132 + 128 * 128) * 4;                      // 99328
    cudaFuncSetAttribute(k_chunk_local, cudaFuncAttributeMaxDynamicSharedMemorySize, smem3);
    cudaFuncSetAttribute(k_inter, cudaFuncAttributeMaxDynamicSharedMemorySize, smem5);

    // 1. qkv = hidden @ w_qkv^T
    sgemm_nt<<<dim3(O3 / 128, (BB * TT) / 128), 256>>>(hidden, w_qkv, (float*)p_qkv,
                                                       BB * TT, O3, HDIM, 0);
    // 2. split + rmsnorm + rope (+ fold D^-0.5 into q)
    k_norm_rope<<<(BB * TT * HH) / 4, 128>>>(q_ln_w, k_ln_w, pos);
    // 3. per-chunk local: att/intra/U  (parallel over b,h,c)
    k_chunk_local<<<BB * HH * NCH, 256, smem3>>>();
    // 4. decayed prefix scan U -> S
    k_scan<<<(BB * HH * DD * DD) / 256, 256>>>();
    // 5. inter-chunk term accumulated into o
    k_inter<<<BB * HH * NCH, 256, smem5>>>();
    // 6. gate = sigmoid(hidden @ w_g_proj^T)
    sgemm_nt<<<dim3(HDIM / 128, (BB * TT) / 128), 256>>>(hidden, w_g_proj, (float*)p_gate,
                                                         BB * TT, HDIM, HDIM, 1);
    // 7. group rmsnorm * weight * gate
    k_gnorm_gate<<<(BB * TT * HH) / 4, 128>>>(g_norm_w);
    // 8. out = on @ w_dense^T
    sgemm_nt<<<dim3(HDIM / 128, (BB * TT) / 128), 256>>>((const float*)p_on, w_dense, out,
                                                         BB * TT, HDIM, HDIM, 0);
}

// round 3
// speedup vs baseline: 1.8985x; 1.8985x over previous
#include <cuda_runtime.h>
#include <cuda_bf16.h>
#include <cstdint>

#define BB 2
#define TT 4096
#define HH 16
#define DD 128
#define HDIM 2048
#define O3 6144
#define NCH 64
#define CH 64

// ---------------- scratch (static device globals; no runtime allocation) ----
static __device__ float g_qkv[(size_t)BB * TT * O3];          // (bt, o)
static __device__ float g_q[(size_t)BB * HH * TT * DD];       // (b,h,t,d)
static __device__ float g_k[(size_t)BB * HH * TT * DD];
static __device__ float g_v[(size_t)BB * HH * TT * DD];
static __device__ float g_o[(size_t)BB * HH * TT * DD];
static __device__ float g_gate[(size_t)BB * TT * HDIM];       // (bt, hd) sigmoid'ed
static __device__ float g_U[(size_t)BB * HH * NCH * DD * DD]; // per-chunk KV outer
static __device__ float g_S[(size_t)BB * HH * NCH * DD * DD]; // scanned state

// bf16 split operands
static __device__ __nv_bfloat16 g_hh[(size_t)BB * TT * HDIM];   // hidden hi
static __device__ __nv_bfloat16 g_hl[(size_t)BB * TT * HDIM];   // hidden lo
static __device__ __nv_bfloat16 g_wqh[(size_t)O3 * HDIM];
static __device__ __nv_bfloat16 g_wql[(size_t)O3 * HDIM];
static __device__ __nv_bfloat16 g_wgh[(size_t)HDIM * HDIM];
static __device__ __nv_bfloat16 g_wgl[(size_t)HDIM * HDIM];
static __device__ __nv_bfloat16 g_wdh[(size_t)HDIM * HDIM];
static __device__ __nv_bfloat16 g_wdl[(size_t)HDIM * HDIM];
static __device__ __nv_bfloat16 g_onh[(size_t)BB * TT * HDIM];  // gated/normed o hi
static __device__ __nv_bfloat16 g_onl[(size_t)BB * TT * HDIM];

__device__ __forceinline__ float head_slope(int h) {
    float a = (float)exp2(-0.5 * (double)(h + 1));
    return (float)(-(double)a * (1.0 - 11.0 / 31.0 + 1e-5));
}

__device__ __forceinline__ uint32_t s2u(const void* p) {
    uint32_t a;
    asm("{ .reg .u64 t; cvta.to.shared.u64 t, %1; cvt.u32.u64 %0, t; }" : "=r"(a) : "l"(p));
    return a;
}

__device__ __forceinline__ void cp16(uint32_t dst, const void* src) {
    asm volatile("cp.async.cg.shared.global [%0], [%1], 16;" :: "r"(dst), "l"(src));
}

__device__ __forceinline__ void ldsm4(uint32_t& r0, uint32_t& r1, uint32_t& r2, uint32_t& r3,
                                      uint32_t addr) {
    asm volatile("ldmatrix.sync.aligned.m8n8.x4.shared.b16 {%0,%1,%2,%3}, [%4];"
                 : "=r"(r0), "=r"(r1), "=r"(r2), "=r"(r3) : "r"(addr));
}

__device__ __forceinline__ void mma16816(float* c, const uint32_t* a, const uint32_t* b) {
    asm volatile(
        "mma.sync.aligned.m16n8k16.row.col.f32.bf16.bf16.f32 "
        "{%0,%1,%2,%3}, {%4,%5,%6,%7}, {%8,%9}, {%0,%1,%2,%3};"
        : "+f"(c[0]), "+f"(c[1]), "+f"(c[2]), "+f"(c[3])
        : "r"(a[0]), "r"(a[1]), "r"(a[2]), "r"(a[3]), "r"(b[0]), "r"(b[1]));
}

// ======================= split-bf16 mma.sync GEMM ============================
// C[M, Ntot] = (Ah+Al)[M,2048] * (Bh+Bl)[Ntot,2048]^T  (lo*lo dropped)
// tile 128x128, BK=64, 3 K-segments (hi*hi, lo*hi, hi*lo) -> 96 BK-chunks
#define GPITCH 144                    // bytes per smem row (64 bf16 data + pad)
#define GOPB (128 * GPITCH)           // 18432 bytes per operand per stage
#define GSTG (2 * GOPB)               // 36864 per stage
#define GNSTG 4

__global__ void __launch_bounds__(256, 1) gemm_bf16split(
    const __nv_bfloat16* __restrict__ Ah, const __nv_bfloat16* __restrict__ Al,
    const __nv_bfloat16* __restrict__ Bh, const __nv_bfloat16* __restrict__ Bl,
    float* __restrict__ C, int Ntot, int act) {
    extern __shared__ __align__(128) char smem[];
    const uint32_t sbase = s2u(smem);
    const int tid = threadIdx.x;
    const int lane = tid & 31;
    const int warp = tid >> 5;
    const int wy = warp & 3;    // M: 4 x 32
    const int wx = warp >> 2;   // N: 2 x 64
    const int m0 = blockIdx.y * 128;
    const int n0 = blockIdx.x * 128;

    float acc[2][8][4];
#pragma unroll
    for (int i = 0; i < 2; i++)
#pragma unroll
        for (int j = 0; j < 8; j++)
#pragma unroll
            for (int q = 0; q < 4; q++) acc[i][j][q] = 0.f;

#define LOAD_CHUNK(c, s)                                                                \
    do {                                                                                \
        int _seg = (c) >> 5;                                                            \
        int _kk = ((c) & 31) << 6;                                                      \
        const __nv_bfloat16* _Ab = ((_seg == 1) ? Al : Ah) + (size_t)m0 * 2048 + _kk;   \
        const __nv_bfloat16* _Bb = ((_seg == 2) ? Bl : Bh) + (size_t)n0 * 2048 + _kk;   \
        uint32_t _sa = sbase + (s) * GSTG;                                              \
        uint32_t _sb = _sa + GOPB;                                                      \
        _Pragma("unroll") for (int t = 0; t < 4; t++) {                                 \
            int idx = tid + t * 256;                                                    \
            int row = idx >> 3, ch = idx & 7;                                           \
            cp16(_sa + row * GPITCH + ch * 16, _Ab + (size_t)row * 2048 + ch * 8);      \
        }                                                                               \
        _Pragma("unroll") for (int t = 0; t < 4; t++) {                                 \
            int idx = tid + t * 256;                                                    \
            int row = idx >> 3, ch = idx & 7;                                           \
            cp16(_sb + row * GPITCH + ch * 16, _Bb + (size_t)row * 2048 + ch * 8);      \
        }                                                                               \
    } while (0)

    // prologue: chunks 0..2 into stages 0..2
    for (int c = 0; c < 3; c++) {
        LOAD_CHUNK(c, c);
        asm volatile("cp.async.commit_group;" ::: "memory");
    }

    // per-thread ldmatrix base offsets
    const uint32_t aoff = (uint32_t)(wy * 32 + (lane & 15)) * GPITCH + (lane >> 4) * 16;
    const int brow = (lane & 7) + ((lane >> 4) << 3);
    const uint32_t boff0 = GOPB + (uint32_t)(wx * 64 + brow) * GPITCH + ((lane >> 3) & 1) * 16;

    for (int i = 0; i < 96; i++) {
        const int s = i & 3;
        asm volatile("cp.async.wait_group 2;" ::: "memory");
        __syncthreads();
        const int j = i + 3;
        if (j < 96) LOAD_CHUNK(j, j & 3);
        asm volatile("cp.async.commit_group;" ::: "memory");

        const uint32_t sa = sbase + s * GSTG;
#pragma unroll
        for (int ks = 0; ks < 4; ks++) {
            uint32_t a[2][4], b[4][2];
            ldsm4(a[0][0], a[0][1], a[0][2], a[0][3], sa + aoff + ks * 32);
            ldsm4(a[1][0], a[1][1], a[1][2], a[1][3], sa + aoff + 16 * GPITCH + ks * 32);
            ldsm4(b[0][0], b[0][1], b[1][0], b[1][1], sa + boff0 + ks * 32);
            ldsm4(b[2][0], b[2][1], b[3][0], b[3][1], sa + boff0 + 16 * GPITCH + ks * 32);
#pragma unroll
            for (int mt = 0; mt < 2; mt++)
#pragma unroll
                for (int nt = 0; nt < 4; nt++) {
                    mma16816(acc[mt][nt * 2 + 0], a[mt], b[nt]);
                }
            // second set of 4 n-tiles (n offset +32)
            ldsm4(b[0][0], b[0][1], b[1][0], b[1][1], sa + boff0 + 32 * GPITCH + ks * 32);
            ldsm4(b[2][0], b[2][1], b[3][0], b[3][1], sa + boff0 + 48 * GPITCH + ks * 32);
#pragma unroll
            for (int mt = 0; mt < 2; mt++)
#pragma unroll
                for (int nt = 0; nt < 4; nt++) {
                    mma16816(acc[mt][nt * 2 + 1], a[mt], b[nt]);
                }
        }
    }

    // epilogue: acc[mt][j][.] where n-tile index = (j>>1) pair base + ...
    // layout used above: acc[mt][nt*2+half] covers n = wx*64 + half*32 + nt*8
    const int rbase = m0 + wy * 32 + (lane >> 2);
    const int cbase = n0 + wx * 64 + (lane & 3) * 2;
#pragma unroll
    for (int mt = 0; mt < 2; mt++) {
#pragma unroll
        for (int j = 0; j < 8; j++) {
            int nt = j >> 1, half = j & 1;
            int col = cbase + half * 32 + nt * 8;
            float v[4];
#pragma unroll
            for (int q = 0; q < 4; q++) {
                float x = acc[mt][j][q];
                v[q] = act ? (1.f / (1.f + expf(-x))) : x;
            }
            float* d0 = C + (size_t)(rbase + mt * 16) * Ntot + col;
            float* d1 = C + (size_t)(rbase + mt * 16 + 8) * Ntot + col;
            *(float2*)d0 = make_float2(v[0], v[1]);
            *(float2*)d1 = make_float2(v[2], v[3]);
        }
    }
}

// ---------------- fp32 -> bf16 hi/lo split ----------------------------------
__global__ void __launch_bounds__(256) k_cvt_hilo(const float* __restrict__ src,
                                                  __nv_bfloat16* __restrict__ hi,
                                                  __nv_bfloat16* __restrict__ lo, int n4) {
    int i = blockIdx.x * 256 + threadIdx.x;
    if (i >= n4) return;
    float4 x = ((const float4*)src)[i];
    float xs[4] = {x.x, x.y, x.z, x.w};
    __nv_bfloat16 h[4], l[4];
#pragma unroll
    for (int j = 0; j < 4; j++) {
        h[j] = __float2bfloat16(xs[j]);
        l[j] = __float2bfloat16(xs[j] - __bfloat162float(h[j]));
    }
    ((uint2*)hi)[i] = *(uint2*)h;
    ((uint2*)lo)[i] = *(uint2*)l;
}

// ---------------- split qkv + per-head rmsnorm + rope; one warp per (b,t,h) --
__global__ void __launch_bounds__(128) k_norm_rope(const float* __restrict__ qw,
                                                   const float* __restrict__ kw,
                                                   const int* __restrict__ pos) {
    int warp = blockIdx.x * 4 + (threadIdx.x >> 5);
    int lane = threadIdx.x & 31;
    int h = warp & (HH - 1);
    int bt = warp >> 4;
    size_t base = (size_t)bt * O3 + h * DD + lane * 4;

    float4 q4 = *(const float4*)(g_qkv + base);
    float4 k4 = *(const float4*)(g_qkv + base + HDIM);
    float4 v4 = *(const float4*)(g_qkv + base + 2 * HDIM);
    float qv[4] = {q4.x, q4.y, q4.z, q4.w};
    float kv[4] = {k4.x, k4.y, k4.z, k4.w};

    float sq = qv[0] * qv[0] + qv[1] * qv[1] + qv[2] * qv[2] + qv[3] * qv[3];
    float sk = kv[0] * kv[0] + kv[1] * kv[1] + kv[2] * kv[2] + kv[3] * kv[3];
#pragma unroll
    for (int off = 16; off > 0; off >>= 1) {
        sq += __shfl_xor_sync(0xffffffffu, sq, off);
        sk += __shfl_xor_sync(0xffffffffu, sk, off);
    }
    float rq = rsqrtf(sq * (1.f / DD) + 1e-6f);
    float rk = rsqrtf(sk * (1.f / DD) + 1e-6f);
    float4 wq = *(const float4*)(qw + lane * 4);
    float4 wk = *(const float4*)(kw + lane * 4);
    float wqa[4] = {wq.x, wq.y, wq.z, wq.w};
    float wka[4] = {wk.x, wk.y, wk.z, wk.w};
#pragma unroll
    for (int j = 0; j < 4; j++) {
        qv[j] = qv[j] * rq * wqa[j];
        kv[j] = kv[j] * rk * wka[j];
    }

    float p = (float)pos[bt];
    float qp[4], kp[4];
#pragma unroll
    for (int j = 0; j < 4; j++) {
        qp[j] = __shfl_xor_sync(0xffffffffu, qv[j], 8);
        kp[j] = __shfl_xor_sync(0xffffffffu, kv[j], 8);
    }
    if (lane < 16) {
        float sgn = (lane < 8) ? -1.f : 1.f;
        int jb = (lane & 7) * 4;
#pragma unroll
        for (int j = 0; j < 4; j++) {
            float inv = exp2f(-(float)(jb + j) * 0.4152410118609203f);
            float ang = p * inv;
            float sn, cs;
            sincosf(ang, &sn, &cs);
            qv[j] = qv[j] * cs + sgn * qp[j] * sn;
            kv[j] = kv[j] * cs + sgn * kp[j] * sn;
        }
    }

    int b = bt >> 12, t = bt & (TT - 1);
    size_t ob = ((size_t)(b * HH + h) * TT + t) * DD + lane * 4;
    const float qscale = 0.08838834764831845f;
    *(float4*)(g_q + ob) = make_float4(qv[0] * qscale, qv[1] * qscale, qv[2] * qscale, qv[3] * qscale);
    *(float4*)(g_k + ob) = make_float4(kv[0], kv[1], kv[2], kv[3]);
    *(float4*)(g_v + ob) = v4;
}

// ---------------- pass A: per (b,h,c): att(masked), intra = att@v, U ---------
#define QK_P 68
__global__ void __launch_bounds__(256, 1) k_chunk_local() {
    extern __shared__ __align__(16) float sm[];
    float* qsT = sm;
    float* ksT = qsT + 128 * QK_P;
    float* vs = ksT + 128 * QK_P;
    float* att = vs + 64 * 128;
    float* kdec = att + 64 * 65;

    const int tid = threadIdx.x;
    const int c = blockIdx.x & (NCH - 1);
    const int bh = blockIdx.x >> 6;
    const int h = bh & (HH - 1);
    const float slope = head_slope(h);
    const size_t tbase = ((size_t)bh * TT + c * CH) * DD;

#pragma unroll
    for (int l = 0; l < 8; l++) {
        int idx = tid + l * 256;
        int row = idx >> 5;
        int c0 = (idx & 31) << 2;
        float4 a = *(const float4*)(g_q + tbase + row * DD + c0);
        float4 b = *(const float4*)(g_k + tbase + row * DD + c0);
        float4 vv = *(const float4*)(g_v + tbase + row * DD + c0);
        qsT[(c0 + 0) * QK_P + row] = a.x;
        qsT[(c0 + 1) * QK_P + row] = a.y;
        qsT[(c0 + 2) * QK_P + row] = a.z;
        qsT[(c0 + 3) * QK_P + row] = a.w;
        ksT[(c0 + 0) * QK_P + row] = b.x;
        ksT[(c0 + 1) * QK_P + row] = b.y;
        ksT[(c0 + 2) * QK_P + row] = b.z;
        ksT[(c0 + 3) * QK_P + row] = b.w;
        *(float4*)&vs[row * DD + c0] = vv;
    }
    if (tid < 64) kdec[tid] = expf(slope * (float)(63 - tid));
    __syncthreads();

    const int tx = tid & 15, ty = tid >> 4;

    {
        float accA[4][4];
#pragma unroll
        for (int i = 0; i < 4; i++)
#pragma unroll
            for (int j = 0; j < 4; j++) accA[i][j] = 0.f;
#pragma unroll 4
        for (int d = 0; d < 128; d++) {
            float a[4], b[4];
            *(float4*)a = *(const float4*)&qsT[d * QK_P + 4 * ty];
            *(float4*)b = *(const float4*)&ksT[d * QK_P + 4 * tx];
#pragma unroll
            for (int i = 0; i < 4; i++)
#pragma unroll
                for (int j = 0; j < 4; j++) accA[i][j] += a[i] * b[j];
        }
#pragma unroll
        for (int i = 0; i < 4; i++)
#pragma unroll
            for (int j = 0; j < 4; j++) {
                int ri = 4 * ty + i, cj = 4 * tx + j;
                float m = (ri >= cj) ? expf(slope * (float)(ri - cj)) : 0.f;
                att[ri * 65 + cj] = accA[i][j] * m;
            }
    }
    __syncthreads();

    {
        float accI[4][8];
#pragma unroll
        for (int i = 0; i < 4; i++)
#pragma unroll
            for (int j = 0; j < 8; j++) accI[i][j] = 0.f;
#pragma unroll 2
        for (int j = 0; j < 64; j++) {
            float a[4];
#pragma unroll
            for (int r = 0; r < 4; r++) a[r] = att[(4 * ty + r) * 65 + j];
            float b[8];
            *(float4*)(b) = *(const float4*)&vs[j * DD + 8 * tx];
            *(float4*)(b + 4) = *(const float4*)&vs[j * DD + 8 * tx + 4];
#pragma unroll
            for (int r = 0; r < 4; r++)
#pragma unroll
                for (int e = 0; e < 8; e++) accI[r][e] += a[r] * b[e];
        }
#pragma unroll
        for (int r = 0; r < 4; r++) {
            float* dst = g_o + tbase + (size_t)(4 * ty + r) * DD + 8 * tx;
            *(float4*)(dst) = make_float4(accI[r][0], accI[r][1], accI[r][2], accI[r][3]);
            *(float4*)(dst + 4) = make_float4(accI[r][4], accI[r][5], accI[r][6], accI[r][7]);
        }
    }

    {
        float accU[8][8];
#pragma unroll
        for (int i = 0; i < 8; i++)
#pragma unroll
            for (int j = 0; j < 8; j++) accU[i][j] = 0.f;
#pragma unroll 2
        for (int i = 0; i < 64; i++) {
            float kd = kdec[i];
            float a[8];
#pragma unroll
            for (int r = 0; r < 8; r++) a[r] = ksT[(8 * ty + r) * QK_P + i];
            float b[8];
            *(float4*)(b) = *(const float4*)&vs[i * DD + 8 * tx];
            *(float4*)(b + 4) = *(const float4*)&vs[i * DD + 8 * tx + 4];
#pragma unroll
            for (int e = 0; e < 8; e++) b[e] *= kd;
#pragma unroll
            for (int r = 0; r < 8; r++)
#pragma unroll
                for (int e = 0; e < 8; e++) accU[r][e] += a[r] * b[e];
        }
        size_t ub = ((size_t)bh * NCH + c) * (DD * DD);
#pragma unroll
        for (int r = 0; r < 8; r++) {
            float* dst = g_U + ub + (size_t)(8 * ty + r) * DD + 8 * tx;
            *(float4*)(dst) = make_float4(accU[r][0], accU[r][1], accU[r][2], accU[r][3]);
            *(float4*)(dst + 4) = make_float4(accU[r][4], accU[r][5], accU[r][6], accU[r][7]);
        }
    }
}

// ---------------- pass B: decayed prefix scan of U over chunks -> S_c ---------
__global__ void __launch_bounds__(256) k_scan() {
    int g = blockIdx.x * 256 + threadIdx.x;
    int bh = g >> 14;
    int de = g & 16383;
    float chdec = expf(head_slope(bh & (HH - 1)) * 64.f);
    size_t base = (size_t)bh * NCH * (DD * DD) + de;
    float s = 0.f;
    for (int c = 0; c < NCH; c++) {
        size_t idx = base + (size_t)c * (DD * DD);
        g_S[idx] = s;
        s = s * chdec + g_U[idx];
    }
}

// ---------------- pass C: inter = (q * qdec) @ S_c, accumulate into g_o -------
__global__ void __launch_bounds__(256, 1) k_inter() {
    extern __shared__ __align__(16) float sm2[];
    float* qs = sm2;
    float* Ss = qs + 64 * 132;
    const int tid = threadIdx.x;
    const int c = blockIdx.x & (NCH - 1);
    const int bh = blockIdx.x >> 6;
    const float slope = head_slope(bh & (HH - 1));
    const size_t tbase = ((size_t)bh * TT + c * CH) * DD;
    const size_t sbase = ((size_t)bh * NCH + c) * (DD * DD);

#pragma unroll
    for (int l = 0; l < 8; l++) {
        int idx = tid + l * 256;
        int row = idx >> 5;
        int c0 = (idx & 31) << 2;
        *(float4*)&qs[row * 132 + c0] = *(const float4*)(g_q + tbase + row * DD + c0);
    }
#pragma unroll
    for (int l = 0; l < 16; l++) {
        int idx = tid + l * 256;
        *(float4*)&Ss[idx * 4] = *(const float4*)(g_S + sbase + (size_t)idx * 4);
    }
    __syncthreads();

    const int tx = tid & 15, ty = tid >> 4;
    float acc[4][8];
#pragma unroll
    for (int i = 0; i < 4; i++)
#pragma unroll
        for (int j = 0; j < 8; j++) acc[i][j] = 0.f;
#pragma unroll 2
    for (int d = 0; d < 128; d++) {
        float a[4];
#pragma unroll
        for (int r = 0; r < 4; r++) a[r] = qs[(4 * ty + r) * 132 + d];
        float b[8];
        *(float4*)(b) = *(const float4*)&Ss[d * DD + 8 * tx];
        *(float4*)(b + 4) = *(const float4*)&Ss[d * DD + 8 * tx + 4];
#pragma unroll
        for (int r = 0; r < 4; r++)
#pragma unroll
            for (int e = 0; e < 8; e++) acc[r][e] += a[r] * b[e];
    }
#pragma unroll
    for (int r = 0; r < 4; r++) {
        int i = 4 * ty + r;
        float qd = expf(slope * (float)(i + 1));
        float* dst = g_o + tbase + (size_t)i * DD + 8 * tx;
        float4 c0 = *(float4*)(dst);
        float4 c1 = *(float4*)(dst + 4);
        c0.x += acc[r][0] * qd; c0.y += acc[r][1] * qd;
        c0.z += acc[r][2] * qd; c0.w += acc[r][3] * qd;
        c1.x += acc[r][4] * qd; c1.y += acc[r][5] * qd;
        c1.z += acc[r][6] * qd; c1.w += acc[r][7] * qd;
        *(float4*)(dst) = c0;
        *(float4*)(dst + 4) = c1;
    }
}

// ---------------- group rmsnorm * g_norm_w * gate -> bf16 hi/lo ---------------
__global__ void __launch_bounds__(128) k_gnorm_gate(const float* __restrict__ gnw) {
    int warp = blockIdx.x * 4 + (threadIdx.x >> 5);
    int lane = threadIdx.x & 31;
    int h = warp & (HH - 1);
    int bt = warp >> 4;
    int b = bt >> 12, t = bt & (TT - 1);
    size_t ob = ((size_t)(b * HH + h) * TT + t) * DD + lane * 4;
    float4 x4 = *(const float4*)(g_o + ob);
    float x[4] = {x4.x, x4.y, x4.z, x4.w};
    float ss = x[0] * x[0] + x[1] * x[1] + x[2] * x[2] + x[3] * x[3];
#pragma unroll
    for (int off = 16; off > 0; off >>= 1) ss += __shfl_xor_sync(0xffffffffu, ss, off);
    float r = rsqrtf(ss * (1.f / DD) + 1e-6f);
    float4 w = *(const float4*)(gnw + h * DD + lane * 4);
    size_t gb = (size_t)bt * HDIM + h * DD + lane * 4;
    float4 g = *(const float4*)(g_gate + gb);
    float y[4] = {x[0] * r * w.x * g.x, x[1] * r * w.y * g.y,
                  x[2] * r * w.z * g.z, x[3] * r * w.w * g.w};
    __nv_bfloat16 hb[4], lb[4];
#pragma unroll
    for (int j = 0; j < 4; j++) {
        hb[j] = __float2bfloat16(y[j]);
        lb[j] = __float2bfloat16(y[j] - __bfloat162float(hb[j]));
    }
    *(uint2*)(g_onh + gb) = *(uint2*)hb;
    *(uint2*)(g_onl + gb) = *(uint2*)lb;
}

// -----------------------------------------------------------------------------
extern "C" void kernel_launch(void* const* d_in, const int* in_sizes, int n_in,
                              void* d_out, int out_size) {
    const float* hidden = (const float*)d_in[0];
    const float* w_qkv = (const float*)d_in[1];
    const float* q_ln_w = (const float*)d_in[2];
    const float* k_ln_w = (const float*)d_in[3];
    const float* g_norm_w = (const float*)d_in[4];
    const float* w_g_proj = (const float*)d_in[5];
    const float* w_dense = (const float*)d_in[6];
    const int* pos = (const int*)d_in[7];
    float* out = (float*)d_out;

    void *p_qkv, *p_gate;
    void *p_hh, *p_hl, *p_wqh, *p_wql, *p_wgh, *p_wgl, *p_wdh, *p_wdl, *p_onh, *p_onl;
    cudaGetSymbolAddress(&p_qkv, g_qkv);
    cudaGetSymbolAddress(&p_gate, g_gate);
    cudaGetSymbolAddress(&p_hh, g_hh);
    cudaGetSymbolAddress(&p_hl, g_hl);
    cudaGetSymbolAddress(&p_wqh, g_wqh);
    cudaGetSymbolAddress(&p_wql, g_wql);
    cudaGetSymbolAddress(&p_wgh, g_wgh);
    cudaGetSymbolAddress(&p_wgl, g_wgl);
    cudaGetSymbolAddress(&p_wdh, g_wdh);
    cudaGetSymbolAddress(&p_wdl, g_wdl);
    cudaGetSymbolAddress(&p_onh, g_onh);
    cudaGetSymbolAddress(&p_onl, g_onl);

    const int smem3 = (128 * QK_P * 2 + 64 * 128 + 64 * 65 + 64) * 4;  // 119296
    const int smem5 = (64 * 132 + 128 * 128) * 4;                      // 99328
    const int smemG = GNSTG * GSTG;                                    // 147456
    cudaFuncSetAttribute(k_chunk_local, cudaFuncAttributeMaxDynamicSharedMemorySize, smem3);
    cudaFuncSetAttribute(k_inter, cudaFuncAttributeMaxDynamicSharedMemorySize, smem5);
    cudaFuncSetAttribute(gemm_bf16split, cudaFuncAttributeMaxDynamicSharedMemorySize, smemG);

    // 0. split conversions
    {
        int n4;
        n4 = BB * TT * HDIM / 4;
        k_cvt_hilo<<<(n4 + 255) / 256, 256>>>(hidden, (__nv_bfloat16*)p_hh, (__nv_bfloat16*)p_hl, n4);
        n4 = O3 * HDIM / 4;
        k_cvt_hilo<<<(n4 + 255) / 256, 256>>>(w_qkv, (__nv_bfloat16*)p_wqh, (__nv_bfloat16*)p_wql, n4);
        n4 = HDIM * HDIM / 4;
        k_cvt_hilo<<<(n4 + 255) / 256, 256>>>(w_g_proj, (__nv_bfloat16*)p_wgh, (__nv_bfloat16*)p_wgl, n4);
        k_cvt_hilo<<<(n4 + 255) / 256, 256>>>(w_dense, (__nv_bfloat16*)p_wdh, (__nv_bfloat16*)p_wdl, n4);
    }

    // 1. qkv = hidden @ w_qkv^T   (mma.sync split-bf16)
    gemm_bf16split<<<dim3(O3 / 128, (BB * TT) / 128), 256, smemG>>>(
        (const __nv_bfloat16*)p_hh, (const __nv_bfloat16*)p_hl,
        (const __nv_bfloat16*)p_wqh, (const __nv_bfloat16*)p_wql,
        (float*)p_qkv, O3, 0);
    // 2. split + rmsnorm + rope
    k_norm_rope<<<(BB * TT * HH) / 4, 128>>>(q_ln_w, k_ln_w, pos);
    // 3. per-chunk local
    k_chunk_local<<<BB * HH * NCH, 256, smem3>>>();
    // 4. decayed prefix scan
    k_scan<<<(BB * HH * DD * DD) / 256, 256>>>();
    // 5. inter-chunk
    k_inter<<<BB * HH * NCH, 256, smem5>>>();
    // 6. gate = sigmoid(hidden @ w_g_proj^T)
    gemm_bf16split<<<dim3(HDIM / 128, (BB * TT) / 128), 256, smemG>>>(
        (const __nv_bfloat16*)p_hh, (const __nv_bfloat16*)p_hl,
        (const __nv_bfloat16*)p_wgh, (const __nv_bfloat16*)p_wgl,
        (float*)p_gate, HDIM, 1);
    // 7. group rmsnorm * weight * gate -> bf16 hi/lo
    k_gnorm_gate<<<(BB * TT * HH) / 4, 128>>>(g_norm_w);
    // 8. out = on @ w_dense^T
    gemm_bf16split<<<dim3(HDIM / 128, (BB * TT) / 128), 256, smemG>>>(
        (const __nv_bfloat16*)p_onh, (const __nv_bfloat16*)p_onl,
        (const __nv_bfloat16*)p_wdh, (const __nv_bfloat16*)p_wdl,
        out, HDIM, 0);
}

// round 4
// speedup vs baseline: 2.5816x; 1.3598x over previous
#include <cuda_runtime.h>
#include <cuda_fp16.h>
#include <cstdint>

#define BB 2
#define TT 4096
#define HH 16
#define DD 128
#define HDIM 2048
#define O3 6144
#define NCH 64
#define CH 64

// ---------------- scratch (static device globals; no runtime allocation) ----
static __device__ float g_qkv[(size_t)BB * TT * O3];          // (bt, o)
static __device__ float g_q[(size_t)BB * HH * TT * DD];       // (b,h,t,d)
static __device__ float g_k[(size_t)BB * HH * TT * DD];
static __device__ float g_v[(size_t)BB * HH * TT * DD];
static __device__ float g_o[(size_t)BB * HH * TT * DD];
static __device__ float g_gate[(size_t)BB * TT * HDIM];       // (bt, hd) sigmoid'ed
static __device__ float g_U[(size_t)BB * HH * NCH * DD * DD]; // per-chunk KV outer
static __device__ float g_S[(size_t)BB * HH * NCH * DD * DD]; // scanned state

// fp16 operands: activations split hi/lo, weights single
static __device__ __half g_hh[(size_t)BB * TT * HDIM];   // hidden hi
static __device__ __half g_hl[(size_t)BB * TT * HDIM];   // hidden lo
static __device__ __half g_wqh[(size_t)O3 * HDIM];
static __device__ __half g_wgh[(size_t)HDIM * HDIM];
static __device__ __half g_wdh[(size_t)HDIM * HDIM];
static __device__ __half g_onh[(size_t)BB * TT * HDIM];  // gated/normed o hi
static __device__ __half g_onl[(size_t)BB * TT * HDIM];

__device__ __forceinline__ float head_slope(int h) {
    float a = (float)exp2(-0.5 * (double)(h + 1));
    return (float)(-(double)a * (1.0 - 11.0 / 31.0 + 1e-5));
}

__device__ __forceinline__ uint32_t s2u(const void* p) {
    uint32_t a;
    asm("{ .reg .u64 t; cvta.to.shared.u64 t, %1; cvt.u32.u64 %0, t; }" : "=r"(a) : "l"(p));
    return a;
}

__device__ __forceinline__ void cp16(uint32_t dst, const void* src) {
    asm volatile("cp.async.cg.shared.global [%0], [%1], 16;" :: "r"(dst), "l"(src));
}

__device__ __forceinline__ void ldsm4(uint32_t& r0, uint32_t& r1, uint32_t& r2, uint32_t& r3,
                                      uint32_t addr) {
    asm volatile("ldmatrix.sync.aligned.m8n8.x4.shared.b16 {%0,%1,%2,%3}, [%4];"
                 : "=r"(r0), "=r"(r1), "=r"(r2), "=r"(r3) : "r"(addr));
}

__device__ __forceinline__ void mma16816(float* c, const uint32_t* a, const uint32_t* b) {
    asm volatile(
        "mma.sync.aligned.m16n8k16.row.col.f32.f16.f16.f32 "
        "{%0,%1,%2,%3}, {%4,%5,%6,%7}, {%8,%9}, {%0,%1,%2,%3};"
        : "+f"(c[0]), "+f"(c[1]), "+f"(c[2]), "+f"(c[3])
        : "r"(a[0]), "r"(a[1]), "r"(a[2]), "r"(a[3]), "r"(b[0]), "r"(b[1]));
}

// ======================= split-fp16 mma.sync GEMM ============================
// C[M, Ntot] = (Ah+Al)[M,2048] * B[Ntot,2048]^T   (B single fp16)
// tile 128x128, BK=64, 2 K-segments (hi*B, lo*B) -> 64 BK-chunks
#define GPITCH 144                    // bytes per smem row (64 fp16 data + pad)
#define GOPB (128 * GPITCH)           // 18432 bytes per operand per stage
#define GSTG (2 * GOPB)               // 36864 per stage
#define GNSTG 4
#define GCHUNKS 64

__global__ void __launch_bounds__(256, 1) gemm_f16split(
    const __half* __restrict__ Ah, const __half* __restrict__ Al,
    const __half* __restrict__ Bm,
    float* __restrict__ C, int Ntot, int act) {
    extern __shared__ __align__(128) char smem[];
    const uint32_t sbase = s2u(smem);
    const int tid = threadIdx.x;
    const int lane = tid & 31;
    const int warp = tid >> 5;
    const int wy = warp & 3;    // M: 4 x 32
    const int wx = warp >> 2;   // N: 2 x 64
    const int m0 = blockIdx.y * 128;
    const int n0 = blockIdx.x * 128;

    float acc[2][8][4];
#pragma unroll
    for (int i = 0; i < 2; i++)
#pragma unroll
        for (int j = 0; j < 8; j++)
#pragma unroll
            for (int q = 0; q < 4; q++) acc[i][j][q] = 0.f;

#define LOAD_CHUNK(c, s)                                                                \
    do {                                                                                \
        int _seg = (c) >> 5;                                                            \
        int _kk = ((c) & 31) << 6;                                                      \
        const __half* _Ab = (_seg ? Al : Ah) + (size_t)m0 * 2048 + _kk;                 \
        const __half* _Bb = Bm + (size_t)n0 * 2048 + _kk;                               \
        uint32_t _sa = sbase + (s) * GSTG;                                              \
        uint32_t _sb = _sa + GOPB;                                                      \
        _Pragma("unroll") for (int t = 0; t < 4; t++) {                                 \
            int idx = tid + t * 256;                                                    \
            int row = idx >> 3, ch = idx & 7;                                           \
            cp16(_sa + row * GPITCH + ch * 16, _Ab + (size_t)row * 2048 + ch * 8);      \
        }                                                                               \
        _Pragma("unroll") for (int t = 0; t < 4; t++) {                                 \
            int idx = tid + t * 256;                                                    \
            int row = idx >> 3, ch = idx & 7;                                           \
            cp16(_sb + row * GPITCH + ch * 16, _Bb + (size_t)row * 2048 + ch * 8);      \
        }                                                                               \
    } while (0)

    // prologue: chunks 0..2 into stages 0..2
    for (int c = 0; c < 3; c++) {
        LOAD_CHUNK(c, c);
        asm volatile("cp.async.commit_group;" ::: "memory");
    }

    // per-thread ldmatrix base offsets
    const uint32_t aoff = (uint32_t)(wy * 32 + (lane & 15)) * GPITCH + (lane >> 4) * 16;
    const int brow = (lane & 7) + ((lane >> 4) << 3);
    const uint32_t boff0 = GOPB + (uint32_t)(wx * 64 + brow) * GPITCH + ((lane >> 3) & 1) * 16;

    for (int i = 0; i < GCHUNKS; i++) {
        const int s = i & 3;
        asm volatile("cp.async.wait_group 2;" ::: "memory");
        __syncthreads();
        const int j = i + 3;
        if (j < GCHUNKS) LOAD_CHUNK(j, j & 3);
        asm volatile("cp.async.commit_group;" ::: "memory");

        const uint32_t sa = sbase + s * GSTG;
#pragma unroll
        for (int ks = 0; ks < 4; ks++) {
            uint32_t a[2][4], b[4][2];
            ldsm4(a[0][0], a[0][1], a[0][2], a[0][3], sa + aoff + ks * 32);
            ldsm4(a[1][0], a[1][1], a[1][2], a[1][3], sa + aoff + 16 * GPITCH + ks * 32);
            ldsm4(b[0][0], b[0][1], b[1][0], b[1][1], sa + boff0 + ks * 32);
            ldsm4(b[2][0], b[2][1], b[3][0], b[3][1], sa + boff0 + 16 * GPITCH + ks * 32);
#pragma unroll
            for (int mt = 0; mt < 2; mt++)
#pragma unroll
                for (int nt = 0; nt < 4; nt++) {
                    mma16816(acc[mt][nt * 2 + 0], a[mt], b[nt]);
                }
            ldsm4(b[0][0], b[0][1], b[1][0], b[1][1], sa + boff0 + 32 * GPITCH + ks * 32);
            ldsm4(b[2][0], b[2][1], b[3][0], b[3][1], sa + boff0 + 48 * GPITCH + ks * 32);
#pragma unroll
            for (int mt = 0; mt < 2; mt++)
#pragma unroll
                for (int nt = 0; nt < 4; nt++) {
                    mma16816(acc[mt][nt * 2 + 1], a[mt], b[nt]);
                }
        }
    }

    const int rbase = m0 + wy * 32 + (lane >> 2);
    const int cbase = n0 + wx * 64 + (lane & 3) * 2;
#pragma unroll
    for (int mt = 0; mt < 2; mt++) {
#pragma unroll
        for (int j = 0; j < 8; j++) {
            int nt = j >> 1, half = j & 1;
            int col = cbase + half * 32 + nt * 8;
            float v[4];
#pragma unroll
            for (int q = 0; q < 4; q++) {
                float x = acc[mt][j][q];
                v[q] = act ? (1.f / (1.f + expf(-x))) : x;
            }
            float* d0 = C + (size_t)(rbase + mt * 16) * Ntot + col;
            float* d1 = C + (size_t)(rbase + mt * 16 + 8) * Ntot + col;
            *(float2*)d0 = make_float2(v[0], v[1]);
            *(float2*)d1 = make_float2(v[2], v[3]);
        }
    }
}

// ---------------- fp32 -> fp16 hi/lo split -----------------------------------
__global__ void __launch_bounds__(256) k_cvt_hilo(const float* __restrict__ src,
                                                  __half* __restrict__ hi,
                                                  __half* __restrict__ lo, int n4) {
    int i = blockIdx.x * 256 + threadIdx.x;
    if (i >= n4) return;
    float4 x = ((const float4*)src)[i];
    float xs[4] = {x.x, x.y, x.z, x.w};
    __half h[4], l[4];
#pragma unroll
    for (int j = 0; j < 4; j++) {
        h[j] = __float2half(xs[j]);
        l[j] = __float2half(xs[j] - __half2float(h[j]));
    }
    ((uint2*)hi)[i] = *(uint2*)h;
    ((uint2*)lo)[i] = *(uint2*)l;
}

// ---------------- fp32 -> fp16 single ----------------------------------------
__global__ void __launch_bounds__(256) k_cvt_f16(const float* __restrict__ src,
                                                 __half* __restrict__ dst, int n4) {
    int i = blockIdx.x * 256 + threadIdx.x;
    if (i >= n4) return;
    float4 x = ((const float4*)src)[i];
    __half h[4] = {__float2half(x.x), __float2half(x.y), __float2half(x.z), __float2half(x.w)};
    ((uint2*)dst)[i] = *(uint2*)h;
}

// ---------------- split qkv + per-head rmsnorm + rope; one warp per (b,t,h) --
__global__ void __launch_bounds__(128) k_norm_rope(const float* __restrict__ qw,
                                                   const float* __restrict__ kw,
                                                   const int* __restrict__ pos) {
    int warp = blockIdx.x * 4 + (threadIdx.x >> 5);
    int lane = threadIdx.x & 31;
    int h = warp & (HH - 1);
    int bt = warp >> 4;
    size_t base = (size_t)bt * O3 + h * DD + lane * 4;

    float4 q4 = *(const float4*)(g_qkv + base);
    float4 k4 = *(const float4*)(g_qkv + base + HDIM);
    float4 v4 = *(const float4*)(g_qkv + base + 2 * HDIM);
    float qv[4] = {q4.x, q4.y, q4.z, q4.w};
    float kv[4] = {k4.x, k4.y, k4.z, k4.w};

    float sq = qv[0] * qv[0] + qv[1] * qv[1] + qv[2] * qv[2] + qv[3] * qv[3];
    float sk = kv[0] * kv[0] + kv[1] * kv[1] + kv[2] * kv[2] + kv[3] * kv[3];
#pragma unroll
    for (int off = 16; off > 0; off >>= 1) {
        sq += __shfl_xor_sync(0xffffffffu, sq, off);
        sk += __shfl_xor_sync(0xffffffffu, sk, off);
    }
    float rq = rsqrtf(sq * (1.f / DD) + 1e-6f);
    float rk = rsqrtf(sk * (1.f / DD) + 1e-6f);
    float4 wq = *(const float4*)(qw + lane * 4);
    float4 wk = *(const float4*)(kw + lane * 4);
    float wqa[4] = {wq.x, wq.y, wq.z, wq.w};
    float wka[4] = {wk.x, wk.y, wk.z, wk.w};
#pragma unroll
    for (int j = 0; j < 4; j++) {
        qv[j] = qv[j] * rq * wqa[j];
        kv[j] = kv[j] * rk * wka[j];
    }

    float p = (float)pos[bt];
    float qp[4], kp[4];
#pragma unroll
    for (int j = 0; j < 4; j++) {
        qp[j] = __shfl_xor_sync(0xffffffffu, qv[j], 8);
        kp[j] = __shfl_xor_sync(0xffffffffu, kv[j], 8);
    }
    if (lane < 16) {
        float sgn = (lane < 8) ? -1.f : 1.f;
        int jb = (lane & 7) * 4;
#pragma unroll
        for (int j = 0; j < 4; j++) {
            float inv = exp2f(-(float)(jb + j) * 0.4152410118609203f);
            float ang = p * inv;
            float sn, cs;
            sincosf(ang, &sn, &cs);
            qv[j] = qv[j] * cs + sgn * qp[j] * sn;
            kv[j] = kv[j] * cs + sgn * kp[j] * sn;
        }
    }

    int b = bt >> 12, t = bt & (TT - 1);
    size_t ob = ((size_t)(b * HH + h) * TT + t) * DD + lane * 4;
    const float qscale = 0.08838834764831845f;
    *(float4*)(g_q + ob) = make_float4(qv[0] * qscale, qv[1] * qscale, qv[2] * qscale, qv[3] * qscale);
    *(float4*)(g_k + ob) = make_float4(kv[0], kv[1], kv[2], kv[3]);
    *(float4*)(g_v + ob) = v4;
}

// ---------------- pass A: per (b,h,c): att(masked), intra = att@v, U ---------
#define QK_P 68
__global__ void __launch_bounds__(256, 1) k_chunk_local() {
    extern __shared__ __align__(16) float sm[];
    float* qsT = sm;
    float* ksT = qsT + 128 * QK_P;
    float* vs = ksT + 128 * QK_P;
    float* att = vs + 64 * 128;
    float* kdec = att + 64 * 65;

    const int tid = threadIdx.x;
    const int c = blockIdx.x & (NCH - 1);
    const int bh = blockIdx.x >> 6;
    const int h = bh & (HH - 1);
    const float slope = head_slope(h);
    const size_t tbase = ((size_t)bh * TT + c * CH) * DD;

#pragma unroll
    for (int l = 0; l < 8; l++) {
        int idx = tid + l * 256;
        int row = idx >> 5;
        int c0 = (idx & 31) << 2;
        float4 a = *(const float4*)(g_q + tbase + row * DD + c0);
        float4 b = *(const float4*)(g_k + tbase + row * DD + c0);
        float4 vv = *(const float4*)(g_v + tbase + row * DD + c0);
        qsT[(c0 + 0) * QK_P + row] = a.x;
        qsT[(c0 + 1) * QK_P + row] = a.y;
        qsT[(c0 + 2) * QK_P + row] = a.z;
        qsT[(c0 + 3) * QK_P + row] = a.w;
        ksT[(c0 + 0) * QK_P + row] = b.x;
        ksT[(c0 + 1) * QK_P + row] = b.y;
        ksT[(c0 + 2) * QK_P + row] = b.z;
        ksT[(c0 + 3) * QK_P + row] = b.w;
        *(float4*)&vs[row * DD + c0] = vv;
    }
    if (tid < 64) kdec[tid] = expf(slope * (float)(63 - tid));
    __syncthreads();

    const int tx = tid & 15, ty = tid >> 4;

    {
        float accA[4][4];
#pragma unroll
        for (int i = 0; i < 4; i++)
#pragma unroll
            for (int j = 0; j < 4; j++) accA[i][j] = 0.f;
#pragma unroll 4
        for (int d = 0; d < 128; d++) {
            float a[4], b[4];
            *(float4*)a = *(const float4*)&qsT[d * QK_P + 4 * ty];
            *(float4*)b = *(const float4*)&ksT[d * QK_P + 4 * tx];
#pragma unroll
            for (int i = 0; i < 4; i++)
#pragma unroll
                for (int j = 0; j < 4; j++) accA[i][j] += a[i] * b[j];
        }
#pragma unroll
        for (int i = 0; i < 4; i++)
#pragma unroll
            for (int j = 0; j < 4; j++) {
                int ri = 4 * ty + i, cj = 4 * tx + j;
                float m = (ri >= cj) ? expf(slope * (float)(ri - cj)) : 0.f;
                att[ri * 65 + cj] = accA[i][j] * m;
            }
    }
    __syncthreads();

    {
        float accI[4][8];
#pragma unroll
        for (int i = 0; i < 4; i++)
#pragma unroll
            for (int j = 0; j < 8; j++) accI[i][j] = 0.f;
#pragma unroll 2
        for (int j = 0; j < 64; j++) {
            float a[4];
#pragma unroll
            for (int r = 0; r < 4; r++) a[r] = att[(4 * ty + r) * 65 + j];
            float b[8];
            *(float4*)(b) = *(const float4*)&vs[j * DD + 8 * tx];
            *(float4*)(b + 4) = *(const float4*)&vs[j * DD + 8 * tx + 4];
#pragma unroll
            for (int r = 0; r < 4; r++)
#pragma unroll
                for (int e = 0; e < 8; e++) accI[r][e] += a[r] * b[e];
        }
#pragma unroll
        for (int r = 0; r < 4; r++) {
            float* dst = g_o + tbase + (size_t)(4 * ty + r) * DD + 8 * tx;
            *(float4*)(dst) = make_float4(accI[r][0], accI[r][1], accI[r][2], accI[r][3]);
            *(float4*)(dst + 4) = make_float4(accI[r][4], accI[r][5], accI[r][6], accI[r][7]);
        }
    }

    {
        float accU[8][8];
#pragma unroll
        for (int i = 0; i < 8; i++)
#pragma unroll
            for (int j = 0; j < 8; j++) accU[i][j] = 0.f;
#pragma unroll 2
        for (int i = 0; i < 64; i++) {
            float kd = kdec[i];
            float a[8];
#pragma unroll
            for (int r = 0; r < 8; r++) a[r] = ksT[(8 * ty + r) * QK_P + i];
            float b[8];
            *(float4*)(b) = *(const float4*)&vs[i * DD + 8 * tx];
            *(float4*)(b + 4) = *(const float4*)&vs[i * DD + 8 * tx + 4];
#pragma unroll
            for (int e = 0; e < 8; e++) b[e] *= kd;
#pragma unroll
            for (int r = 0; r < 8; r++)
#pragma unroll
                for (int e = 0; e < 8; e++) accU[r][e] += a[r] * b[e];
        }
        size_t ub = ((size_t)bh * NCH + c) * (DD * DD);
#pragma unroll
        for (int r = 0; r < 8; r++) {
            float* dst = g_U + ub + (size_t)(8 * ty + r) * DD + 8 * tx;
            *(float4*)(dst) = make_float4(accU[r][0], accU[r][1], accU[r][2], accU[r][3]);
            *(float4*)(dst + 4) = make_float4(accU[r][4], accU[r][5], accU[r][6], accU[r][7]);
        }
    }
}

// ---------------- pass B: decayed prefix scan of U over chunks -> S_c ---------
__global__ void __launch_bounds__(256) k_scan() {
    int g = blockIdx.x * 256 + threadIdx.x;
    int bh = g >> 14;
    int de = g & 16383;
    float chdec = expf(head_slope(bh & (HH - 1)) * 64.f);
    size_t base = (size_t)bh * NCH * (DD * DD) + de;
    float s = 0.f;
    for (int c = 0; c < NCH; c++) {
        size_t idx = base + (size_t)c * (DD * DD);
        g_S[idx] = s;
        s = s * chdec + g_U[idx];
    }
}

// ---------------- pass C: inter = (q * qdec) @ S_c, accumulate into g_o -------
__global__ void __launch_bounds__(256, 1) k_inter() {
    extern __shared__ __align__(16) float sm2[];
    float* qs = sm2;
    float* Ss = qs + 64 * 132;
    const int tid = threadIdx.x;
    const int c = blockIdx.x & (NCH - 1);
    const int bh = blockIdx.x >> 6;
    const float slope = head_slope(bh & (HH - 1));
    const size_t tbase = ((size_t)bh * TT + c * CH) * DD;
    const size_t sbase = ((size_t)bh * NCH + c) * (DD * DD);

#pragma unroll
    for (int l = 0; l < 8; l++) {
        int idx = tid + l * 256;
        int row = idx >> 5;
        int c0 = (idx & 31) << 2;
        *(float4*)&qs[row * 132 + c0] = *(const float4*)(g_q + tbase + row * DD + c0);
    }
#pragma unroll
    for (int l = 0; l < 16; l++) {
        int idx = tid + l * 256;
        *(float4*)&Ss[idx * 4] = *(const float4*)(g_S + sbase + (size_t)idx * 4);
    }
    __syncthreads();

    const int tx = tid & 15, ty = tid >> 4;
    float acc[4][8];
#pragma unroll
    for (int i = 0; i < 4; i++)
#pragma unroll
        for (int j = 0; j < 8; j++) acc[i][j] = 0.f;
#pragma unroll 2
    for (int d = 0; d < 128; d++) {
        float a[4];
#pragma unroll
        for (int r = 0; r < 4; r++) a[r] = qs[(4 * ty + r) * 132 + d];
        float b[8];
        *(float4*)(b) = *(const float4*)&Ss[d * DD + 8 * tx];
        *(float4*)(b + 4) = *(const float4*)&Ss[d * DD + 8 * tx + 4];
#pragma unroll
        for (int r = 0; r < 4; r++)
#pragma unroll
            for (int e = 0; e < 8; e++) acc[r][e] += a[r] * b[e];
    }
#pragma unroll
    for (int r = 0; r < 4; r++) {
        int i = 4 * ty + r;
        float qd = expf(slope * (float)(i + 1));
        float* dst = g_o + tbase + (size_t)i * DD + 8 * tx;
        float4 c0 = *(float4*)(dst);
        float4 c1 = *(float4*)(dst + 4);
        c0.x += acc[r][0] * qd; c0.y += acc[r][1] * qd;
        c0.z += acc[r][2] * qd; c0.w += acc[r][3] * qd;
        c1.x += acc[r][4] * qd; c1.y += acc[r][5] * qd;
        c1.z += acc[r][6] * qd; c1.w += acc[r][7] * qd;
        *(float4*)(dst) = c0;
        *(float4*)(dst + 4) = c1;
    }
}

// ---------------- group rmsnorm * g_norm_w * gate -> fp16 hi/lo ---------------
__global__ void __launch_bounds__(128) k_gnorm_gate(const float* __restrict__ gnw) {
    int warp = blockIdx.x * 4 + (threadIdx.x >> 5);
    int lane = threadIdx.x & 31;
    int h = warp & (HH - 1);
    int bt = warp >> 4;
    int b = bt >> 12, t = bt & (TT - 1);
    size_t ob = ((size_t)(b * HH + h) * TT + t) * DD + lane * 4;
    float4 x4 = *(const float4*)(g_o + ob);
    float x[4] = {x4.x, x4.y, x4.z, x4.w};
    float ss = x[0] * x[0] + x[1] * x[1] + x[2] * x[2] + x[3] * x[3];
#pragma unroll
    for (int off = 16; off > 0; off >>= 1) ss += __shfl_xor_sync(0xffffffffu, ss, off);
    float r = rsqrtf(ss * (1.f / DD) + 1e-6f);
    float4 w = *(const float4*)(gnw + h * DD + lane * 4);
    size_t gb = (size_t)bt * HDIM + h * DD + lane * 4;
    float4 g = *(const float4*)(g_gate + gb);
    float y[4] = {x[0] * r * w.x * g.x, x[1] * r * w.y * g.y,
                  x[2] * r * w.z * g.z, x[3] * r * w.w * g.w};
    __half hb[4], lb[4];
#pragma unroll
    for (int j = 0; j < 4; j++) {
        hb[j] = __float2half(y[j]);
        lb[j] = __float2half(y[j] - __half2float(hb[j]));
    }
    *(uint2*)(g_onh + gb) = *(uint2*)hb;
    *(uint2*)(g_onl + gb) = *(uint2*)lb;
}

// -----------------------------------------------------------------------------
extern "C" void kernel_launch(void* const* d_in, const int* in_sizes, int n_in,
                              void* d_out, int out_size) {
    const float* hidden = (const float*)d_in[0];
    const float* w_qkv = (const float*)d_in[1];
    const float* q_ln_w = (const float*)d_in[2];
    const float* k_ln_w = (const float*)d_in[3];
    const float* g_norm_w = (const float*)d_in[4];
    const float* w_g_proj = (const float*)d_in[5];
    const float* w_dense = (const float*)d_in[6];
    const int* pos = (const int*)d_in[7];
    float* out = (float*)d_out;

    void *p_qkv, *p_gate;
    void *p_hh, *p_hl, *p_wqh, *p_wgh, *p_wdh, *p_onh, *p_onl;
    cudaGetSymbolAddress(&p_qkv, g_qkv);
    cudaGetSymbolAddress(&p_gate, g_gate);
    cudaGetSymbolAddress(&p_hh, g_hh);
    cudaGetSymbolAddress(&p_hl, g_hl);
    cudaGetSymbolAddress(&p_wqh, g_wqh);
    cudaGetSymbolAddress(&p_wgh, g_wgh);
    cudaGetSymbolAddress(&p_wdh, g_wdh);
    cudaGetSymbolAddress(&p_onh, g_onh);
    cudaGetSymbolAddress(&p_onl, g_onl);

    const int smem3 = (128 * QK_P * 2 + 64 * 128 + 64 * 65 + 64) * 4;  // 119296
    const int smem5 = (64 * 132 + 128 * 128) * 4;                      // 99328
    const int smemG = GNSTG * GSTG;                                    // 147456
    cudaFuncSetAttribute(k_chunk_local, cudaFuncAttributeMaxDynamicSharedMemorySize, smem3);
    cudaFuncSetAttribute(k_inter, cudaFuncAttributeMaxDynamicSharedMemorySize, smem5);
    cudaFuncSetAttribute(gemm_f16split, cudaFuncAttributeMaxDynamicSharedMemorySize, smemG);

    // 0. conversions
    {
        int n4;
        n4 = BB * TT * HDIM / 4;
        k_cvt_hilo<<<(n4 + 255) / 256, 256>>>(hidden, (__half*)p_hh, (__half*)p_hl, n4);
        n4 = O3 * HDIM / 4;
        k_cvt_f16<<<(n4 + 255) / 256, 256>>>(w_qkv, (__half*)p_wqh, n4);
        n4 = HDIM * HDIM / 4;
        k_cvt_f16<<<(n4 + 255) / 256, 256>>>(w_g_proj, (__half*)p_wgh, n4);
        k_cvt_f16<<<(n4 + 255) / 256, 256>>>(w_dense, (__half*)p_wdh, n4);
    }

    // 1. qkv = hidden @ w_qkv^T   (mma.sync split-fp16)
    gemm_f16split<<<dim3(O3 / 128, (BB * TT) / 128), 256, smemG>>>(
        (const __half*)p_hh, (const __half*)p_hl, (const __half*)p_wqh,
        (float*)p_qkv, O3, 0);
    // 2. split + rmsnorm + rope
    k_norm_rope<<<(BB * TT * HH) / 4, 128>>>(q_ln_w, k_ln_w, pos);
    // 3. per-chunk local
    k_chunk_local<<<BB * HH * NCH, 256, smem3>>>();
    // 4. decayed prefix scan
    k_scan<<<(BB * HH * DD * DD) / 256, 256>>>();
    // 5. inter-chunk
    k_inter<<<BB * HH * NCH, 256, smem5>>>();
    // 6. gate = sigmoid(hidden @ w_g_proj^T)
    gemm_f16split<<<dim3(HDIM / 128, (BB * TT) / 128), 256, smemG>>>(
        (const __half*)p_hh, (const __half*)p_hl, (const __half*)p_wgh,
        (float*)p_gate, HDIM, 1);
    // 7. group rmsnorm * weight * gate -> fp16 hi/lo
    k_gnorm_gate<<<(BB * TT * HH) / 4, 128>>>(g_norm_w);
    // 8. out = on @ w_dense^T
    gemm_f16split<<<dim3(HDIM / 128, (BB * TT) / 128), 256, smemG>>>(
        (const __half*)p_onh, (const __half*)p_onl, (const __half*)p_wdh,
        out, HDIM, 0);
}

// round 5
// speedup vs baseline: 2.7225x; 1.0546x over previous
#include <cuda_runtime.h>
#include <cuda_fp16.h>
#include <cstdint>

#define BB 2
#define TT 4096
#define HH 16
#define DD 128
#define HDIM 2048
#define O3 6144
#define NCH 64
#define CH 64

// ---------------- scratch (static device globals; no runtime allocation) ----
static __device__ float g_qkv[(size_t)BB * TT * O3];          // (bt, o)
static __device__ float g_q[(size_t)BB * HH * TT * DD];       // (b,h,t,d)
static __device__ float g_k[(size_t)BB * HH * TT * DD];
static __device__ float g_v[(size_t)BB * HH * TT * DD];
static __device__ float g_o[(size_t)BB * HH * TT * DD];
static __device__ float g_gate[(size_t)BB * TT * HDIM];       // (bt, hd) sigmoid'ed
static __device__ float g_U[(size_t)BB * HH * NCH * DD * DD]; // per-chunk KV outer
static __device__ float g_S[(size_t)BB * HH * NCH * DD * DD]; // scanned state

// fp16 operands: activations split hi/lo, weights single
static __device__ __half g_hh[(size_t)BB * TT * HDIM];   // hidden hi
static __device__ __half g_hl[(size_t)BB * TT * HDIM];   // hidden lo
static __device__ __half g_wqh[(size_t)O3 * HDIM];
static __device__ __half g_wgh[(size_t)HDIM * HDIM];
static __device__ __half g_wdh[(size_t)HDIM * HDIM];
static __device__ __half g_onh[(size_t)BB * TT * HDIM];  // gated/normed o hi
static __device__ __half g_onl[(size_t)BB * TT * HDIM];

__device__ __forceinline__ float head_slope(int h) {
    float a = (float)exp2(-0.5 * (double)(h + 1));
    return (float)(-(double)a * (1.0 - 11.0 / 31.0 + 1e-5));
}

__device__ __forceinline__ uint32_t s2u(const void* p) {
    uint32_t a;
    asm("{ .reg .u64 t; cvta.to.shared.u64 t, %1; cvt.u32.u64 %0, t; }" : "=r"(a) : "l"(p));
    return a;
}

__device__ __forceinline__ void cp16(uint32_t dst, const void* src) {
    asm volatile("cp.async.cg.shared.global [%0], [%1], 16;" :: "r"(dst), "l"(src));
}

__device__ __forceinline__ void ldsm4(uint32_t& r0, uint32_t& r1, uint32_t& r2, uint32_t& r3,
                                      uint32_t addr) {
    asm volatile("ldmatrix.sync.aligned.m8n8.x4.shared.b16 {%0,%1,%2,%3}, [%4];"
                 : "=r"(r0), "=r"(r1), "=r"(r2), "=r"(r3) : "r"(addr));
}

__device__ __forceinline__ void mma16816(float* c, const uint32_t* a, const uint32_t* b) {
    asm volatile(
        "mma.sync.aligned.m16n8k16.row.col.f32.f16.f16.f32 "
        "{%0,%1,%2,%3}, {%4,%5,%6,%7}, {%8,%9}, {%0,%1,%2,%3};"
        : "+f"(c[0]), "+f"(c[1]), "+f"(c[2]), "+f"(c[3])
        : "r"(a[0]), "r"(a[1]), "r"(a[2]), "r"(a[3]), "r"(b[0]), "r"(b[1]));
}

// ======================= split-fp16 mma.sync GEMM ============================
// C[M, Ntot] = (Ah+Al)[M,2048] * B[Ntot,2048]^T   (B single fp16)
// tile 256x128, BK=64, 2 K-segments (hi*B, lo*B) -> 64 BK-chunks
#define GPITCH 144                    // bytes per smem row (64 fp16 data + pad)
#define GA_BYTES (256 * GPITCH)       // 36864
#define GB_BYTES (128 * GPITCH)       // 18432
#define GSTG (GA_BYTES + GB_BYTES)    // 55296 per stage
#define GNSTG 4
#define GCHUNKS 64

__global__ void __launch_bounds__(256, 1) gemm_f16split(
    const __half* __restrict__ Ah, const __half* __restrict__ Al,
    const __half* __restrict__ Bm,
    float* __restrict__ C, int Ntot, int act) {
    extern __shared__ __align__(128) char smem[];
    const uint32_t sbase = s2u(smem);
    const int tid = threadIdx.x;
    const int lane = tid & 31;
    const int warp = tid >> 5;
    const int wy = warp & 3;    // M: 4 x 64
    const int wx = warp >> 2;   // N: 2 x 64
    const int m0 = blockIdx.y * 256;
    const int n0 = blockIdx.x * 128;

    float acc[4][8][4];
#pragma unroll
    for (int i = 0; i < 4; i++)
#pragma unroll
        for (int j = 0; j < 8; j++)
#pragma unroll
            for (int q = 0; q < 4; q++) acc[i][j][q] = 0.f;

#define LOAD_CHUNK(c, s)                                                                \
    do {                                                                                \
        int _seg = (c) >> 5;                                                            \
        int _kk = ((c) & 31) << 6;                                                      \
        const __half* _Ab = (_seg ? Al : Ah) + (size_t)m0 * 2048 + _kk;                 \
        const __half* _Bb = Bm + (size_t)n0 * 2048 + _kk;                               \
        uint32_t _sa = sbase + (s) * GSTG;                                              \
        uint32_t _sb = _sa + GA_BYTES;                                                  \
        _Pragma("unroll") for (int t = 0; t < 8; t++) {                                 \
            int idx = tid + t * 256;                                                    \
            int row = idx >> 3, ch = idx & 7;                                           \
            cp16(_sa + row * GPITCH + ch * 16, _Ab + (size_t)row * 2048 + ch * 8);      \
        }                                                                               \
        _Pragma("unroll") for (int t = 0; t < 4; t++) {                                 \
            int idx = tid + t * 256;                                                    \
            int row = idx >> 3, ch = idx & 7;                                           \
            cp16(_sb + row * GPITCH + ch * 16, _Bb + (size_t)row * 2048 + ch * 8);      \
        }                                                                               \
    } while (0)

    // prologue: chunks 0..2 into stages 0..2
    for (int c = 0; c < 3; c++) {
        LOAD_CHUNK(c, c);
        asm volatile("cp.async.commit_group;" ::: "memory");
    }

    // per-thread ldmatrix base offsets
    const uint32_t aoff = (uint32_t)(wy * 64 + (lane & 15)) * GPITCH + (lane >> 4) * 16;
    const int brow = (lane & 7) + ((lane >> 4) << 3);
    const uint32_t boff0 = GA_BYTES + (uint32_t)(wx * 64 + brow) * GPITCH + ((lane >> 3) & 1) * 16;

    for (int i = 0; i < GCHUNKS; i++) {
        const int s = i & 3;
        asm volatile("cp.async.wait_group 2;" ::: "memory");
        __syncthreads();
        const int j = i + 3;
        if (j < GCHUNKS) LOAD_CHUNK(j, j & 3);
        asm volatile("cp.async.commit_group;" ::: "memory");

        const uint32_t sa = sbase + s * GSTG;
#pragma unroll
        for (int ks = 0; ks < 4; ks++) {
            uint32_t a[4][4], b[4][2];
#pragma unroll
            for (int mt = 0; mt < 4; mt++)
                ldsm4(a[mt][0], a[mt][1], a[mt][2], a[mt][3],
                      sa + aoff + mt * 16 * GPITCH + ks * 32);
            ldsm4(b[0][0], b[0][1], b[1][0], b[1][1], sa + boff0 + ks * 32);
            ldsm4(b[2][0], b[2][1], b[3][0], b[3][1], sa + boff0 + 16 * GPITCH + ks * 32);
#pragma unroll
            for (int mt = 0; mt < 4; mt++)
#pragma unroll
                for (int nt = 0; nt < 4; nt++) {
                    mma16816(acc[mt][nt * 2 + 0], a[mt], b[nt]);
                }
            ldsm4(b[0][0], b[0][1], b[1][0], b[1][1], sa + boff0 + 32 * GPITCH + ks * 32);
            ldsm4(b[2][0], b[2][1], b[3][0], b[3][1], sa + boff0 + 48 * GPITCH + ks * 32);
#pragma unroll
            for (int mt = 0; mt < 4; mt++)
#pragma unroll
                for (int nt = 0; nt < 4; nt++) {
                    mma16816(acc[mt][nt * 2 + 1], a[mt], b[nt]);
                }
        }
    }

    const int rbase = m0 + wy * 64 + (lane >> 2);
    const int cbase = n0 + wx * 64 + (lane & 3) * 2;
#pragma unroll
    for (int mt = 0; mt < 4; mt++) {
#pragma unroll
        for (int j = 0; j < 8; j++) {
            int nt = j >> 1, half = j & 1;
            int col = cbase + half * 32 + nt * 8;
            float v[4];
#pragma unroll
            for (int q = 0; q < 4; q++) {
                float x = acc[mt][j][q];
                v[q] = act ? (1.f / (1.f + expf(-x))) : x;
            }
            float* d0 = C + (size_t)(rbase + mt * 16) * Ntot + col;
            float* d1 = C + (size_t)(rbase + mt * 16 + 8) * Ntot + col;
            *(float2*)d0 = make_float2(v[0], v[1]);
            *(float2*)d1 = make_float2(v[2], v[3]);
        }
    }
}

// ---------------- fp32 -> fp16 hi/lo split -----------------------------------
__global__ void __launch_bounds__(256) k_cvt_hilo(const float* __restrict__ src,
                                                  __half* __restrict__ hi,
                                                  __half* __restrict__ lo, int n4) {
    int i = blockIdx.x * 256 + threadIdx.x;
    if (i >= n4) return;
    float4 x = ((const float4*)src)[i];
    float xs[4] = {x.x, x.y, x.z, x.w};
    __half h[4], l[4];
#pragma unroll
    for (int j = 0; j < 4; j++) {
        h[j] = __float2half(xs[j]);
        l[j] = __float2half(xs[j] - __half2float(h[j]));
    }
    ((uint2*)hi)[i] = *(uint2*)h;
    ((uint2*)lo)[i] = *(uint2*)l;
}

// ---------------- fp32 -> fp16 single ----------------------------------------
__global__ void __launch_bounds__(256) k_cvt_f16(const float* __restrict__ src,
                                                 __half* __restrict__ dst, int n4) {
    int i = blockIdx.x * 256 + threadIdx.x;
    if (i >= n4) return;
    float4 x = ((const float4*)src)[i];
    __half h[4] = {__float2half(x.x), __float2half(x.y), __float2half(x.z), __float2half(x.w)};
    ((uint2*)dst)[i] = *(uint2*)h;
}

// ---------------- split qkv + per-head rmsnorm + rope; one warp per (b,t,h) --
__global__ void __launch_bounds__(128) k_norm_rope(const float* __restrict__ qw,
                                                   const float* __restrict__ kw,
                                                   const int* __restrict__ pos) {
    int warp = blockIdx.x * 4 + (threadIdx.x >> 5);
    int lane = threadIdx.x & 31;
    int h = warp & (HH - 1);
    int bt = warp >> 4;
    size_t base = (size_t)bt * O3 + h * DD + lane * 4;

    float4 q4 = *(const float4*)(g_qkv + base);
    float4 k4 = *(const float4*)(g_qkv + base + HDIM);
    float4 v4 = *(const float4*)(g_qkv + base + 2 * HDIM);
    float qv[4] = {q4.x, q4.y, q4.z, q4.w};
    float kv[4] = {k4.x, k4.y, k4.z, k4.w};

    float sq = qv[0] * qv[0] + qv[1] * qv[1] + qv[2] * qv[2] + qv[3] * qv[3];
    float sk = kv[0] * kv[0] + kv[1] * kv[1] + kv[2] * kv[2] + kv[3] * kv[3];
#pragma unroll
    for (int off = 16; off > 0; off >>= 1) {
        sq += __shfl_xor_sync(0xffffffffu, sq, off);
        sk += __shfl_xor_sync(0xffffffffu, sk, off);
    }
    float rq = rsqrtf(sq * (1.f / DD) + 1e-6f);
    float rk = rsqrtf(sk * (1.f / DD) + 1e-6f);
    float4 wq = *(const float4*)(qw + lane * 4);
    float4 wk = *(const float4*)(kw + lane * 4);
    float wqa[4] = {wq.x, wq.y, wq.z, wq.w};
    float wka[4] = {wk.x, wk.y, wk.z, wk.w};
#pragma unroll
    for (int j = 0; j < 4; j++) {
        qv[j] = qv[j] * rq * wqa[j];
        kv[j] = kv[j] * rk * wka[j];
    }

    float p = (float)pos[bt];
    float qp[4], kp[4];
#pragma unroll
    for (int j = 0; j < 4; j++) {
        qp[j] = __shfl_xor_sync(0xffffffffu, qv[j], 8);
        kp[j] = __shfl_xor_sync(0xffffffffu, kv[j], 8);
    }
    if (lane < 16) {
        float sgn = (lane < 8) ? -1.f : 1.f;
        int jb = (lane & 7) * 4;
#pragma unroll
        for (int j = 0; j < 4; j++) {
            float inv = exp2f(-(float)(jb + j) * 0.4152410118609203f);
            float ang = p * inv;
            float sn, cs;
            sincosf(ang, &sn, &cs);
            qv[j] = qv[j] * cs + sgn * qp[j] * sn;
            kv[j] = kv[j] * cs + sgn * kp[j] * sn;
        }
    }

    int b = bt >> 12, t = bt & (TT - 1);
    size_t ob = ((size_t)(b * HH + h) * TT + t) * DD + lane * 4;
    const float qscale = 0.08838834764831845f;
    *(float4*)(g_q + ob) = make_float4(qv[0] * qscale, qv[1] * qscale, qv[2] * qscale, qv[3] * qscale);
    *(float4*)(g_k + ob) = make_float4(kv[0], kv[1], kv[2], kv[3]);
    *(float4*)(g_v + ob) = v4;
}

// ---------------- pass A: per (b,h,c): att(masked), intra = att@v, U ---------
#define QK_P 68
__global__ void __launch_bounds__(256, 1) k_chunk_local() {
    extern __shared__ __align__(16) float sm[];
    float* qsT = sm;
    float* ksT = qsT + 128 * QK_P;
    float* vs = ksT + 128 * QK_P;
    float* att = vs + 64 * 128;
    float* kdec = att + 64 * 65;

    const int tid = threadIdx.x;
    const int c = blockIdx.x & (NCH - 1);
    const int bh = blockIdx.x >> 6;
    const int h = bh & (HH - 1);
    const float slope = head_slope(h);
    const size_t tbase = ((size_t)bh * TT + c * CH) * DD;

#pragma unroll
    for (int l = 0; l < 8; l++) {
        int idx = tid + l * 256;
        int row = idx >> 5;
        int c0 = (idx & 31) << 2;
        float4 a = *(const float4*)(g_q + tbase + row * DD + c0);
        float4 b = *(const float4*)(g_k + tbase + row * DD + c0);
        float4 vv = *(const float4*)(g_v + tbase + row * DD + c0);
        qsT[(c0 + 0) * QK_P + row] = a.x;
        qsT[(c0 + 1) * QK_P + row] = a.y;
        qsT[(c0 + 2) * QK_P + row] = a.z;
        qsT[(c0 + 3) * QK_P + row] = a.w;
        ksT[(c0 + 0) * QK_P + row] = b.x;
        ksT[(c0 + 1) * QK_P + row] = b.y;
        ksT[(c0 + 2) * QK_P + row] = b.z;
        ksT[(c0 + 3) * QK_P + row] = b.w;
        *(float4*)&vs[row * DD + c0] = vv;
    }
    if (tid < 64) kdec[tid] = expf(slope * (float)(63 - tid));
    __syncthreads();

    const int tx = tid & 15, ty = tid >> 4;

    {
        float accA[4][4];
#pragma unroll
        for (int i = 0; i < 4; i++)
#pragma unroll
            for (int j = 0; j < 4; j++) accA[i][j] = 0.f;
#pragma unroll 4
        for (int d = 0; d < 128; d++) {
            float a[4], b[4];
            *(float4*)a = *(const float4*)&qsT[d * QK_P + 4 * ty];
            *(float4*)b = *(const float4*)&ksT[d * QK_P + 4 * tx];
#pragma unroll
            for (int i = 0; i < 4; i++)
#pragma unroll
                for (int j = 0; j < 4; j++) accA[i][j] += a[i] * b[j];
        }
#pragma unroll
        for (int i = 0; i < 4; i++)
#pragma unroll
            for (int j = 0; j < 4; j++) {
                int ri = 4 * ty + i, cj = 4 * tx + j;
                float m = (ri >= cj) ? expf(slope * (float)(ri - cj)) : 0.f;
                att[ri * 65 + cj] = accA[i][j] * m;
            }
    }
    __syncthreads();

    {
        float accI[4][8];
#pragma unroll
        for (int i = 0; i < 4; i++)
#pragma unroll
            for (int j = 0; j < 8; j++) accI[i][j] = 0.f;
#pragma unroll 2
        for (int j = 0; j < 64; j++) {
            float a[4];
#pragma unroll
            for (int r = 0; r < 4; r++) a[r] = att[(4 * ty + r) * 65 + j];
            float b[8];
            *(float4*)(b) = *(const float4*)&vs[j * DD + 8 * tx];
            *(float4*)(b + 4) = *(const float4*)&vs[j * DD + 8 * tx + 4];
#pragma unroll
            for (int r = 0; r < 4; r++)
#pragma unroll
                for (int e = 0; e < 8; e++) accI[r][e] += a[r] * b[e];
        }
#pragma unroll
        for (int r = 0; r < 4; r++) {
            float* dst = g_o + tbase + (size_t)(4 * ty + r) * DD + 8 * tx;
            *(float4*)(dst) = make_float4(accI[r][0], accI[r][1], accI[r][2], accI[r][3]);
            *(float4*)(dst + 4) = make_float4(accI[r][4], accI[r][5], accI[r][6], accI[r][7]);
        }
    }

    {
        float accU[8][8];
#pragma unroll
        for (int i = 0; i < 8; i++)
#pragma unroll
            for (int j = 0; j < 8; j++) accU[i][j] = 0.f;
#pragma unroll 2
        for (int i = 0; i < 64; i++) {
            float kd = kdec[i];
            float a[8];
#pragma unroll
            for (int r = 0; r < 8; r++) a[r] = ksT[(8 * ty + r) * QK_P + i];
            float b[8];
            *(float4*)(b) = *(const float4*)&vs[i * DD + 8 * tx];
            *(float4*)(b + 4) = *(const float4*)&vs[i * DD + 8 * tx + 4];
#pragma unroll
            for (int e = 0; e < 8; e++) b[e] *= kd;
#pragma unroll
            for (int r = 0; r < 8; r++)
#pragma unroll
                for (int e = 0; e < 8; e++) accU[r][e] += a[r] * b[e];
        }
        size_t ub = ((size_t)bh * NCH + c) * (DD * DD);
#pragma unroll
        for (int r = 0; r < 8; r++) {
            float* dst = g_U + ub + (size_t)(8 * ty + r) * DD + 8 * tx;
            *(float4*)(dst) = make_float4(accU[r][0], accU[r][1], accU[r][2], accU[r][3]);
            *(float4*)(dst + 4) = make_float4(accU[r][4], accU[r][5], accU[r][6], accU[r][7]);
        }
    }
}

// ---------------- pass B: decayed prefix scan of U over chunks -> S_c ---------
// float4 per thread: 32 bh * 4096 vec4 = 131072 threads
__global__ void __launch_bounds__(256) k_scan() {
    int g = blockIdx.x * 256 + threadIdx.x;
    int bh = g >> 12;
    int de4 = g & 4095;
    float chdec = expf(head_slope(bh & (HH - 1)) * 64.f);
    size_t base = (size_t)bh * NCH * (DD * DD) + (size_t)de4 * 4;
    float4 s = make_float4(0.f, 0.f, 0.f, 0.f);
    for (int c = 0; c < NCH; c++) {
        size_t idx = base + (size_t)c * (DD * DD);
        *(float4*)(g_S + idx) = s;
        float4 u = *(const float4*)(g_U + idx);
        s.x = s.x * chdec + u.x;
        s.y = s.y * chdec + u.y;
        s.z = s.z * chdec + u.z;
        s.w = s.w * chdec + u.w;
    }
}

// ---------------- pass C: inter = (q * qdec) @ S_c, accumulate into g_o -------
__global__ void __launch_bounds__(256, 1) k_inter() {
    extern __shared__ __align__(16) float sm2[];
    float* qs = sm2;
    float* Ss = qs + 64 * 132;
    const int tid = threadIdx.x;
    const int c = blockIdx.x & (NCH - 1);
    const int bh = blockIdx.x >> 6;
    const float slope = head_slope(bh & (HH - 1));
    const size_t tbase = ((size_t)bh * TT + c * CH) * DD;
    const size_t sbase = ((size_t)bh * NCH + c) * (DD * DD);

#pragma unroll
    for (int l = 0; l < 8; l++) {
        int idx = tid + l * 256;
        int row = idx >> 5;
        int c0 = (idx & 31) << 2;
        *(float4*)&qs[row * 132 + c0] = *(const float4*)(g_q + tbase + row * DD + c0);
    }
#pragma unroll
    for (int l = 0; l < 16; l++) {
        int idx = tid + l * 256;
        *(float4*)&Ss[idx * 4] = *(const float4*)(g_S + sbase + (size_t)idx * 4);
    }
    __syncthreads();

    const int tx = tid & 15, ty = tid >> 4;
    float acc[4][8];
#pragma unroll
    for (int i = 0; i < 4; i++)
#pragma unroll
        for (int j = 0; j < 8; j++) acc[i][j] = 0.f;
#pragma unroll 2
    for (int d = 0; d < 128; d++) {
        float a[4];
#pragma unroll
        for (int r = 0; r < 4; r++) a[r] = qs[(4 * ty + r) * 132 + d];
        float b[8];
        *(float4*)(b) = *(const float4*)&Ss[d * DD + 8 * tx];
        *(float4*)(b + 4) = *(const float4*)&Ss[d * DD + 8 * tx + 4];
#pragma unroll
        for (int r = 0; r < 4; r++)
#pragma unroll
            for (int e = 0; e < 8; e++) acc[r][e] += a[r] * b[e];
    }
#pragma unroll
    for (int r = 0; r < 4; r++) {
        int i = 4 * ty + r;
        float qd = expf(slope * (float)(i + 1));
        float* dst = g_o + tbase + (size_t)i * DD + 8 * tx;
        float4 c0 = *(float4*)(dst);
        float4 c1 = *(float4*)(dst + 4);
        c0.x += acc[r][0] * qd; c0.y += acc[r][1] * qd;
        c0.z += acc[r][2] * qd; c0.w += acc[r][3] * qd;
        c1.x += acc[r][4] * qd; c1.y += acc[r][5] * qd;
        c1.z += acc[r][6] * qd; c1.w += acc[r][7] * qd;
        *(float4*)(dst) = c0;
        *(float4*)(dst + 4) = c1;
    }
}

// ---------------- group rmsnorm * g_norm_w * gate -> fp16 hi/lo ---------------
__global__ void __launch_bounds__(128) k_gnorm_gate(const float* __restrict__ gnw) {
    int warp = blockIdx.x * 4 + (threadIdx.x >> 5);
    int lane = threadIdx.x & 31;
    int h = warp & (HH - 1);
    int bt = warp >> 4;
    int b = bt >> 12, t = bt & (TT - 1);
    size_t ob = ((size_t)(b * HH + h) * TT + t) * DD + lane * 4;
    float4 x4 = *(const float4*)(g_o + ob);
    float x[4] = {x4.x, x4.y, x4.z, x4.w};
    float ss = x[0] * x[0] + x[1] * x[1] + x[2] * x[2] + x[3] * x[3];
#pragma unroll
    for (int off = 16; off > 0; off >>= 1) ss += __shfl_xor_sync(0xffffffffu, ss, off);
    float r = rsqrtf(ss * (1.f / DD) + 1e-6f);
    float4 w = *(const float4*)(gnw + h * DD + lane * 4);
    size_t gb = (size_t)bt * HDIM + h * DD + lane * 4;
    float4 g = *(const float4*)(g_gate + gb);
    float y[4] = {x[0] * r * w.x * g.x, x[1] * r * w.y * g.y,
                  x[2] * r * w.z * g.z, x[3] * r * w.w * g.w};
    __half hb[4], lb[4];
#pragma unroll
    for (int j = 0; j < 4; j++) {
        hb[j] = __float2half(y[j]);
        lb[j] = __float2half(y[j] - __half2float(hb[j]));
    }
    *(uint2*)(g_onh + gb) = *(uint2*)hb;
    *(uint2*)(g_onl + gb) = *(uint2*)lb;
}

// -----------------------------------------------------------------------------
extern "C" void kernel_launch(void* const* d_in, const int* in_sizes, int n_in,
                              void* d_out, int out_size) {
    const float* hidden = (const float*)d_in[0];
    const float* w_qkv = (const float*)d_in[1];
    const float* q_ln_w = (const float*)d_in[2];
    const float* k_ln_w = (const float*)d_in[3];
    const float* g_norm_w = (const float*)d_in[4];
    const float* w_g_proj = (const float*)d_in[5];
    const float* w_dense = (const float*)d_in[6];
    const int* pos = (const int*)d_in[7];
    float* out = (float*)d_out;

    void *p_qkv, *p_gate;
    void *p_hh, *p_hl, *p_wqh, *p_wgh, *p_wdh, *p_onh, *p_onl;
    cudaGetSymbolAddress(&p_qkv, g_qkv);
    cudaGetSymbolAddress(&p_gate, g_gate);
    cudaGetSymbolAddress(&p_hh, g_hh);
    cudaGetSymbolAddress(&p_hl, g_hl);
    cudaGetSymbolAddress(&p_wqh, g_wqh);
    cudaGetSymbolAddress(&p_wgh, g_wgh);
    cudaGetSymbolAddress(&p_wdh, g_wdh);
    cudaGetSymbolAddress(&p_onh, g_onh);
    cudaGetSymbolAddress(&p_onl, g_onl);

    const int smem3 = (128 * QK_P * 2 + 64 * 128 + 64 * 65 + 64) * 4;  // 119296
    const int smem5 = (64 * 132 + 128 * 128) * 4;                      // 99328
    const int smemG = GNSTG * GSTG;                                    // 221184
    cudaFuncSetAttribute(k_chunk_local, cudaFuncAttributeMaxDynamicSharedMemorySize, smem3);
    cudaFuncSetAttribute(k_inter, cudaFuncAttributeMaxDynamicSharedMemorySize, smem5);
    cudaFuncSetAttribute(gemm_f16split, cudaFuncAttributeMaxDynamicSharedMemorySize, smemG);

    // 0. conversions
    {
        int n4;
        n4 = BB * TT * HDIM / 4;
        k_cvt_hilo<<<(n4 + 255) / 256, 256>>>(hidden, (__half*)p_hh, (__half*)p_hl, n4);
        n4 = O3 * HDIM / 4;
        k_cvt_f16<<<(n4 + 255) / 256, 256>>>(w_qkv, (__half*)p_wqh, n4);
        n4 = HDIM * HDIM / 4;
        k_cvt_f16<<<(n4 + 255) / 256, 256>>>(w_g_proj, (__half*)p_wgh, n4);
        k_cvt_f16<<<(n4 + 255) / 256, 256>>>(w_dense, (__half*)p_wdh, n4);
    }

    // 1. qkv = hidden @ w_qkv^T   (mma.sync split-fp16, 256x128 tiles)
    gemm_f16split<<<dim3(O3 / 128, (BB * TT) / 256), 256, smemG>>>(
        (const __half*)p_hh, (const __half*)p_hl, (const __half*)p_wqh,
        (float*)p_qkv, O3, 0);
    // 2. split + rmsnorm + rope
    k_norm_rope<<<(BB * TT * HH) / 4, 128>>>(q_ln_w, k_ln_w, pos);
    // 3. per-chunk local
    k_chunk_local<<<BB * HH * NCH, 256, smem3>>>();
    // 4. decayed prefix scan (float4)
    k_scan<<<(BB * HH * DD * DD / 4) / 256, 256>>>();
    // 5. inter-chunk
    k_inter<<<BB * HH * NCH, 256, smem5>>>();
    // 6. gate = sigmoid(hidden @ w_g_proj^T)
    gemm_f16split<<<dim3(HDIM / 128, (BB * TT) / 256), 256, smemG>>>(
        (const __half*)p_hh, (const __half*)p_hl, (const __half*)p_wgh,
        (float*)p_gate, HDIM, 1);
    // 7. group rmsnorm * weight * gate -> fp16 hi/lo
    k_gnorm_gate<<<(BB * TT * HH) / 4, 128>>>(g_norm_w);
    // 8. out = on @ w_dense^T
    gemm_f16split<<<dim3(HDIM / 128, (BB * TT) / 256), 256, smemG>>>(
        (const __half*)p_onh, (const __half*)p_onl, (const __half*)p_wdh,
        out, HDIM, 0);
}

// round 6
// speedup vs baseline: 2.8191x; 1.0355x over previous
#include <cuda_runtime.h>
#include <cuda_fp16.h>
#include <cstdint>

#define BB 2
#define TT 4096
#define HH 16
#define DD 128
#define HDIM 2048
#define O3 6144
#define NCH 64
#define CH 64

// ---------------- scratch (static device globals; no runtime allocation) ----
static __device__ float g_qkv[(size_t)BB * TT * O3];          // (bt, o)
static __device__ float g_q[(size_t)BB * HH * TT * DD];       // (b,h,t,d)
static __device__ float g_k[(size_t)BB * HH * TT * DD];
static __device__ float g_v[(size_t)BB * HH * TT * DD];
static __device__ float g_o[(size_t)BB * HH * TT * DD];
static __device__ float g_gate[(size_t)BB * TT * HDIM];       // (bt, hd) sigmoid'ed
static __device__ float g_U[(size_t)BB * HH * NCH * DD * DD]; // per-chunk KV outer
static __device__ float g_S[(size_t)BB * HH * NCH * DD * DD]; // scanned state

// fp16 operands: activations split hi/lo, weights single
static __device__ __half g_hh[(size_t)BB * TT * HDIM];   // hidden hi
static __device__ __half g_hl[(size_t)BB * TT * HDIM];   // hidden lo
static __device__ __half g_wqh[(size_t)O3 * HDIM];
static __device__ __half g_wgh[(size_t)HDIM * HDIM];
static __device__ __half g_wdh[(size_t)HDIM * HDIM];
static __device__ __half g_onh[(size_t)BB * TT * HDIM];  // gated/normed o hi
static __device__ __half g_onl[(size_t)BB * TT * HDIM];

__device__ __forceinline__ float head_slope(int h) {
    float a = (float)exp2(-0.5 * (double)(h + 1));
    return (float)(-(double)a * (1.0 - 11.0 / 31.0 + 1e-5));
}

__device__ __forceinline__ uint32_t s2u(const void* p) {
    uint32_t a;
    asm("{ .reg .u64 t; cvta.to.shared.u64 t, %1; cvt.u32.u64 %0, t; }" : "=r"(a) : "l"(p));
    return a;
}

__device__ __forceinline__ void cp16(uint32_t dst, const void* src) {
    asm volatile("cp.async.cg.shared.global [%0], [%1], 16;" :: "r"(dst), "l"(src));
}

__device__ __forceinline__ void ldsm4(uint32_t& r0, uint32_t& r1, uint32_t& r2, uint32_t& r3,
                                      uint32_t addr) {
    asm volatile("ldmatrix.sync.aligned.m8n8.x4.shared.b16 {%0,%1,%2,%3}, [%4];"
                 : "=r"(r0), "=r"(r1), "=r"(r2), "=r"(r3) : "r"(addr));
}

__device__ __forceinline__ void mma16816(float* c, const uint32_t* a, const uint32_t* b) {
    asm volatile(
        "mma.sync.aligned.m16n8k16.row.col.f32.f16.f16.f32 "
        "{%0,%1,%2,%3}, {%4,%5,%6,%7}, {%8,%9}, {%0,%1,%2,%3};"
        : "+f"(c[0]), "+f"(c[1]), "+f"(c[2]), "+f"(c[3])
        : "r"(a[0]), "r"(a[1]), "r"(a[2]), "r"(a[3]), "r"(b[0]), "r"(b[1]));
}

__device__ __forceinline__ void mma16816h(uint32_t* c, const uint32_t* a, const uint32_t* b) {
    asm volatile(
        "mma.sync.aligned.m16n8k16.row.col.f16.f16.f16.f16 "
        "{%0,%1}, {%2,%3,%4,%5}, {%6,%7}, {%0,%1};"
        : "+r"(c[0]), "+r"(c[1])
        : "r"(a[0]), "r"(a[1]), "r"(a[2]), "r"(a[3]), "r"(b[0]), "r"(b[1]));
}

// ======================= split-fp16 mma.sync GEMM ============================
// C[M, Ntot] = (Ah+Al)[M,2048] * B[Ntot,2048]^T   (B single fp16)
// tile 256x128, BK=64. chunks 0..31 = lo segment (f16 accum, full-rate HMMA),
// chunks 32..63 = hi segment (f32 accum). lo accum converted to f32 at boundary.
#define GPITCH 144                    // bytes per smem row (64 fp16 data + pad)
#define GA_BYTES (256 * GPITCH)       // 36864
#define GB_BYTES (128 * GPITCH)       // 18432
#define GSTG (GA_BYTES + GB_BYTES)    // 55296 per stage
#define GNSTG 4
#define GCHUNKS 64

__global__ void __launch_bounds__(256, 1) gemm_f16split(
    const __half* __restrict__ Ah, const __half* __restrict__ Al,
    const __half* __restrict__ Bm,
    float* __restrict__ C, int Ntot, int act) {
    extern __shared__ __align__(128) char smem[];
    const uint32_t sbase = s2u(smem);
    const int tid = threadIdx.x;
    const int lane = tid & 31;
    const int warp = tid >> 5;
    const int wy = warp & 3;    // M: 4 x 64
    const int wx = warp >> 2;   // N: 2 x 64
    const int m0 = blockIdx.y * 256;
    const int n0 = blockIdx.x * 128;

#define LOAD_CHUNK(c, s)                                                                \
    do {                                                                                \
        int _seg = (c) >> 5;                                                            \
        int _kk = ((c) & 31) << 6;                                                      \
        const __half* _Ab = (_seg ? Ah : Al) + (size_t)m0 * 2048 + _kk;                 \
        const __half* _Bb = Bm + (size_t)n0 * 2048 + _kk;                               \
        uint32_t _sa = sbase + (s) * GSTG;                                              \
        uint32_t _sb = _sa + GA_BYTES;                                                  \
        _Pragma("unroll") for (int t = 0; t < 8; t++) {                                 \
            int idx = tid + t * 256;                                                    \
            int row = idx >> 3, ch = idx & 7;                                           \
            cp16(_sa + row * GPITCH + ch * 16, _Ab + (size_t)row * 2048 + ch * 8);      \
        }                                                                               \
        _Pragma("unroll") for (int t = 0; t < 4; t++) {                                 \
            int idx = tid + t * 256;                                                    \
            int row = idx >> 3, ch = idx & 7;                                           \
            cp16(_sb + row * GPITCH + ch * 16, _Bb + (size_t)row * 2048 + ch * 8);      \
        }                                                                               \
    } while (0)

#define PIPE_HEAD(i)                                                                    \
    const int s = (i) & 3;                                                              \
    asm volatile("cp.async.wait_group 2;" ::: "memory");                                \
    __syncthreads();                                                                    \
    {                                                                                   \
        const int j = (i) + 3;                                                          \
        if (j < GCHUNKS) LOAD_CHUNK(j, j & 3);                                          \
    }                                                                                   \
    asm volatile("cp.async.commit_group;" ::: "memory");                                \
    const uint32_t sa = sbase + s * GSTG;

    // prologue: chunks 0..2 into stages 0..2
    for (int c = 0; c < 3; c++) {
        LOAD_CHUNK(c, c);
        asm volatile("cp.async.commit_group;" ::: "memory");
    }

    // per-thread ldmatrix base offsets
    const uint32_t aoff = (uint32_t)(wy * 64 + (lane & 15)) * GPITCH + (lane >> 4) * 16;
    const int brow = (lane & 7) + ((lane >> 4) << 3);
    const uint32_t boff0 = GA_BYTES + (uint32_t)(wx * 64 + brow) * GPITCH + ((lane >> 3) & 1) * 16;

    float acc[4][8][4];

    // ---- pass 1: lo segment, f16 accumulation (full-rate HMMA) ----
    {
        uint32_t acc16[4][8][2];
#pragma unroll
        for (int i = 0; i < 4; i++)
#pragma unroll
            for (int j = 0; j < 8; j++) { acc16[i][j][0] = 0u; acc16[i][j][1] = 0u; }

        for (int i = 0; i < 32; i++) {
            PIPE_HEAD(i);
#pragma unroll
            for (int ks = 0; ks < 4; ks++) {
                uint32_t a[4][4], b[4][2];
#pragma unroll
                for (int mt = 0; mt < 4; mt++)
                    ldsm4(a[mt][0], a[mt][1], a[mt][2], a[mt][3],
                          sa + aoff + mt * 16 * GPITCH + ks * 32);
                ldsm4(b[0][0], b[0][1], b[1][0], b[1][1], sa + boff0 + ks * 32);
                ldsm4(b[2][0], b[2][1], b[3][0], b[3][1], sa + boff0 + 16 * GPITCH + ks * 32);
#pragma unroll
                for (int mt = 0; mt < 4; mt++)
#pragma unroll
                    for (int nt = 0; nt < 4; nt++)
                        mma16816h(acc16[mt][nt * 2 + 0], a[mt], b[nt]);
                ldsm4(b[0][0], b[0][1], b[1][0], b[1][1], sa + boff0 + 32 * GPITCH + ks * 32);
                ldsm4(b[2][0], b[2][1], b[3][0], b[3][1], sa + boff0 + 48 * GPITCH + ks * 32);
#pragma unroll
                for (int mt = 0; mt < 4; mt++)
#pragma unroll
                    for (int nt = 0; nt < 4; nt++)
                        mma16816h(acc16[mt][nt * 2 + 1], a[mt], b[nt]);
            }
        }

        // convert f16 accumulators into f32 accumulators
#pragma unroll
        for (int mt = 0; mt < 4; mt++)
#pragma unroll
            for (int j = 0; j < 8; j++) {
                float2 p0 = __half22float2(*(__half2*)&acc16[mt][j][0]);
                float2 p1 = __half22float2(*(__half2*)&acc16[mt][j][1]);
                acc[mt][j][0] = p0.x;
                acc[mt][j][1] = p0.y;
                acc[mt][j][2] = p1.x;
                acc[mt][j][3] = p1.y;
            }
    }

    // ---- pass 2: hi segment, f32 accumulation ----
    for (int i = 32; i < 64; i++) {
        PIPE_HEAD(i);
#pragma unroll
        for (int ks = 0; ks < 4; ks++) {
            uint32_t a[4][4], b[4][2];
#pragma unroll
            for (int mt = 0; mt < 4; mt++)
                ldsm4(a[mt][0], a[mt][1], a[mt][2], a[mt][3],
                      sa + aoff + mt * 16 * GPITCH + ks * 32);
            ldsm4(b[0][0], b[0][1], b[1][0], b[1][1], sa + boff0 + ks * 32);
            ldsm4(b[2][0], b[2][1], b[3][0], b[3][1], sa + boff0 + 16 * GPITCH + ks * 32);
#pragma unroll
            for (int mt = 0; mt < 4; mt++)
#pragma unroll
                for (int nt = 0; nt < 4; nt++)
                    mma16816(acc[mt][nt * 2 + 0], a[mt], b[nt]);
            ldsm4(b[0][0], b[0][1], b[1][0], b[1][1], sa + boff0 + 32 * GPITCH + ks * 32);
            ldsm4(b[2][0], b[2][1], b[3][0], b[3][1], sa + boff0 + 48 * GPITCH + ks * 32);
#pragma unroll
            for (int mt = 0; mt < 4; mt++)
#pragma unroll
                for (int nt = 0; nt < 4; nt++)
                    mma16816(acc[mt][nt * 2 + 1], a[mt], b[nt]);
        }
    }

    const int rbase = m0 + wy * 64 + (lane >> 2);
    const int cbase = n0 + wx * 64 + (lane & 3) * 2;
#pragma unroll
    for (int mt = 0; mt < 4; mt++) {
#pragma unroll
        for (int j = 0; j < 8; j++) {
            int nt = j >> 1, half = j & 1;
            int col = cbase + half * 32 + nt * 8;
            float v[4];
#pragma unroll
            for (int q = 0; q < 4; q++) {
                float x = acc[mt][j][q];
                v[q] = act ? (1.f / (1.f + expf(-x))) : x;
            }
            float* d0 = C + (size_t)(rbase + mt * 16) * Ntot + col;
            float* d1 = C + (size_t)(rbase + mt * 16 + 8) * Ntot + col;
            *(float2*)d0 = make_float2(v[0], v[1]);
            *(float2*)d1 = make_float2(v[2], v[3]);
        }
    }
}

// ---------------- fp32 -> fp16 hi/lo split -----------------------------------
__global__ void __launch_bounds__(256) k_cvt_hilo(const float* __restrict__ src,
                                                  __half* __restrict__ hi,
                                                  __half* __restrict__ lo, int n4) {
    int i = blockIdx.x * 256 + threadIdx.x;
    if (i >= n4) return;
    float4 x = ((const float4*)src)[i];
    float xs[4] = {x.x, x.y, x.z, x.w};
    __half h[4], l[4];
#pragma unroll
    for (int j = 0; j < 4; j++) {
        h[j] = __float2half(xs[j]);
        l[j] = __float2half(xs[j] - __half2float(h[j]));
    }
    ((uint2*)hi)[i] = *(uint2*)h;
    ((uint2*)lo)[i] = *(uint2*)l;
}

// ---------------- fp32 -> fp16 single ----------------------------------------
__global__ void __launch_bounds__(256) k_cvt_f16(const float* __restrict__ src,
                                                 __half* __restrict__ dst, int n4) {
    int i = blockIdx.x * 256 + threadIdx.x;
    if (i >= n4) return;
    float4 x = ((const float4*)src)[i];
    __half h[4] = {__float2half(x.x), __float2half(x.y), __float2half(x.z), __float2half(x.w)};
    ((uint2*)dst)[i] = *(uint2*)h;
}

// ---------------- split qkv + per-head rmsnorm + rope; one warp per (b,t,h) --
__global__ void __launch_bounds__(128) k_norm_rope(const float* __restrict__ qw,
                                                   const float* __restrict__ kw,
                                                   const int* __restrict__ pos) {
    int warp = blockIdx.x * 4 + (threadIdx.x >> 5);
    int lane = threadIdx.x & 31;
    int h = warp & (HH - 1);
    int bt = warp >> 4;
    size_t base = (size_t)bt * O3 + h * DD + lane * 4;

    float4 q4 = *(const float4*)(g_qkv + base);
    float4 k4 = *(const float4*)(g_qkv + base + HDIM);
    float4 v4 = *(const float4*)(g_qkv + base + 2 * HDIM);
    float qv[4] = {q4.x, q4.y, q4.z, q4.w};
    float kv[4] = {k4.x, k4.y, k4.z, k4.w};

    float sq = qv[0] * qv[0] + qv[1] * qv[1] + qv[2] * qv[2] + qv[3] * qv[3];
    float sk = kv[0] * kv[0] + kv[1] * kv[1] + kv[2] * kv[2] + kv[3] * kv[3];
#pragma unroll
    for (int off = 16; off > 0; off >>= 1) {
        sq += __shfl_xor_sync(0xffffffffu, sq, off);
        sk += __shfl_xor_sync(0xffffffffu, sk, off);
    }
    float rq = rsqrtf(sq * (1.f / DD) + 1e-6f);
    float rk = rsqrtf(sk * (1.f / DD) + 1e-6f);
    float4 wq = *(const float4*)(qw + lane * 4);
    float4 wk = *(const float4*)(kw + lane * 4);
    float wqa[4] = {wq.x, wq.y, wq.z, wq.w};
    float wka[4] = {wk.x, wk.y, wk.z, wk.w};
#pragma unroll
    for (int j = 0; j < 4; j++) {
        qv[j] = qv[j] * rq * wqa[j];
        kv[j] = kv[j] * rk * wka[j];
    }

    float p = (float)pos[bt];
    float qp[4], kp[4];
#pragma unroll
    for (int j = 0; j < 4; j++) {
        qp[j] = __shfl_xor_sync(0xffffffffu, qv[j], 8);
        kp[j] = __shfl_xor_sync(0xffffffffu, kv[j], 8);
    }
    if (lane < 16) {
        float sgn = (lane < 8) ? -1.f : 1.f;
        int jb = (lane & 7) * 4;
#pragma unroll
        for (int j = 0; j < 4; j++) {
            float inv = exp2f(-(float)(jb + j) * 0.4152410118609203f);
            float ang = p * inv;
            float sn, cs;
            sincosf(ang, &sn, &cs);
            qv[j] = qv[j] * cs + sgn * qp[j] * sn;
            kv[j] = kv[j] * cs + sgn * kp[j] * sn;
        }
    }

    int b = bt >> 12, t = bt & (TT - 1);
    size_t ob = ((size_t)(b * HH + h) * TT + t) * DD + lane * 4;
    const float qscale = 0.08838834764831845f;
    *(float4*)(g_q + ob) = make_float4(qv[0] * qscale, qv[1] * qscale, qv[2] * qscale, qv[3] * qscale);
    *(float4*)(g_k + ob) = make_float4(kv[0], kv[1], kv[2], kv[3]);
    *(float4*)(g_v + ob) = v4;
}

// ---------------- pass A: per (b,h,c): att(masked), intra = att@v, U ---------
#define QK_P 68
__global__ void __launch_bounds__(256, 1) k_chunk_local() {
    extern __shared__ __align__(16) float sm[];
    float* qsT = sm;
    float* ksT = qsT + 128 * QK_P;
    float* vs = ksT + 128 * QK_P;
    float* att = vs + 64 * 128;
    float* kdec = att + 64 * 65;

    const int tid = threadIdx.x;
    const int c = blockIdx.x & (NCH - 1);
    const int bh = blockIdx.x >> 6;
    const int h = bh & (HH - 1);
    const float slope = head_slope(h);
    const size_t tbase = ((size_t)bh * TT + c * CH) * DD;

#pragma unroll
    for (int l = 0; l < 8; l++) {
        int idx = tid + l * 256;
        int row = idx >> 5;
        int c0 = (idx & 31) << 2;
        float4 a = *(const float4*)(g_q + tbase + row * DD + c0);
        float4 b = *(const float4*)(g_k + tbase + row * DD + c0);
        float4 vv = *(const float4*)(g_v + tbase + row * DD + c0);
        qsT[(c0 + 0) * QK_P + row] = a.x;
        qsT[(c0 + 1) * QK_P + row] = a.y;
        qsT[(c0 + 2) * QK_P + row] = a.z;
        qsT[(c0 + 3) * QK_P + row] = a.w;
        ksT[(c0 + 0) * QK_P + row] = b.x;
        ksT[(c0 + 1) * QK_P + row] = b.y;
        ksT[(c0 + 2) * QK_P + row] = b.z;
        ksT[(c0 + 3) * QK_P + row] = b.w;
        *(float4*)&vs[row * DD + c0] = vv;
    }
    if (tid < 64) kdec[tid] = expf(slope * (float)(63 - tid));
    __syncthreads();

    const int tx = tid & 15, ty = tid >> 4;

    {
        float accA[4][4];
#pragma unroll
        for (int i = 0; i < 4; i++)
#pragma unroll
            for (int j = 0; j < 4; j++) accA[i][j] = 0.f;
#pragma unroll 4
        for (int d = 0; d < 128; d++) {
            float a[4], b[4];
            *(float4*)a = *(const float4*)&qsT[d * QK_P + 4 * ty];
            *(float4*)b = *(const float4*)&ksT[d * QK_P + 4 * tx];
#pragma unroll
            for (int i = 0; i < 4; i++)
#pragma unroll
                for (int j = 0; j < 4; j++) accA[i][j] += a[i] * b[j];
        }
#pragma unroll
        for (int i = 0; i < 4; i++)
#pragma unroll
            for (int j = 0; j < 4; j++) {
                int ri = 4 * ty + i, cj = 4 * tx + j;
                float m = (ri >= cj) ? expf(slope * (float)(ri - cj)) : 0.f;
                att[ri * 65 + cj] = accA[i][j] * m;
            }
    }
    __syncthreads();

    {
        float accI[4][8];
#pragma unroll
        for (int i = 0; i < 4; i++)
#pragma unroll
            for (int j = 0; j < 8; j++) accI[i][j] = 0.f;
#pragma unroll 2
        for (int j = 0; j < 64; j++) {
            float a[4];
#pragma unroll
            for (int r = 0; r < 4; r++) a[r] = att[(4 * ty + r) * 65 + j];
            float b[8];
            *(float4*)(b) = *(const float4*)&vs[j * DD + 8 * tx];
            *(float4*)(b + 4) = *(const float4*)&vs[j * DD + 8 * tx + 4];
#pragma unroll
            for (int r = 0; r < 4; r++)
#pragma unroll
                for (int e = 0; e < 8; e++) accI[r][e] += a[r] * b[e];
        }
#pragma unroll
        for (int r = 0; r < 4; r++) {
            float* dst = g_o + tbase + (size_t)(4 * ty + r) * DD + 8 * tx;
            *(float4*)(dst) = make_float4(accI[r][0], accI[r][1], accI[r][2], accI[r][3]);
            *(float4*)(dst + 4) = make_float4(accI[r][4], accI[r][5], accI[r][6], accI[r][7]);
        }
    }

    {
        float accU[8][8];
#pragma unroll
        for (int i = 0; i < 8; i++)
#pragma unroll
            for (int j = 0; j < 8; j++) accU[i][j] = 0.f;
#pragma unroll 2
        for (int i = 0; i < 64; i++) {
            float kd = kdec[i];
            float a[8];
#pragma unroll
            for (int r = 0; r < 8; r++) a[r] = ksT[(8 * ty + r) * QK_P + i];
            float b[8];
            *(float4*)(b) = *(const float4*)&vs[i * DD + 8 * tx];
            *(float4*)(b + 4) = *(const float4*)&vs[i * DD + 8 * tx + 4];
#pragma unroll
            for (int e = 0; e < 8; e++) b[e] *= kd;
#pragma unroll
            for (int r = 0; r < 8; r++)
#pragma unroll
                for (int e = 0; e < 8; e++) accU[r][e] += a[r] * b[e];
        }
        size_t ub = ((size_t)bh * NCH + c) * (DD * DD);
#pragma unroll
        for (int r = 0; r < 8; r++) {
            float* dst = g_U + ub + (size_t)(8 * ty + r) * DD + 8 * tx;
            *(float4*)(dst) = make_float4(accU[r][0], accU[r][1], accU[r][2], accU[r][3]);
            *(float4*)(dst + 4) = make_float4(accU[r][4], accU[r][5], accU[r][6], accU[r][7]);
        }
    }
}

// ---------------- pass B: decayed prefix scan of U over chunks -> S_c ---------
__global__ void __launch_bounds__(256) k_scan() {
    int g = blockIdx.x * 256 + threadIdx.x;
    int bh = g >> 12;
    int de4 = g & 4095;
    float chdec = expf(head_slope(bh & (HH - 1)) * 64.f);
    size_t base = (size_t)bh * NCH * (DD * DD) + (size_t)de4 * 4;
    float4 s = make_float4(0.f, 0.f, 0.f, 0.f);
    for (int c = 0; c < NCH; c++) {
        size_t idx = base + (size_t)c * (DD * DD);
        *(float4*)(g_S + idx) = s;
        float4 u = *(const float4*)(g_U + idx);
        s.x = s.x * chdec + u.x;
        s.y = s.y * chdec + u.y;
        s.z = s.z * chdec + u.z;
        s.w = s.w * chdec + u.w;
    }
}

// ---------------- pass C: inter = (q * qdec) @ S_c, accumulate into g_o -------
__global__ void __launch_bounds__(256, 1) k_inter() {
    extern __shared__ __align__(16) float sm2[];
    float* qs = sm2;
    float* Ss = qs + 64 * 132;
    const int tid = threadIdx.x;
    const int c = blockIdx.x & (NCH - 1);
    const int bh = blockIdx.x >> 6;
    const float slope = head_slope(bh & (HH - 1));
    const size_t tbase = ((size_t)bh * TT + c * CH) * DD;
    const size_t sbase = ((size_t)bh * NCH + c) * (DD * DD);

#pragma unroll
    for (int l = 0; l < 8; l++) {
        int idx = tid + l * 256;
        int row = idx >> 5;
        int c0 = (idx & 31) << 2;
        *(float4*)&qs[row * 132 + c0] = *(const float4*)(g_q + tbase + row * DD + c0);
    }
#pragma unroll
    for (int l = 0; l < 16; l++) {
        int idx = tid + l * 256;
        *(float4*)&Ss[idx * 4] = *(const float4*)(g_S + sbase + (size_t)idx * 4);
    }
    __syncthreads();

    const int tx = tid & 15, ty = tid >> 4;
    float acc[4][8];
#pragma unroll
    for (int i = 0; i < 4; i++)
#pragma unroll
        for (int j = 0; j < 8; j++) acc[i][j] = 0.f;
#pragma unroll 2
    for (int d = 0; d < 128; d++) {
        float a[4];
#pragma unroll
        for (int r = 0; r < 4; r++) a[r] = qs[(4 * ty + r) * 132 + d];
        float b[8];
        *(float4*)(b) = *(const float4*)&Ss[d * DD + 8 * tx];
        *(float4*)(b + 4) = *(const float4*)&Ss[d * DD + 8 * tx + 4];
#pragma unroll
        for (int r = 0; r < 4; r++)
#pragma unroll
            for (int e = 0; e < 8; e++) acc[r][e] += a[r] * b[e];
    }
#pragma unroll
    for (int r = 0; r < 4; r++) {
        int i = 4 * ty + r;
        float qd = expf(slope * (float)(i + 1));
        float* dst = g_o + tbase + (size_t)i * DD + 8 * tx;
        float4 c0 = *(float4*)(dst);
        float4 c1 = *(float4*)(dst + 4);
        c0.x += acc[r][0] * qd; c0.y += acc[r][1] * qd;
        c0.z += acc[r][2] * qd; c0.w += acc[r][3] * qd;
        c1.x += acc[r][4] * qd; c1.y += acc[r][5] * qd;
        c1.z += acc[r][6] * qd; c1.w += acc[r][7] * qd;
        *(float4*)(dst) = c0;
        *(float4*)(dst + 4) = c1;
    }
}

// ---------------- group rmsnorm * g_norm_w * gate -> fp16 hi/lo ---------------
__global__ void __launch_bounds__(128) k_gnorm_gate(const float* __restrict__ gnw) {
    int warp = blockIdx.x * 4 + (threadIdx.x >> 5);
    int lane = threadIdx.x & 31;
    int h = warp & (HH - 1);
    int bt = warp >> 4;
    int b = bt >> 12, t = bt & (TT - 1);
    size_t ob = ((size_t)(b * HH + h) * TT + t) * DD + lane * 4;
    float4 x4 = *(const float4*)(g_o + ob);
    float x[4] = {x4.x, x4.y, x4.z, x4.w};
    float ss = x[0] * x[0] + x[1] * x[1] + x[2] * x[2] + x[3] * x[3];
#pragma unroll
    for (int off = 16; off > 0; off >>= 1) ss += __shfl_xor_sync(0xffffffffu, ss, off);
    float r = rsqrtf(ss * (1.f / DD) + 1e-6f);
    float4 w = *(const float4*)(gnw + h * DD + lane * 4);
    size_t gb = (size_t)bt * HDIM + h * DD + lane * 4;
    float4 g = *(const float4*)(g_gate + gb);
    float y[4] = {x[0] * r * w.x * g.x, x[1] * r * w.y * g.y,
                  x[2] * r * w.z * g.z, x[3] * r * w.w * g.w};
    __half hb[4], lb[4];
#pragma unroll
    for (int j = 0; j < 4; j++) {
        hb[j] = __float2half(y[j]);
        lb[j] = __float2half(y[j] - __half2float(hb[j]));
    }
    *(uint2*)(g_onh + gb) = *(uint2*)hb;
    *(uint2*)(g_onl + gb) = *(uint2*)lb;
}

// -----------------------------------------------------------------------------
extern "C" void kernel_launch(void* const* d_in, const int* in_sizes, int n_in,
                              void* d_out, int out_size) {
    const float* hidden = (const float*)d_in[0];
    const float* w_qkv = (const float*)d_in[1];
    const float* q_ln_w = (const float*)d_in[2];
    const float* k_ln_w = (const float*)d_in[3];
    const float* g_norm_w = (const float*)d_in[4];
    const float* w_g_proj = (const float*)d_in[5];
    const float* w_dense = (const float*)d_in[6];
    const int* pos = (const int*)d_in[7];
    float* out = (float*)d_out;

    void *p_qkv, *p_gate;
    void *p_hh, *p_hl, *p_wqh, *p_wgh, *p_wdh, *p_onh, *p_onl;
    cudaGetSymbolAddress(&p_qkv, g_qkv);
    cudaGetSymbolAddress(&p_gate, g_gate);
    cudaGetSymbolAddress(&p_hh, g_hh);
    cudaGetSymbolAddress(&p_hl, g_hl);
    cudaGetSymbolAddress(&p_wqh, g_wqh);
    cudaGetSymbolAddress(&p_wgh, g_wgh);
    cudaGetSymbolAddress(&p_wdh, g_wdh);
    cudaGetSymbolAddress(&p_onh, g_onh);
    cudaGetSymbolAddress(&p_onl, g_onl);

    const int smem3 = (128 * QK_P * 2 + 64 * 128 + 64 * 65 + 64) * 4;  // 119296
    const int smem5 = (64 * 132 + 128 * 128) * 4;                      // 99328
    const int smemG = GNSTG * GSTG;                                    // 221184
    cudaFuncSetAttribute(k_chunk_local, cudaFuncAttributeMaxDynamicSharedMemorySize, smem3);
    cudaFuncSetAttribute(k_inter, cudaFuncAttributeMaxDynamicSharedMemorySize, smem5);
    cudaFuncSetAttribute(gemm_f16split, cudaFuncAttributeMaxDynamicSharedMemorySize, smemG);

    // 0. conversions
    {
        int n4;
        n4 = BB * TT * HDIM / 4;
        k_cvt_hilo<<<(n4 + 255) / 256, 256>>>(hidden, (__half*)p_hh, (__half*)p_hl, n4);
        n4 = O3 * HDIM / 4;
        k_cvt_f16<<<(n4 + 255) / 256, 256>>>(w_qkv, (__half*)p_wqh, n4);
        n4 = HDIM * HDIM / 4;
        k_cvt_f16<<<(n4 + 255) / 256, 256>>>(w_g_proj, (__half*)p_wgh, n4);
        k_cvt_f16<<<(n4 + 255) / 256, 256>>>(w_dense, (__half*)p_wdh, n4);
    }

    // 1. qkv = hidden @ w_qkv^T
    gemm_f16split<<<dim3(O3 / 128, (BB * TT) / 256), 256, smemG>>>(
        (const __half*)p_hh, (const __half*)p_hl, (const __half*)p_wqh,
        (float*)p_qkv, O3, 0);
    // 2. split + rmsnorm + rope
    k_norm_rope<<<(BB * TT * HH) / 4, 128>>>(q_ln_w, k_ln_w, pos);
    // 3. per-chunk local
    k_chunk_local<<<BB * HH * NCH, 256, smem3>>>();
    // 4. decayed prefix scan (float4)
    k_scan<<<(BB * HH * DD * DD / 4) / 256, 256>>>();
    // 5. inter-chunk
    k_inter<<<BB * HH * NCH, 256, smem5>>>();
    // 6. gate = sigmoid(hidden @ w_g_proj^T)
    gemm_f16split<<<dim3(HDIM / 128, (BB * TT) / 256), 256, smemG>>>(
        (const __half*)p_hh, (const __half*)p_hl, (const __half*)p_wgh,
        (float*)p_gate, HDIM, 1);
    // 7. group rmsnorm * weight * gate -> fp16 hi/lo
    k_gnorm_gate<<<(BB * TT * HH) / 4, 128>>>(g_norm_w);
    // 8. out = on @ w_dense^T
    gemm_f16split<<<dim3(HDIM / 128, (BB * TT) / 256), 256, smemG>>>(
        (const __half*)p_onh, (const __half*)p_onl, (const __half*)p_wdh,
        out, HDIM, 0);
}

// round 7
// speedup vs baseline: 2.8740x; 1.0195x over previous
#include <cuda_runtime.h>
#include <cuda_fp16.h>
#include <cstdint>

#define BB 2
#define TT 4096
#define HH 16
#define DD 128
#define HDIM 2048
#define O3 6144
#define NCH 64
#define CH 64

// ---------------- scratch (static device globals; no runtime allocation) ----
static __device__ float g_qkv[(size_t)BB * TT * O3];          // (bt, o)
static __device__ float g_q[(size_t)BB * HH * TT * DD];       // (b,h,t,d)
static __device__ float g_k[(size_t)BB * HH * TT * DD];
static __device__ float g_v[(size_t)BB * HH * TT * DD];
static __device__ float g_o[(size_t)BB * HH * TT * DD];
static __device__ float g_gate[(size_t)BB * TT * HDIM];       // (bt, hd) sigmoid'ed
static __device__ float g_U[(size_t)BB * HH * NCH * DD * DD]; // per-chunk KV outer
static __device__ float g_S[(size_t)BB * HH * NCH * DD * DD]; // scanned state

// fp16 operands (single precision level; f32 accum in MMA)
static __device__ __half g_hh[(size_t)BB * TT * HDIM];   // hidden
static __device__ __half g_wqh[(size_t)O3 * HDIM];
static __device__ __half g_wgh[(size_t)HDIM * HDIM];
static __device__ __half g_wdh[(size_t)HDIM * HDIM];
static __device__ __half g_onh[(size_t)BB * TT * HDIM];  // gated/normed o

__device__ __forceinline__ float head_slope(int h) {
    float a = (float)exp2(-0.5 * (double)(h + 1));
    return (float)(-(double)a * (1.0 - 11.0 / 31.0 + 1e-5));
}

__device__ __forceinline__ uint32_t s2u(const void* p) {
    uint32_t a;
    asm("{ .reg .u64 t; cvta.to.shared.u64 t, %1; cvt.u32.u64 %0, t; }" : "=r"(a) : "l"(p));
    return a;
}

__device__ __forceinline__ void cp16(uint32_t dst, const void* src) {
    asm volatile("cp.async.cg.shared.global [%0], [%1], 16;" :: "r"(dst), "l"(src));
}

__device__ __forceinline__ void ldsm4(uint32_t& r0, uint32_t& r1, uint32_t& r2, uint32_t& r3,
                                      uint32_t addr) {
    asm volatile("ldmatrix.sync.aligned.m8n8.x4.shared.b16 {%0,%1,%2,%3}, [%4];"
                 : "=r"(r0), "=r"(r1), "=r"(r2), "=r"(r3) : "r"(addr));
}

__device__ __forceinline__ void mma16816(float* c, const uint32_t* a, const uint32_t* b) {
    asm volatile(
        "mma.sync.aligned.m16n8k16.row.col.f32.f16.f16.f32 "
        "{%0,%1,%2,%3}, {%4,%5,%6,%7}, {%8,%9}, {%0,%1,%2,%3};"
        : "+f"(c[0]), "+f"(c[1]), "+f"(c[2]), "+f"(c[3])
        : "r"(a[0]), "r"(a[1]), "r"(a[2]), "r"(a[3]), "r"(b[0]), "r"(b[1]));
}

// ======================= fp16 mma.sync GEMM ==================================
// C[M, Ntot] = A[M,2048] * B[Ntot,2048]^T   (both fp16, f32 accum)
// tile 256x128, BK=64 -> 32 chunks
#define GPITCH 144                    // bytes per smem row (64 fp16 data + pad)
#define GA_BYTES (256 * GPITCH)       // 36864
#define GB_BYTES (128 * GPITCH)       // 18432
#define GSTG (GA_BYTES + GB_BYTES)    // 55296 per stage
#define GNSTG 4
#define GCHUNKS 32

__global__ void __launch_bounds__(256, 1) gemm_f16(
    const __half* __restrict__ Am, const __half* __restrict__ Bm,
    float* __restrict__ C, int Ntot, int act) {
    extern __shared__ __align__(128) char smem[];
    const uint32_t sbase = s2u(smem);
    const int tid = threadIdx.x;
    const int lane = tid & 31;
    const int warp = tid >> 5;
    const int wy = warp & 3;    // M: 4 x 64
    const int wx = warp >> 2;   // N: 2 x 64
    const int m0 = blockIdx.y * 256;
    const int n0 = blockIdx.x * 128;

    float acc[4][8][4];
#pragma unroll
    for (int i = 0; i < 4; i++)
#pragma unroll
        for (int j = 0; j < 8; j++)
#pragma unroll
            for (int q = 0; q < 4; q++) acc[i][j][q] = 0.f;

#define LOAD_CHUNK(c, s)                                                                \
    do {                                                                                \
        int _kk = (c) << 6;                                                             \
        const __half* _Ab = Am + (size_t)m0 * 2048 + _kk;                               \
        const __half* _Bb = Bm + (size_t)n0 * 2048 + _kk;                               \
        uint32_t _sa = sbase + (s) * GSTG;                                              \
        uint32_t _sb = _sa + GA_BYTES;                                                  \
        _Pragma("unroll") for (int t = 0; t < 8; t++) {                                 \
            int idx = tid + t * 256;                                                    \
            int row = idx >> 3, ch = idx & 7;                                           \
            cp16(_sa + row * GPITCH + ch * 16, _Ab + (size_t)row * 2048 + ch * 8);      \
        }                                                                               \
        _Pragma("unroll") for (int t = 0; t < 4; t++) {                                 \
            int idx = tid + t * 256;                                                    \
            int row = idx >> 3, ch = idx & 7;                                           \
            cp16(_sb + row * GPITCH + ch * 16, _Bb + (size_t)row * 2048 + ch * 8);      \
        }                                                                               \
    } while (0)

    // prologue: chunks 0..2 into stages 0..2
    for (int c = 0; c < 3; c++) {
        LOAD_CHUNK(c, c);
        asm volatile("cp.async.commit_group;" ::: "memory");
    }

    // per-thread ldmatrix base offsets
    const uint32_t aoff = (uint32_t)(wy * 64 + (lane & 15)) * GPITCH + (lane >> 4) * 16;
    const int brow = (lane & 7) + ((lane >> 4) << 3);
    const uint32_t boff0 = GA_BYTES + (uint32_t)(wx * 64 + brow) * GPITCH + ((lane >> 3) & 1) * 16;

    for (int i = 0; i < GCHUNKS; i++) {
        const int s = i & 3;
        asm volatile("cp.async.wait_group 2;" ::: "memory");
        __syncthreads();
        {
            const int j = i + 3;
            if (j < GCHUNKS) LOAD_CHUNK(j, j & 3);
        }
        asm volatile("cp.async.commit_group;" ::: "memory");
        const uint32_t sa = sbase + s * GSTG;

#pragma unroll
        for (int ks = 0; ks < 4; ks++) {
            uint32_t a[4][4], b[4][2];
#pragma unroll
            for (int mt = 0; mt < 4; mt++)
                ldsm4(a[mt][0], a[mt][1], a[mt][2], a[mt][3],
                      sa + aoff + mt * 16 * GPITCH + ks * 32);
            ldsm4(b[0][0], b[0][1], b[1][0], b[1][1], sa + boff0 + ks * 32);
            ldsm4(b[2][0], b[2][1], b[3][0], b[3][1], sa + boff0 + 16 * GPITCH + ks * 32);
#pragma unroll
            for (int mt = 0; mt < 4; mt++)
#pragma unroll
                for (int nt = 0; nt < 4; nt++)
                    mma16816(acc[mt][nt * 2 + 0], a[mt], b[nt]);
            ldsm4(b[0][0], b[0][1], b[1][0], b[1][1], sa + boff0 + 32 * GPITCH + ks * 32);
            ldsm4(b[2][0], b[2][1], b[3][0], b[3][1], sa + boff0 + 48 * GPITCH + ks * 32);
#pragma unroll
            for (int mt = 0; mt < 4; mt++)
#pragma unroll
                for (int nt = 0; nt < 4; nt++)
                    mma16816(acc[mt][nt * 2 + 1], a[mt], b[nt]);
        }
    }

    const int rbase = m0 + wy * 64 + (lane >> 2);
    const int cbase = n0 + wx * 64 + (lane & 3) * 2;
#pragma unroll
    for (int mt = 0; mt < 4; mt++) {
#pragma unroll
        for (int j = 0; j < 8; j++) {
            int nt = j >> 1, half = j & 1;
            int col = cbase + half * 32 + nt * 8;
            float v[4];
#pragma unroll
            for (int q = 0; q < 4; q++) {
                float x = acc[mt][j][q];
                v[q] = act ? (1.f / (1.f + expf(-x))) : x;
            }
            float* d0 = C + (size_t)(rbase + mt * 16) * Ntot + col;
            float* d1 = C + (size_t)(rbase + mt * 16 + 8) * Ntot + col;
            *(float2*)d0 = make_float2(v[0], v[1]);
            *(float2*)d1 = make_float2(v[2], v[3]);
        }
    }
}

// ---------------- fp32 -> fp16 single ----------------------------------------
__global__ void __launch_bounds__(256) k_cvt_f16(const float* __restrict__ src,
                                                 __half* __restrict__ dst, int n4) {
    int i = blockIdx.x * 256 + threadIdx.x;
    if (i >= n4) return;
    float4 x = ((const float4*)src)[i];
    __half h[4] = {__float2half(x.x), __float2half(x.y), __float2half(x.z), __float2half(x.w)};
    ((uint2*)dst)[i] = *(uint2*)h;
}

// ---------------- split qkv + per-head rmsnorm + rope; one warp per (b,t,h) --
__global__ void __launch_bounds__(128) k_norm_rope(const float* __restrict__ qw,
                                                   const float* __restrict__ kw,
                                                   const int* __restrict__ pos) {
    int warp = blockIdx.x * 4 + (threadIdx.x >> 5);
    int lane = threadIdx.x & 31;
    int h = warp & (HH - 1);
    int bt = warp >> 4;
    size_t base = (size_t)bt * O3 + h * DD + lane * 4;

    float4 q4 = *(const float4*)(g_qkv + base);
    float4 k4 = *(const float4*)(g_qkv + base + HDIM);
    float4 v4 = *(const float4*)(g_qkv + base + 2 * HDIM);
    float qv[4] = {q4.x, q4.y, q4.z, q4.w};
    float kv[4] = {k4.x, k4.y, k4.z, k4.w};

    float sq = qv[0] * qv[0] + qv[1] * qv[1] + qv[2] * qv[2] + qv[3] * qv[3];
    float sk = kv[0] * kv[0] + kv[1] * kv[1] + kv[2] * kv[2] + kv[3] * kv[3];
#pragma unroll
    for (int off = 16; off > 0; off >>= 1) {
        sq += __shfl_xor_sync(0xffffffffu, sq, off);
        sk += __shfl_xor_sync(0xffffffffu, sk, off);
    }
    float rq = rsqrtf(sq * (1.f / DD) + 1e-6f);
    float rk = rsqrtf(sk * (1.f / DD) + 1e-6f);
    float4 wq = *(const float4*)(qw + lane * 4);
    float4 wk = *(const float4*)(kw + lane * 4);
    float wqa[4] = {wq.x, wq.y, wq.z, wq.w};
    float wka[4] = {wk.x, wk.y, wk.z, wk.w};
#pragma unroll
    for (int j = 0; j < 4; j++) {
        qv[j] = qv[j] * rq * wqa[j];
        kv[j] = kv[j] * rk * wka[j];
    }

    float p = (float)pos[bt];
    float qp[4], kp[4];
#pragma unroll
    for (int j = 0; j < 4; j++) {
        qp[j] = __shfl_xor_sync(0xffffffffu, qv[j], 8);
        kp[j] = __shfl_xor_sync(0xffffffffu, kv[j], 8);
    }
    if (lane < 16) {
        float sgn = (lane < 8) ? -1.f : 1.f;
        int jb = (lane & 7) * 4;
#pragma unroll
        for (int j = 0; j < 4; j++) {
            float inv = exp2f(-(float)(jb + j) * 0.4152410118609203f);
            float ang = p * inv;
            float sn, cs;
            sincosf(ang, &sn, &cs);
            qv[j] = qv[j] * cs + sgn * qp[j] * sn;
            kv[j] = kv[j] * cs + sgn * kp[j] * sn;
        }
    }

    int b = bt >> 12, t = bt & (TT - 1);
    size_t ob = ((size_t)(b * HH + h) * TT + t) * DD + lane * 4;
    const float qscale = 0.08838834764831845f;
    *(float4*)(g_q + ob) = make_float4(qv[0] * qscale, qv[1] * qscale, qv[2] * qscale, qv[3] * qscale);
    *(float4*)(g_k + ob) = make_float4(kv[0], kv[1], kv[2], kv[3]);
    *(float4*)(g_v + ob) = v4;
}

// ---------------- pass A: per (b,h,c): att(masked), intra = att@v, U ---------
#define QK_P 68
__global__ void __launch_bounds__(256, 1) k_chunk_local() {
    extern __shared__ __align__(16) float sm[];
    float* qsT = sm;
    float* ksT = qsT + 128 * QK_P;
    float* vs = ksT + 128 * QK_P;
    float* att = vs + 64 * 128;
    float* kdec = att + 64 * 65;

    const int tid = threadIdx.x;
    const int c = blockIdx.x & (NCH - 1);
    const int bh = blockIdx.x >> 6;
    const int h = bh & (HH - 1);
    const float slope = head_slope(h);
    const size_t tbase = ((size_t)bh * TT + c * CH) * DD;

#pragma unroll
    for (int l = 0; l < 8; l++) {
        int idx = tid + l * 256;
        int row = idx >> 5;
        int c0 = (idx & 31) << 2;
        float4 a = *(const float4*)(g_q + tbase + row * DD + c0);
        float4 b = *(const float4*)(g_k + tbase + row * DD + c0);
        float4 vv = *(const float4*)(g_v + tbase + row * DD + c0);
        qsT[(c0 + 0) * QK_P + row] = a.x;
        qsT[(c0 + 1) * QK_P + row] = a.y;
        qsT[(c0 + 2) * QK_P + row] = a.z;
        qsT[(c0 + 3) * QK_P + row] = a.w;
        ksT[(c0 + 0) * QK_P + row] = b.x;
        ksT[(c0 + 1) * QK_P + row] = b.y;
        ksT[(c0 + 2) * QK_P + row] = b.z;
        ksT[(c0 + 3) * QK_P + row] = b.w;
        *(float4*)&vs[row * DD + c0] = vv;
    }
    if (tid < 64) kdec[tid] = expf(slope * (float)(63 - tid));
    __syncthreads();

    const int tx = tid & 15, ty = tid >> 4;

    {
        float accA[4][4];
#pragma unroll
        for (int i = 0; i < 4; i++)
#pragma unroll
            for (int j = 0; j < 4; j++) accA[i][j] = 0.f;
#pragma unroll 4
        for (int d = 0; d < 128; d++) {
            float a[4], b[4];
            *(float4*)a = *(const float4*)&qsT[d * QK_P + 4 * ty];
            *(float4*)b = *(const float4*)&ksT[d * QK_P + 4 * tx];
#pragma unroll
            for (int i = 0; i < 4; i++)
#pragma unroll
                for (int j = 0; j < 4; j++) accA[i][j] += a[i] * b[j];
        }
#pragma unroll
        for (int i = 0; i < 4; i++)
#pragma unroll
            for (int j = 0; j < 4; j++) {
                int ri = 4 * ty + i, cj = 4 * tx + j;
                float m = (ri >= cj) ? expf(slope * (float)(ri - cj)) : 0.f;
                att[ri * 65 + cj] = accA[i][j] * m;
            }
    }
    __syncthreads();

    {
        float accI[4][8];
#pragma unroll
        for (int i = 0; i < 4; i++)
#pragma unroll
            for (int j = 0; j < 8; j++) accI[i][j] = 0.f;
#pragma unroll 2
        for (int j = 0; j < 64; j++) {
            float a[4];
#pragma unroll
            for (int r = 0; r < 4; r++) a[r] = att[(4 * ty + r) * 65 + j];
            float b[8];
            *(float4*)(b) = *(const float4*)&vs[j * DD + 8 * tx];
            *(float4*)(b + 4) = *(const float4*)&vs[j * DD + 8 * tx + 4];
#pragma unroll
            for (int r = 0; r < 4; r++)
#pragma unroll
                for (int e = 0; e < 8; e++) accI[r][e] += a[r] * b[e];
        }
#pragma unroll
        for (int r = 0; r < 4; r++) {
            float* dst = g_o + tbase + (size_t)(4 * ty + r) * DD + 8 * tx;
            *(float4*)(dst) = make_float4(accI[r][0], accI[r][1], accI[r][2], accI[r][3]);
            *(float4*)(dst + 4) = make_float4(accI[r][4], accI[r][5], accI[r][6], accI[r][7]);
        }
    }

    {
        float accU[8][8];
#pragma unroll
        for (int i = 0; i < 8; i++)
#pragma unroll
            for (int j = 0; j < 8; j++) accU[i][j] = 0.f;
#pragma unroll 2
        for (int i = 0; i < 64; i++) {
            float kd = kdec[i];
            float a[8];
#pragma unroll
            for (int r = 0; r < 8; r++) a[r] = ksT[(8 * ty + r) * QK_P + i];
            float b[8];
            *(float4*)(b) = *(const float4*)&vs[i * DD + 8 * tx];
            *(float4*)(b + 4) = *(const float4*)&vs[i * DD + 8 * tx + 4];
#pragma unroll
            for (int e = 0; e < 8; e++) b[e] *= kd;
#pragma unroll
            for (int r = 0; r < 8; r++)
#pragma unroll
                for (int e = 0; e < 8; e++) accU[r][e] += a[r] * b[e];
        }
        size_t ub = ((size_t)bh * NCH + c) * (DD * DD);
#pragma unroll
        for (int r = 0; r < 8; r++) {
            float* dst = g_U + ub + (size_t)(8 * ty + r) * DD + 8 * tx;
            *(float4*)(dst) = make_float4(accU[r][0], accU[r][1], accU[r][2], accU[r][3]);
            *(float4*)(dst + 4) = make_float4(accU[r][4], accU[r][5], accU[r][6], accU[r][7]);
        }
    }
}

// ---------------- pass B: decayed prefix scan of U over chunks -> S_c ---------
__global__ void __launch_bounds__(256) k_scan() {
    int g = blockIdx.x * 256 + threadIdx.x;
    int bh = g >> 12;
    int de4 = g & 4095;
    float chdec = expf(head_slope(bh & (HH - 1)) * 64.f);
    size_t base = (size_t)bh * NCH * (DD * DD) + (size_t)de4 * 4;
    float4 s = make_float4(0.f, 0.f, 0.f, 0.f);
    for (int c = 0; c < NCH; c++) {
        size_t idx = base + (size_t)c * (DD * DD);
        *(float4*)(g_S + idx) = s;
        float4 u = *(const float4*)(g_U + idx);
        s.x = s.x * chdec + u.x;
        s.y = s.y * chdec + u.y;
        s.z = s.z * chdec + u.z;
        s.w = s.w * chdec + u.w;
    }
}

// ---------------- pass C: inter = (q * qdec) @ S_c, accumulate into g_o -------
__global__ void __launch_bounds__(256, 1) k_inter() {
    extern __shared__ __align__(16) float sm2[];
    float* qs = sm2;
    float* Ss = qs + 64 * 132;
    const int tid = threadIdx.x;
    const int c = blockIdx.x & (NCH - 1);
    const int bh = blockIdx.x >> 6;
    const float slope = head_slope(bh & (HH - 1));
    const size_t tbase = ((size_t)bh * TT + c * CH) * DD;
    const size_t sbase = ((size_t)bh * NCH + c) * (DD * DD);

#pragma unroll
    for (int l = 0; l < 8; l++) {
        int idx = tid + l * 256;
        int row = idx >> 5;
        int c0 = (idx & 31) << 2;
        *(float4*)&qs[row * 132 + c0] = *(const float4*)(g_q + tbase + row * DD + c0);
    }
#pragma unroll
    for (int l = 0; l < 16; l++) {
        int idx = tid + l * 256;
        *(float4*)&Ss[idx * 4] = *(const float4*)(g_S + sbase + (size_t)idx * 4);
    }
    __syncthreads();

    const int tx = tid & 15, ty = tid >> 4;
    float acc[4][8];
#pragma unroll
    for (int i = 0; i < 4; i++)
#pragma unroll
        for (int j = 0; j < 8; j++) acc[i][j] = 0.f;
#pragma unroll 2
    for (int d = 0; d < 128; d++) {
        float a[4];
#pragma unroll
        for (int r = 0; r < 4; r++) a[r] = qs[(4 * ty + r) * 132 + d];
        float b[8];
        *(float4*)(b) = *(const float4*)&Ss[d * DD + 8 * tx];
        *(float4*)(b + 4) = *(const float4*)&Ss[d * DD + 8 * tx + 4];
#pragma unroll
        for (int r = 0; r < 4; r++)
#pragma unroll
            for (int e = 0; e < 8; e++) acc[r][e] += a[r] * b[e];
    }
#pragma unroll
    for (int r = 0; r < 4; r++) {
        int i = 4 * ty + r;
        float qd = expf(slope * (float)(i + 1));
        float* dst = g_o + tbase + (size_t)i * DD + 8 * tx;
        float4 c0 = *(float4*)(dst);
        float4 c1 = *(float4*)(dst + 4);
        c0.x += acc[r][0] * qd; c0.y += acc[r][1] * qd;
        c0.z += acc[r][2] * qd; c0.w += acc[r][3] * qd;
        c1.x += acc[r][4] * qd; c1.y += acc[r][5] * qd;
        c1.z += acc[r][6] * qd; c1.w += acc[r][7] * qd;
        *(float4*)(dst) = c0;
        *(float4*)(dst + 4) = c1;
    }
}

// ---------------- group rmsnorm * g_norm_w * gate -> fp16 ---------------------
__global__ void __launch_bounds__(128) k_gnorm_gate(const float* __restrict__ gnw) {
    int warp = blockIdx.x * 4 + (threadIdx.x >> 5);
    int lane = threadIdx.x & 31;
    int h = warp & (HH - 1);
    int bt = warp >> 4;
    int b = bt >> 12, t = bt & (TT - 1);
    size_t ob = ((size_t)(b * HH + h) * TT + t) * DD + lane * 4;
    float4 x4 = *(const float4*)(g_o + ob);
    float x[4] = {x4.x, x4.y, x4.z, x4.w};
    float ss = x[0] * x[0] + x[1] * x[1] + x[2] * x[2] + x[3] * x[3];
#pragma unroll
    for (int off = 16; off > 0; off >>= 1) ss += __shfl_xor_sync(0xffffffffu, ss, off);
    float r = rsqrtf(ss * (1.f / DD) + 1e-6f);
    float4 w = *(const float4*)(gnw + h * DD + lane * 4);
    size_t gb = (size_t)bt * HDIM + h * DD + lane * 4;
    float4 g = *(const float4*)(g_gate + gb);
    __half hb[4];
    hb[0] = __float2half(x[0] * r * w.x * g.x);
    hb[1] = __float2half(x[1] * r * w.y * g.y);
    hb[2] = __float2half(x[2] * r * w.z * g.z);
    hb[3] = __float2half(x[3] * r * w.w * g.w);
    *(uint2*)(g_onh + gb) = *(uint2*)hb;
}

// -----------------------------------------------------------------------------
extern "C" void kernel_launch(void* const* d_in, const int* in_sizes, int n_in,
                              void* d_out, int out_size) {
    const float* hidden = (const float*)d_in[0];
    const float* w_qkv = (const float*)d_in[1];
    const float* q_ln_w = (const float*)d_in[2];
    const float* k_ln_w = (const float*)d_in[3];
    const float* g_norm_w = (const float*)d_in[4];
    const float* w_g_proj = (const float*)d_in[5];
    const float* w_dense = (const float*)d_in[6];
    const int* pos = (const int*)d_in[7];
    float* out = (float*)d_out;

    void *p_qkv, *p_gate;
    void *p_hh, *p_wqh, *p_wgh, *p_wdh, *p_onh;
    cudaGetSymbolAddress(&p_qkv, g_qkv);
    cudaGetSymbolAddress(&p_gate, g_gate);
    cudaGetSymbolAddress(&p_hh, g_hh);
    cudaGetSymbolAddress(&p_wqh, g_wqh);
    cudaGetSymbolAddress(&p_wgh, g_wgh);
    cudaGetSymbolAddress(&p_wdh, g_wdh);
    cudaGetSymbolAddress(&p_onh, g_onh);

    const int smem3 = (128 * QK_P * 2 + 64 * 128 + 64 * 65 + 64) * 4;  // 119296
    const int smem5 = (64 * 132 + 128 * 128) * 4;                      // 99328
    const int smemG = GNSTG * GSTG;                                    // 221184
    cudaFuncSetAttribute(k_chunk_local, cudaFuncAttributeMaxDynamicSharedMemorySize, smem3);
    cudaFuncSetAttribute(k_inter, cudaFuncAttributeMaxDynamicSharedMemorySize, smem5);
    cudaFuncSetAttribute(gemm_f16, cudaFuncAttributeMaxDynamicSharedMemorySize, smemG);

    // 0. conversions
    {
        int n4;
        n4 = BB * TT * HDIM / 4;
        k_cvt_f16<<<(n4 + 255) / 256, 256>>>(hidden, (__half*)p_hh, n4);
        n4 = O3 * HDIM / 4;
        k_cvt_f16<<<(n4 + 255) / 256, 256>>>(w_qkv, (__half*)p_wqh, n4);
        n4 = HDIM * HDIM / 4;
        k_cvt_f16<<<(n4 + 255) / 256, 256>>>(w_g_proj, (__half*)p_wgh, n4);
        k_cvt_f16<<<(n4 + 255) / 256, 256>>>(w_dense, (__half*)p_wdh, n4);
    }

    // 1. qkv = hidden @ w_qkv^T
    gemm_f16<<<dim3(O3 / 128, (BB * TT) / 256), 256, smemG>>>(
        (const __half*)p_hh, (const __half*)p_wqh, (float*)p_qkv, O3, 0);
    // 2. split + rmsnorm + rope
    k_norm_rope<<<(BB * TT * HH) / 4, 128>>>(q_ln_w, k_ln_w, pos);
    // 3. per-chunk local
    k_chunk_local<<<BB * HH * NCH, 256, smem3>>>();
    // 4. decayed prefix scan (float4)
    k_scan<<<(BB * HH * DD * DD / 4) / 256, 256>>>();
    // 5. inter-chunk
    k_inter<<<BB * HH * NCH, 256, smem5>>>();
    // 6. gate = sigmoid(hidden @ w_g_proj^T)
    gemm_f16<<<dim3(HDIM / 128, (BB * TT) / 256), 256, smemG>>>(
        (const __half*)p_hh, (const __half*)p_wgh, (float*)p_gate, HDIM, 1);
    // 7. group rmsnorm * weight * gate -> fp16
    k_gnorm_gate<<<(BB * TT * HH) / 4, 128>>>(g_norm_w);
    // 8. out = on @ w_dense^T
    gemm_f16<<<dim3(HDIM / 128, (BB * TT) / 256), 256, smemG>>>(
        (const __half*)p_onh, (const __half*)p_wdh, out, HDIM, 0);
}

// round 8
// speedup vs baseline: 4.4592x; 1.5516x over previous
#include <cuda_runtime.h>
#include <cuda_fp16.h>
#include <cstdint>

#define BB 2
#define TT 4096
#define HH 16
#define DD 128
#define HDIM 2048
#define O3 6144
#define NCH 64
#define CH 64

// ---------------- scratch (static device globals; no runtime allocation) ----
static __device__ float g_q[(size_t)BB * HH * TT * DD];       // (b,h,t,d)
static __device__ float g_k[(size_t)BB * HH * TT * DD];
static __device__ float g_v[(size_t)BB * HH * TT * DD];
static __device__ float g_o[(size_t)BB * HH * TT * DD];       // intra term
static __device__ float g_gate[(size_t)BB * TT * HDIM];       // sigmoid'ed, fp32
static __device__ float g_U[(size_t)BB * HH * NCH * DD * DD];
static __device__ float g_S[(size_t)BB * HH * NCH * DD * DD];
static __device__ float g_ct[(size_t)BB * TT * 32];           // rope cos table
static __device__ float g_st[(size_t)BB * TT * 32];           // rope sin table

// fp16 operands
static __device__ __half g_hh[(size_t)BB * TT * HDIM];
static __device__ __half g_wqh[(size_t)O3 * HDIM];
static __device__ __half g_wgh[(size_t)HDIM * HDIM];
static __device__ __half g_wdh[(size_t)HDIM * HDIM];
static __device__ __half g_onh[(size_t)BB * TT * HDIM];

__device__ __forceinline__ float head_slope(int h) {
    float a = (float)exp2(-0.5 * (double)(h + 1));
    return (float)(-(double)a * (1.0 - 11.0 / 31.0 + 1e-5));
}

__device__ __forceinline__ uint32_t s2u(const void* p) {
    uint32_t a;
    asm("{ .reg .u64 t; cvta.to.shared.u64 t, %1; cvt.u32.u64 %0, t; }" : "=r"(a) : "l"(p));
    return a;
}

__device__ __forceinline__ void cp16(uint32_t dst, const void* src) {
    asm volatile("cp.async.cg.shared.global [%0], [%1], 16;" :: "r"(dst), "l"(src));
}

__device__ __forceinline__ void ldsm4(uint32_t& r0, uint32_t& r1, uint32_t& r2, uint32_t& r3,
                                      uint32_t addr) {
    asm volatile("ldmatrix.sync.aligned.m8n8.x4.shared.b16 {%0,%1,%2,%3}, [%4];"
                 : "=r"(r0), "=r"(r1), "=r"(r2), "=r"(r3) : "r"(addr));
}

__device__ __forceinline__ void mma16816(float* c, const uint32_t* a, const uint32_t* b) {
    asm volatile(
        "mma.sync.aligned.m16n8k16.row.col.f32.f16.f16.f32 "
        "{%0,%1,%2,%3}, {%4,%5,%6,%7}, {%8,%9}, {%0,%1,%2,%3};"
        : "+f"(c[0]), "+f"(c[1]), "+f"(c[2]), "+f"(c[3])
        : "r"(a[0]), "r"(a[1]), "r"(a[2]), "r"(a[3]), "r"(b[0]), "r"(b[1]));
}

// ======================= fp16 mma.sync GEMM ==================================
// C[M,Ntot] = A[M,2048] * B[Ntot,2048]^T, tile 256x128, BK=64 -> 32 chunks
// mode 0: plain fp32 out. mode 1: sigmoid fp32 out. mode 2: fused qkv epilogue
//         (rmsnorm + rope + qscale), writes fp32 q/k/v in (b,h,t,d).
#define GPITCH 144
#define GA_BYTES (256 * GPITCH)
#define GB_BYTES (128 * GPITCH)
#define GSTG (GA_BYTES + GB_BYTES)
#define GNSTG 4
#define GCHUNKS 32

__global__ void __launch_bounds__(256, 1) gemm_f16(
    const __half* __restrict__ Am, const __half* __restrict__ Bm,
    float* __restrict__ C, int Ntot, int mode,
    const float* __restrict__ qlnw, const float* __restrict__ klnw,
    float* __restrict__ outq, float* __restrict__ outk, float* __restrict__ outv) {
    extern __shared__ __align__(128) char smem[];
    const uint32_t sbase = s2u(smem);
    const int tid = threadIdx.x;
    const int lane = tid & 31;
    const int warp = tid >> 5;
    const int wy = warp & 3;
    const int wx = warp >> 2;
    const int m0 = blockIdx.y * 256;
    const int n0 = blockIdx.x * 128;

    float acc[4][8][4];
#pragma unroll
    for (int i = 0; i < 4; i++)
#pragma unroll
        for (int j = 0; j < 8; j++)
#pragma unroll
            for (int q = 0; q < 4; q++) acc[i][j][q] = 0.f;

#define LOAD_CHUNK(c, s)                                                                \
    do {                                                                                \
        int _kk = (c) << 6;                                                             \
        const __half* _Ab = Am + (size_t)m0 * 2048 + _kk;                               \
        const __half* _Bb = Bm + (size_t)n0 * 2048 + _kk;                               \
        uint32_t _sa = sbase + (s) * GSTG;                                              \
        uint32_t _sb = _sa + GA_BYTES;                                                  \
        _Pragma("unroll") for (int t = 0; t < 8; t++) {                                 \
            int idx = tid + t * 256;                                                    \
            int row = idx >> 3, ch = idx & 7;                                           \
            cp16(_sa + row * GPITCH + ch * 16, _Ab + (size_t)row * 2048 + ch * 8);      \
        }                                                                               \
        _Pragma("unroll") for (int t = 0; t < 4; t++) {                                 \
            int idx = tid + t * 256;                                                    \
            int row = idx >> 3, ch = idx & 7;                                           \
            cp16(_sb + row * GPITCH + ch * 16, _Bb + (size_t)row * 2048 + ch * 8);      \
        }                                                                               \
    } while (0)

    for (int c = 0; c < 3; c++) {
        LOAD_CHUNK(c, c);
        asm volatile("cp.async.commit_group;" ::: "memory");
    }

    const uint32_t aoff = (uint32_t)(wy * 64 + (lane & 15)) * GPITCH + (lane >> 4) * 16;
    const int brow = (lane & 7) + ((lane >> 4) << 3);
    const uint32_t boff0 = GA_BYTES + (uint32_t)(wx * 64 + brow) * GPITCH + ((lane >> 3) & 1) * 16;

    for (int i = 0; i < GCHUNKS; i++) {
        const int s = i & 3;
        asm volatile("cp.async.wait_group 2;" ::: "memory");
        __syncthreads();
        {
            const int j = i + 3;
            if (j < GCHUNKS) LOAD_CHUNK(j, j & 3);
        }
        asm volatile("cp.async.commit_group;" ::: "memory");
        const uint32_t sa = sbase + s * GSTG;

#pragma unroll
        for (int ks = 0; ks < 4; ks++) {
            uint32_t a[4][4], b[4][2];
#pragma unroll
            for (int mt = 0; mt < 4; mt++)
                ldsm4(a[mt][0], a[mt][1], a[mt][2], a[mt][3],
                      sa + aoff + mt * 16 * GPITCH + ks * 32);
            ldsm4(b[0][0], b[0][1], b[1][0], b[1][1], sa + boff0 + ks * 32);
            ldsm4(b[2][0], b[2][1], b[3][0], b[3][1], sa + boff0 + 16 * GPITCH + ks * 32);
#pragma unroll
            for (int mt = 0; mt < 4; mt++)
#pragma unroll
                for (int nt = 0; nt < 4; nt++)
                    mma16816(acc[mt][nt * 2 + 0], a[mt], b[nt]);
            ldsm4(b[0][0], b[0][1], b[1][0], b[1][1], sa + boff0 + 32 * GPITCH + ks * 32);
            ldsm4(b[2][0], b[2][1], b[3][0], b[3][1], sa + boff0 + 48 * GPITCH + ks * 32);
#pragma unroll
            for (int mt = 0; mt < 4; mt++)
#pragma unroll
                for (int nt = 0; nt < 4; nt++)
                    mma16816(acc[mt][nt * 2 + 1], a[mt], b[nt]);
        }
    }

    asm volatile("cp.async.wait_group 0;" ::: "memory");
    __syncthreads();

    if (mode == 2) {
        // ---- fused qkv epilogue: rmsnorm + rope + qscale, fp32 out ----
        const int seg = n0 >> 11;          // 0=q, 1=k, 2=v
        const int h = (n0 >> 7) & 15;
        float* rbuf = (float*)smem;        // 512 floats, pipeline smem is dead

        if (seg < 2) {
#pragma unroll
            for (int mt = 0; mt < 4; mt++)
#pragma unroll
                for (int rh = 0; rh < 2; rh++) {
                    float p = 0.f;
#pragma unroll
                    for (int j = 0; j < 8; j++) {
                        float a0 = acc[mt][j][rh * 2], a1 = acc[mt][j][rh * 2 + 1];
                        p += a0 * a0 + a1 * a1;
                    }
                    p += __shfl_xor_sync(0xffffffffu, p, 1);
                    p += __shfl_xor_sync(0xffffffffu, p, 2);
                    if ((lane & 3) == 0)
                        rbuf[wx * 256 + wy * 64 + (lane >> 2) + mt * 16 + rh * 8] = p;
                }
            __syncthreads();
        }

        const float* lnw = (seg == 0) ? qlnw : klnw;
        float* dstbase = (seg == 0) ? outq : ((seg == 1) ? outk : outv);
        const float segscale = (seg == 0) ? 0.08838834764831845f : 1.0f;

#pragma unroll
        for (int mt = 0; mt < 4; mt++) {
#pragma unroll
            for (int rh = 0; rh < 2; rh++) {
                const int rloc = wy * 64 + (lane >> 2) + mt * 16 + rh * 8;
                const int r = m0 + rloc;
                const int b = r >> 12, t = r & 4095;
                float rq = 1.f;
                if (seg < 2)
                    rq = rsqrtf((rbuf[rloc] + rbuf[256 + rloc]) * (1.f / 128.f) + 1e-6f);

                float vals[16];
#pragma unroll
                for (int j = 0; j < 8; j++) {
                    int ld = wx * 64 + (j & 1) * 32 + (j >> 1) * 8 + (lane & 3) * 2;
                    float v0 = acc[mt][j][rh * 2], v1 = acc[mt][j][rh * 2 + 1];
                    if (seg < 2) {
                        v0 *= rq * lnw[ld];
                        v1 *= rq * lnw[ld + 1];
                    }
                    vals[j * 2] = v0;
                    vals[j * 2 + 1] = v1;
                }
                if (seg < 2 && wx == 0) {
                    // rope: j=nt*2 (d<32) pairs with j=nt*2+1 (d+32)
#pragma unroll
                    for (int nt = 0; nt < 4; nt++) {
                        int d = nt * 8 + (lane & 3) * 2;
                        float2 c2 = *(const float2*)&g_ct[(size_t)r * 32 + d];
                        float2 s2 = *(const float2*)&g_st[(size_t)r * 32 + d];
                        float e0 = vals[nt * 4 + 0], e1 = vals[nt * 4 + 1];
                        float o0 = vals[nt * 4 + 2], o1 = vals[nt * 4 + 3];
                        vals[nt * 4 + 0] = e0 * c2.x - o0 * s2.x;
                        vals[nt * 4 + 1] = e1 * c2.y - o1 * s2.y;
                        vals[nt * 4 + 2] = o0 * c2.x + e0 * s2.x;
                        vals[nt * 4 + 3] = o1 * c2.y + e1 * s2.y;
                    }
                }
                size_t obase = ((size_t)(b * HH + h) * TT + t) * DD;
#pragma unroll
                for (int j = 0; j < 8; j++) {
                    int ld = wx * 64 + (j & 1) * 32 + (j >> 1) * 8 + (lane & 3) * 2;
                    *(float2*)(dstbase + obase + ld) =
                        make_float2(vals[j * 2] * segscale, vals[j * 2 + 1] * segscale);
                }
            }
        }
    } else {
        const int rbase = m0 + wy * 64 + (lane >> 2);
        const int cbase = n0 + wx * 64 + (lane & 3) * 2;
#pragma unroll
        for (int mt = 0; mt < 4; mt++) {
#pragma unroll
            for (int j = 0; j < 8; j++) {
                int nt = j >> 1, half = j & 1;
                int col = cbase + half * 32 + nt * 8;
                float v[4];
#pragma unroll
                for (int q = 0; q < 4; q++) {
                    float x = acc[mt][j][q];
                    v[q] = mode ? (1.f / (1.f + expf(-x))) : x;
                }
                float* d0 = C + (size_t)(rbase + mt * 16) * Ntot + col;
                float* d1 = C + (size_t)(rbase + mt * 16 + 8) * Ntot + col;
                *(float2*)d0 = make_float2(v[0], v[1]);
                *(float2*)d1 = make_float2(v[2], v[3]);
            }
        }
    }
}

// ---------------- fp32 -> fp16 --------------------------------------------
__global__ void __launch_bounds__(256) k_cvt_f16(const float* __restrict__ src,
                                                 __half* __restrict__ dst, int n4) {
    int i = blockIdx.x * 256 + threadIdx.x;
    if (i >= n4) return;
    float4 x = ((const float4*)src)[i];
    __half h[4] = {__float2half(x.x), __float2half(x.y), __float2half(x.z), __float2half(x.w)};
    ((uint2*)dst)[i] = *(uint2*)h;
}

// ---------------- rope cos/sin table ----------------------------------------
__global__ void __launch_bounds__(256) k_rope_table(const int* __restrict__ pos) {
    int idx = blockIdx.x * 256 + threadIdx.x;  // BB*TT*32 = 262144
    int bt = idx >> 5, d = idx & 31;
    float p = (float)pos[bt];
    float inv = exp2f(-(float)d * 0.4152410118609203f);
    float sn, cs;
    sincosf(p * inv, &sn, &cs);
    g_ct[idx] = cs;
    g_st[idx] = sn;
}

// ---------------- pass A: per (b,h,c): att(masked), intra = att@v, U ---------
#define QK_P 68
__global__ void __launch_bounds__(256, 1) k_chunk_local() {
    extern __shared__ __align__(16) float sm[];
    float* qsT = sm;
    float* ksT = qsT + 128 * QK_P;
    float* vs = ksT + 128 * QK_P;
    float* att = vs + 64 * 128;
    float* kdec = att + 64 * 65;

    const int tid = threadIdx.x;
    const int c = blockIdx.x & (NCH - 1);
    const int bh = blockIdx.x >> 6;
    const int h = bh & (HH - 1);
    const float slope = head_slope(h);
    const size_t tbase = ((size_t)bh * TT + c * CH) * DD;

#pragma unroll
    for (int l = 0; l < 8; l++) {
        int idx = tid + l * 256;
        int row = idx >> 5;
        int c0 = (idx & 31) << 2;
        float4 a = *(const float4*)(g_q + tbase + row * DD + c0);
        float4 b = *(const float4*)(g_k + tbase + row * DD + c0);
        float4 vv = *(const float4*)(g_v + tbase + row * DD + c0);
        qsT[(c0 + 0) * QK_P + row] = a.x;
        qsT[(c0 + 1) * QK_P + row] = a.y;
        qsT[(c0 + 2) * QK_P + row] = a.z;
        qsT[(c0 + 3) * QK_P + row] = a.w;
        ksT[(c0 + 0) * QK_P + row] = b.x;
        ksT[(c0 + 1) * QK_P + row] = b.y;
        ksT[(c0 + 2) * QK_P + row] = b.z;
        ksT[(c0 + 3) * QK_P + row] = b.w;
        *(float4*)&vs[row * DD + c0] = vv;
    }
    if (tid < 64) kdec[tid] = expf(slope * (float)(63 - tid));
    __syncthreads();

    const int tx = tid & 15, ty = tid >> 4;

    {
        float accA[4][4];
#pragma unroll
        for (int i = 0; i < 4; i++)
#pragma unroll
            for (int j = 0; j < 4; j++) accA[i][j] = 0.f;
#pragma unroll 4
        for (int d = 0; d < 128; d++) {
            float a[4], b[4];
            *(float4*)a = *(const float4*)&qsT[d * QK_P + 4 * ty];
            *(float4*)b = *(const float4*)&ksT[d * QK_P + 4 * tx];
#pragma unroll
            for (int i = 0; i < 4; i++)
#pragma unroll
                for (int j = 0; j < 4; j++) accA[i][j] += a[i] * b[j];
        }
#pragma unroll
        for (int i = 0; i < 4; i++)
#pragma unroll
            for (int j = 0; j < 4; j++) {
                int ri = 4 * ty + i, cj = 4 * tx + j;
                float m = (ri >= cj) ? expf(slope * (float)(ri - cj)) : 0.f;
                att[ri * 65 + cj] = accA[i][j] * m;
            }
    }
    __syncthreads();

    {
        float accI[4][8];
#pragma unroll
        for (int i = 0; i < 4; i++)
#pragma unroll
            for (int j = 0; j < 8; j++) accI[i][j] = 0.f;
#pragma unroll 2
        for (int j = 0; j < 64; j++) {
            float a[4];
#pragma unroll
            for (int r = 0; r < 4; r++) a[r] = att[(4 * ty + r) * 65 + j];
            float b[8];
            *(float4*)(b) = *(const float4*)&vs[j * DD + 8 * tx];
            *(float4*)(b + 4) = *(const float4*)&vs[j * DD + 8 * tx + 4];
#pragma unroll
            for (int r = 0; r < 4; r++)
#pragma unroll
                for (int e = 0; e < 8; e++) accI[r][e] += a[r] * b[e];
        }
#pragma unroll
        for (int r = 0; r < 4; r++) {
            float* dst = g_o + tbase + (size_t)(4 * ty + r) * DD + 8 * tx;
            *(float4*)(dst) = make_float4(accI[r][0], accI[r][1], accI[r][2], accI[r][3]);
            *(float4*)(dst + 4) = make_float4(accI[r][4], accI[r][5], accI[r][6], accI[r][7]);
        }
    }

    {
        float accU[8][8];
#pragma unroll
        for (int i = 0; i < 8; i++)
#pragma unroll
            for (int j = 0; j < 8; j++) accU[i][j] = 0.f;
#pragma unroll 2
        for (int i = 0; i < 64; i++) {
            float kd = kdec[i];
            float a[8];
#pragma unroll
            for (int r = 0; r < 8; r++) a[r] = ksT[(8 * ty + r) * QK_P + i];
            float b[8];
            *(float4*)(b) = *(const float4*)&vs[i * DD + 8 * tx];
            *(float4*)(b + 4) = *(const float4*)&vs[i * DD + 8 * tx + 4];
#pragma unroll
            for (int e = 0; e < 8; e++) b[e] *= kd;
#pragma unroll
            for (int r = 0; r < 8; r++)
#pragma unroll
                for (int e = 0; e < 8; e++) accU[r][e] += a[r] * b[e];
        }
        size_t ub = ((size_t)bh * NCH + c) * (DD * DD);
#pragma unroll
        for (int r = 0; r < 8; r++) {
            float* dst = g_U + ub + (size_t)(8 * ty + r) * DD + 8 * tx;
            *(float4*)(dst) = make_float4(accU[r][0], accU[r][1], accU[r][2], accU[r][3]);
            *(float4*)(dst + 4) = make_float4(accU[r][4], accU[r][5], accU[r][6], accU[r][7]);
        }
    }
}

// ---------------- pass B: decayed prefix scan (float4) -----------------------
__global__ void __launch_bounds__(256) k_scan() {
    int g = blockIdx.x * 256 + threadIdx.x;
    int bh = g >> 12;
    int de4 = g & 4095;
    float chdec = expf(head_slope(bh & (HH - 1)) * 64.f);
    size_t base = (size_t)bh * NCH * (DD * DD) + (size_t)de4 * 4;
    float4 s = make_float4(0.f, 0.f, 0.f, 0.f);
    for (int c = 0; c < NCH; c++) {
        size_t idx = base + (size_t)c * (DD * DD);
        *(float4*)(g_S + idx) = s;
        float4 u = *(const float4*)(g_U + idx);
        s.x = s.x * chdec + u.x;
        s.y = s.y * chdec + u.y;
        s.z = s.z * chdec + u.z;
        s.w = s.w * chdec + u.w;
    }
}

// ---- pass C: inter = (q*qdec)@S + intra, fused gnorm*gate -> onh fp16 -------
__global__ void __launch_bounds__(256, 1) k_inter(const float* __restrict__ gnw) {
    extern __shared__ __align__(16) float sm2[];
    float* qs = sm2;
    float* Ss = qs + 64 * 132;
    const int tid = threadIdx.x;
    const int c = blockIdx.x & (NCH - 1);
    const int bh = blockIdx.x >> 6;
    const int b = bh >> 4, h = bh & (HH - 1);
    const float slope = head_slope(h);
    const size_t tbase = ((size_t)bh * TT + c * CH) * DD;
    const size_t sbase = ((size_t)bh * NCH + c) * (DD * DD);

#pragma unroll
    for (int l = 0; l < 8; l++) {
        int idx = tid + l * 256;
        int row = idx >> 5;
        int c0 = (idx & 31) << 2;
        *(float4*)&qs[row * 132 + c0] = *(const float4*)(g_q + tbase + row * DD + c0);
    }
#pragma unroll
    for (int l = 0; l < 16; l++) {
        int idx = tid + l * 256;
        *(float4*)&Ss[idx * 4] = *(const float4*)(g_S + sbase + (size_t)idx * 4);
    }
    __syncthreads();

    const int tx = tid & 15, ty = tid >> 4;
    float acc[4][8];
#pragma unroll
    for (int i = 0; i < 4; i++)
#pragma unroll
        for (int j = 0; j < 8; j++) acc[i][j] = 0.f;
#pragma unroll 2
    for (int d = 0; d < 128; d++) {
        float a[4];
#pragma unroll
        for (int r = 0; r < 4; r++) a[r] = qs[(4 * ty + r) * 132 + d];
        float b[8];
        *(float4*)(b) = *(const float4*)&Ss[d * DD + 8 * tx];
        *(float4*)(b + 4) = *(const float4*)&Ss[d * DD + 8 * tx + 4];
#pragma unroll
        for (int r = 0; r < 4; r++)
#pragma unroll
            for (int e = 0; e < 8; e++) acc[r][e] += a[r] * b[e];
    }

    // fused epilogue: o = intra + inter; group rmsnorm over d; * gnw * gate
    const float4 w0 = *(const float4*)&gnw[h * DD + 8 * tx];
    const float4 w1 = *(const float4*)&gnw[h * DD + 8 * tx + 4];
#pragma unroll
    for (int r = 0; r < 4; r++) {
        int i = 4 * ty + r;
        float qd = expf(slope * (float)(i + 1));
        const float* osrc = g_o + tbase + (size_t)i * DD + 8 * tx;
        float4 c0 = *(const float4*)osrc;
        float4 c1 = *(const float4*)(osrc + 4);
        float v[8];
        v[0] = c0.x + acc[r][0] * qd;
        v[1] = c0.y + acc[r][1] * qd;
        v[2] = c0.z + acc[r][2] * qd;
        v[3] = c0.w + acc[r][3] * qd;
        v[4] = c1.x + acc[r][4] * qd;
        v[5] = c1.y + acc[r][5] * qd;
        v[6] = c1.z + acc[r][6] * qd;
        v[7] = c1.w + acc[r][7] * qd;
        float ss = 0.f;
#pragma unroll
        for (int e = 0; e < 8; e++) ss += v[e] * v[e];
        ss += __shfl_xor_sync(0xffffffffu, ss, 1);
        ss += __shfl_xor_sync(0xffffffffu, ss, 2);
        ss += __shfl_xor_sync(0xffffffffu, ss, 4);
        ss += __shfl_xor_sync(0xffffffffu, ss, 8);
        float rq = rsqrtf(ss * (1.f / 128.f) + 1e-6f);

        size_t bt = (size_t)b * TT + c * CH + i;
        const float* gp = g_gate + bt * HDIM + h * DD + 8 * tx;
        float4 g0 = *(const float4*)gp;
        float4 g1 = *(const float4*)(gp + 4);
        __half hb[8];
        hb[0] = __float2half(v[0] * rq * w0.x * g0.x);
        hb[1] = __float2half(v[1] * rq * w0.y * g0.y);
        hb[2] = __float2half(v[2] * rq * w0.z * g0.z);
        hb[3] = __float2half(v[3] * rq * w0.w * g0.w);
        hb[4] = __float2half(v[4] * rq * w1.x * g1.x);
        hb[5] = __float2half(v[5] * rq * w1.y * g1.y);
        hb[6] = __float2half(v[6] * rq * w1.z * g1.z);
        hb[7] = __float2half(v[7] * rq * w1.w * g1.w);
        *(uint4*)(g_onh + bt * HDIM + h * DD + 8 * tx) = *(uint4*)hb;
    }
}

// -----------------------------------------------------------------------------
extern "C" void kernel_launch(void* const* d_in, const int* in_sizes, int n_in,
                              void* d_out, int out_size) {
    const float* hidden = (const float*)d_in[0];
    const float* w_qkv = (const float*)d_in[1];
    const float* q_ln_w = (const float*)d_in[2];
    const float* k_ln_w = (const float*)d_in[3];
    const float* g_norm_w = (const float*)d_in[4];
    const float* w_g_proj = (const float*)d_in[5];
    const float* w_dense = (const float*)d_in[6];
    const int* pos = (const int*)d_in[7];
    float* out = (float*)d_out;

    void *p_gate, *p_hh, *p_wqh, *p_wgh, *p_wdh, *p_onh, *p_q, *p_k, *p_v;
    cudaGetSymbolAddress(&p_gate, g_gate);
    cudaGetSymbolAddress(&p_hh, g_hh);
    cudaGetSymbolAddress(&p_wqh, g_wqh);
    cudaGetSymbolAddress(&p_wgh, g_wgh);
    cudaGetSymbolAddress(&p_wdh, g_wdh);
    cudaGetSymbolAddress(&p_onh, g_onh);
    cudaGetSymbolAddress(&p_q, g_q);
    cudaGetSymbolAddress(&p_k, g_k);
    cudaGetSymbolAddress(&p_v, g_v);

    const int smem3 = (128 * QK_P * 2 + 64 * 128 + 64 * 65 + 64) * 4;  // 119296
    const int smem5 = (64 * 132 + 128 * 128) * 4;                      // 99328
    const int smemG = GNSTG * GSTG;                                    // 221184
    cudaFuncSetAttribute(k_chunk_local, cudaFuncAttributeMaxDynamicSharedMemorySize, smem3);
    cudaFuncSetAttribute(k_inter, cudaFuncAttributeMaxDynamicSharedMemorySize, smem5);
    cudaFuncSetAttribute(gemm_f16, cudaFuncAttributeMaxDynamicSharedMemorySize, smemG);

    // 0: hidden -> fp16
    k_cvt_f16<<<16384, 256>>>(hidden, (__half*)p_hh, BB * TT * HDIM / 4);
    // 1: w_qkv -> fp16
    k_cvt_f16<<<12288, 256>>>(w_qkv, (__half*)p_wqh, O3 * HDIM / 4);
    // 2: rope table
    k_rope_table<<<(BB * TT * 32) / 256, 256>>>(pos);
    // 3: qkv GEMM with fused rmsnorm+rope epilogue   (ncu profile slot)
    gemm_f16<<<dim3(O3 / 128, (BB * TT) / 256), 256, smemG>>>(
        (const __half*)p_hh, (const __half*)p_wqh, nullptr, O3, 2,
        q_ln_w, k_ln_w, (float*)p_q, (float*)p_k, (float*)p_v);
    // 4: w_g_proj -> fp16
    k_cvt_f16<<<4096, 256>>>(w_g_proj, (__half*)p_wgh, HDIM * HDIM / 4);
    // 5: gate = sigmoid(hidden @ w_g_proj^T), fp32
    gemm_f16<<<dim3(HDIM / 128, (BB * TT) / 256), 256, smemG>>>(
        (const __half*)p_hh, (const __half*)p_wgh, (float*)p_gate, HDIM, 1,
        nullptr, nullptr, nullptr, nullptr, nullptr);
    // 6: per-chunk local (att, intra, U)
    k_chunk_local<<<BB * HH * NCH, 256, smem3>>>();
    // 7: decayed prefix scan
    k_scan<<<(BB * HH * DD * DD / 4) / 256, 256>>>();
    // 8: inter + fused group-rmsnorm * gate -> onh fp16
    k_inter<<<BB * HH * NCH, 256, smem5>>>(g_norm_w);
    // 9: w_dense -> fp16
    k_cvt_f16<<<4096, 256>>>(w_dense, (__half*)p_wdh, HDIM * HDIM / 4);
    // 10: out = on @ w_dense^T, fp32
    gemm_f16<<<dim3(HDIM / 128, (BB * TT) / 256), 256, smemG>>>(
        (const __half*)p_onh, (const __half*)p_wdh, out, HDIM, 0,
        nullptr, nullptr, nullptr, nullptr, nullptr);
}

// round 9
// speedup vs baseline: 4.5605x; 1.0227x over previous
#include <cuda_runtime.h>
#include <cuda_fp16.h>
#include <cstdint>

#define BB 2
#define TT 4096
#define HH 16
#define DD 128
#define HDIM 2048
#define O3 6144
#define NQG 8192
#define NCH 64
#define CH 64

typedef unsigned long long ull;

// ---------------- scratch (static device globals; no runtime allocation) ----
static __device__ float g_q[(size_t)BB * HH * TT * DD];       // (b,h,t,d)
static __device__ float g_k[(size_t)BB * HH * TT * DD];
static __device__ float g_v[(size_t)BB * HH * TT * DD];
static __device__ float g_o[(size_t)BB * HH * TT * DD];       // intra term
static __device__ float g_gate[(size_t)BB * TT * HDIM];       // sigmoid'ed, fp32
static __device__ float g_U[(size_t)BB * HH * NCH * DD * DD];
static __device__ float g_S[(size_t)BB * HH * NCH * DD * DD];
static __device__ float g_ct[(size_t)BB * TT * 32];
static __device__ float g_st[(size_t)BB * TT * 32];

// fp16 operands
static __device__ __half g_hh[(size_t)BB * TT * HDIM];
static __device__ __half g_wqh[(size_t)O3 * HDIM];
static __device__ __half g_wgh[(size_t)HDIM * HDIM];
static __device__ __half g_wdh[(size_t)HDIM * HDIM];
static __device__ __half g_onh[(size_t)BB * TT * HDIM];

__device__ __forceinline__ float head_slope(int h) {
    float a = (float)exp2(-0.5 * (double)(h + 1));
    return (float)(-(double)a * (1.0 - 11.0 / 31.0 + 1e-5));
}

__device__ __forceinline__ uint32_t s2u(const void* p) {
    uint32_t a;
    asm("{ .reg .u64 t; cvta.to.shared.u64 t, %1; cvt.u32.u64 %0, t; }" : "=r"(a) : "l"(p));
    return a;
}

// ---- packed f32x2 helpers (exact fp32 rn math, 2 FMA per fma-pipe slot) ----
__device__ __forceinline__ ull pk2(float lo, float hi) {
    ull d;
    asm("mov.b64 %0, {%1, %2};" : "=l"(d) : "f"(lo), "f"(hi));
    return d;
}
__device__ __forceinline__ void fma2(ull& c, ull a, ull b) {
    asm("fma.rn.f32x2 %0, %1, %2, %3;" : "=l"(c) : "l"(a), "l"(b), "l"(c));
}
__device__ __forceinline__ ull mul2(ull a, ull b) {
    ull d;
    asm("mul.rn.f32x2 %0, %1, %2;" : "=l"(d) : "l"(a), "l"(b));
    return d;
}
__device__ __forceinline__ float2 upk(ull d) {
    float2 f;
    asm("mov.b64 {%0, %1}, %2;" : "=f"(f.x), "=f"(f.y) : "l"(d));
    return f;
}

__device__ __forceinline__ void cp16(uint32_t dst, const void* src) {
    asm volatile("cp.async.cg.shared.global [%0], [%1], 16;" :: "r"(dst), "l"(src));
}

__device__ __forceinline__ void ldsm4(uint32_t& r0, uint32_t& r1, uint32_t& r2, uint32_t& r3,
                                      uint32_t addr) {
    asm volatile("ldmatrix.sync.aligned.m8n8.x4.shared.b16 {%0,%1,%2,%3}, [%4];"
                 : "=r"(r0), "=r"(r1), "=r"(r2), "=r"(r3) : "r"(addr));
}

__device__ __forceinline__ void mma16816(float* c, const uint32_t* a, const uint32_t* b) {
    asm volatile(
        "mma.sync.aligned.m16n8k16.row.col.f32.f16.f16.f32 "
        "{%0,%1,%2,%3}, {%4,%5,%6,%7}, {%8,%9}, {%0,%1,%2,%3};"
        : "+f"(c[0]), "+f"(c[1]), "+f"(c[2]), "+f"(c[3])
        : "r"(a[0]), "r"(a[1]), "r"(a[2]), "r"(a[3]), "r"(b[0]), "r"(b[1]));
}

// ======================= fp16 mma.sync GEMM ==================================
// tile 256x128, BK=64 -> 32 chunks.
// mode 0: plain fp32 out (dense).
// mode 2: merged qkv+gate. n-segments: 0=q,1=k (rmsnorm+rope), 2=v, 3=gate(sigmoid).
#define GPITCH 144
#define GA_BYTES (256 * GPITCH)
#define GB_BYTES (128 * GPITCH)
#define GSTG (GA_BYTES + GB_BYTES)
#define GNSTG 4
#define GCHUNKS 32

__global__ void __launch_bounds__(256, 1) gemm_f16(
    const __half* __restrict__ Am, const __half* __restrict__ Bm,
    const __half* __restrict__ Bm2,
    float* __restrict__ C, int Ntot, int mode,
    const float* __restrict__ qlnw, const float* __restrict__ klnw,
    float* __restrict__ outq, float* __restrict__ outk, float* __restrict__ outv) {
    extern __shared__ __align__(128) char smem[];
    const uint32_t sbase = s2u(smem);
    const int tid = threadIdx.x;
    const int lane = tid & 31;
    const int warp = tid >> 5;
    const int wy = warp & 3;
    const int wx = warp >> 2;
    const int m0 = blockIdx.y * 256;
    const int n0 = blockIdx.x * 128;

    const __half* Bbase = (mode == 2 && n0 >= O3)
                              ? Bm2 + (size_t)(n0 - O3) * 2048
                              : Bm + (size_t)n0 * 2048;

    float acc[4][8][4];
#pragma unroll
    for (int i = 0; i < 4; i++)
#pragma unroll
        for (int j = 0; j < 8; j++)
#pragma unroll
            for (int q = 0; q < 4; q++) acc[i][j][q] = 0.f;

#define LOAD_CHUNK(c, s)                                                                \
    do {                                                                                \
        int _kk = (c) << 6;                                                             \
        const __half* _Ab = Am + (size_t)m0 * 2048 + _kk;                               \
        const __half* _Bb = Bbase + _kk;                                                \
        uint32_t _sa = sbase + (s) * GSTG;                                              \
        uint32_t _sb = _sa + GA_BYTES;                                                  \
        _Pragma("unroll") for (int t = 0; t < 8; t++) {                                 \
            int idx = tid + t * 256;                                                    \
            int row = idx >> 3, ch = idx & 7;                                           \
            cp16(_sa + row * GPITCH + ch * 16, _Ab + (size_t)row * 2048 + ch * 8);      \
        }                                                                               \
        _Pragma("unroll") for (int t = 0; t < 4; t++) {                                 \
            int idx = tid + t * 256;                                                    \
            int row = idx >> 3, ch = idx & 7;                                           \
            cp16(_sb + row * GPITCH + ch * 16, _Bb + (size_t)row * 2048 + ch * 8);      \
        }                                                                               \
    } while (0)

    for (int c = 0; c < 3; c++) {
        LOAD_CHUNK(c, c);
        asm volatile("cp.async.commit_group;" ::: "memory");
    }

    const uint32_t aoff = (uint32_t)(wy * 64 + (lane & 15)) * GPITCH + (lane >> 4) * 16;
    const int brow = (lane & 7) + ((lane >> 4) << 3);
    const uint32_t boff0 = GA_BYTES + (uint32_t)(wx * 64 + brow) * GPITCH + ((lane >> 3) & 1) * 16;

    for (int i = 0; i < GCHUNKS; i++) {
        const int s = i & 3;
        asm volatile("cp.async.wait_group 2;" ::: "memory");
        __syncthreads();
        {
            const int j = i + 3;
            if (j < GCHUNKS) LOAD_CHUNK(j, j & 3);
        }
        asm volatile("cp.async.commit_group;" ::: "memory");
        const uint32_t sa = sbase + s * GSTG;

#pragma unroll
        for (int ks = 0; ks < 4; ks++) {
            uint32_t a[4][4], b[4][2];
#pragma unroll
            for (int mt = 0; mt < 4; mt++)
                ldsm4(a[mt][0], a[mt][1], a[mt][2], a[mt][3],
                      sa + aoff + mt * 16 * GPITCH + ks * 32);
            ldsm4(b[0][0], b[0][1], b[1][0], b[1][1], sa + boff0 + ks * 32);
            ldsm4(b[2][0], b[2][1], b[3][0], b[3][1], sa + boff0 + 16 * GPITCH + ks * 32);
#pragma unroll
            for (int mt = 0; mt < 4; mt++)
#pragma unroll
                for (int nt = 0; nt < 4; nt++)
                    mma16816(acc[mt][nt * 2 + 0], a[mt], b[nt]);
            ldsm4(b[0][0], b[0][1], b[1][0], b[1][1], sa + boff0 + 32 * GPITCH + ks * 32);
            ldsm4(b[2][0], b[2][1], b[3][0], b[3][1], sa + boff0 + 48 * GPITCH + ks * 32);
#pragma unroll
            for (int mt = 0; mt < 4; mt++)
#pragma unroll
                for (int nt = 0; nt < 4; nt++)
                    mma16816(acc[mt][nt * 2 + 1], a[mt], b[nt]);
        }
    }

    asm volatile("cp.async.wait_group 0;" ::: "memory");
    __syncthreads();

    const int seg = (mode == 2) ? (n0 >> 11) : -1;

    if (mode == 2 && seg < 3) {
        // ---- fused qkv epilogue ----
        const int h = (n0 >> 7) & 15;
        float* rbuf = (float*)smem;

        if (seg < 2) {
#pragma unroll
            for (int mt = 0; mt < 4; mt++)
#pragma unroll
                for (int rh = 0; rh < 2; rh++) {
                    float p = 0.f;
#pragma unroll
                    for (int j = 0; j < 8; j++) {
                        float a0 = acc[mt][j][rh * 2], a1 = acc[mt][j][rh * 2 + 1];
                        p += a0 * a0 + a1 * a1;
                    }
                    p += __shfl_xor_sync(0xffffffffu, p, 1);
                    p += __shfl_xor_sync(0xffffffffu, p, 2);
                    if ((lane & 3) == 0)
                        rbuf[wx * 256 + wy * 64 + (lane >> 2) + mt * 16 + rh * 8] = p;
                }
            __syncthreads();
        }

        const float* lnw = (seg == 0) ? qlnw : klnw;
        float* dstbase = (seg == 0) ? outq : ((seg == 1) ? outk : outv);
        const float segscale = (seg == 0) ? 0.08838834764831845f : 1.0f;

#pragma unroll
        for (int mt = 0; mt < 4; mt++) {
#pragma unroll
            for (int rh = 0; rh < 2; rh++) {
                const int rloc = wy * 64 + (lane >> 2) + mt * 16 + rh * 8;
                const int r = m0 + rloc;
                const int b = r >> 12, t = r & 4095;
                float rq = 1.f;
                if (seg < 2)
                    rq = rsqrtf((rbuf[rloc] + rbuf[256 + rloc]) * (1.f / 128.f) + 1e-6f);

                float vals[16];
#pragma unroll
                for (int j = 0; j < 8; j++) {
                    int ld = wx * 64 + (j & 1) * 32 + (j >> 1) * 8 + (lane & 3) * 2;
                    float v0 = acc[mt][j][rh * 2], v1 = acc[mt][j][rh * 2 + 1];
                    if (seg < 2) {
                        v0 *= rq * lnw[ld];
                        v1 *= rq * lnw[ld + 1];
                    }
                    vals[j * 2] = v0;
                    vals[j * 2 + 1] = v1;
                }
                if (seg < 2 && wx == 0) {
#pragma unroll
                    for (int nt = 0; nt < 4; nt++) {
                        int d = nt * 8 + (lane & 3) * 2;
                        float2 c2 = *(const float2*)&g_ct[(size_t)r * 32 + d];
                        float2 s2 = *(const float2*)&g_st[(size_t)r * 32 + d];
                        float e0 = vals[nt * 4 + 0], e1 = vals[nt * 4 + 1];
                        float o0 = vals[nt * 4 + 2], o1 = vals[nt * 4 + 3];
                        vals[nt * 4 + 0] = e0 * c2.x - o0 * s2.x;
                        vals[nt * 4 + 1] = e1 * c2.y - o1 * s2.y;
                        vals[nt * 4 + 2] = o0 * c2.x + e0 * s2.x;
                        vals[nt * 4 + 3] = o1 * c2.y + e1 * s2.y;
                    }
                }
                size_t obase = ((size_t)(b * HH + h) * TT + t) * DD;
#pragma unroll
                for (int j = 0; j < 8; j++) {
                    int ld = wx * 64 + (j & 1) * 32 + (j >> 1) * 8 + (lane & 3) * 2;
                    *(float2*)(dstbase + obase + ld) =
                        make_float2(vals[j * 2] * segscale, vals[j * 2 + 1] * segscale);
                }
            }
        }
    } else {
        const int act = (seg == 3);
        const int ncol0 = (seg == 3) ? (n0 - O3) : n0;
        const int rbase = m0 + wy * 64 + (lane >> 2);
        const int cbase = ncol0 + wx * 64 + (lane & 3) * 2;
#pragma unroll
        for (int mt = 0; mt < 4; mt++) {
#pragma unroll
            for (int j = 0; j < 8; j++) {
                int nt = j >> 1, half = j & 1;
                int col = cbase + half * 32 + nt * 8;
                float v[4];
#pragma unroll
                for (int q = 0; q < 4; q++) {
                    float x = acc[mt][j][q];
                    v[q] = act ? (1.f / (1.f + expf(-x))) : x;
                }
                float* d0 = C + (size_t)(rbase + mt * 16) * Ntot + col;
                float* d1 = C + (size_t)(rbase + mt * 16 + 8) * Ntot + col;
                *(float2*)d0 = make_float2(v[0], v[1]);
                *(float2*)d1 = make_float2(v[2], v[3]);
            }
        }
    }
}

// ---------------- all fp32 -> fp16 conversions in one kernel -----------------
#define CV_H (BB * TT * HDIM / 4)
#define CV_Q (O3 * HDIM / 4)
#define CV_G (HDIM * HDIM / 4)
__global__ void __launch_bounds__(256) k_cvt_all(const float* __restrict__ hidden,
                                                 const float* __restrict__ wq,
                                                 const float* __restrict__ wg,
                                                 const float* __restrict__ wd) {
    int i = blockIdx.x * 256 + threadIdx.x;
    const float* src;
    __half* dst;
    int off;
    if (i < CV_H) {
        src = hidden; dst = g_hh; off = i;
    } else if (i < CV_H + CV_Q) {
        src = wq; dst = g_wqh; off = i - CV_H;
    } else if (i < CV_H + CV_Q + CV_G) {
        src = wg; dst = g_wgh; off = i - CV_H - CV_Q;
    } else {
        src = wd; dst = g_wdh; off = i - CV_H - CV_Q - CV_G;
    }
    float4 x = ((const float4*)src)[off];
    __half h[4] = {__float2half(x.x), __float2half(x.y), __float2half(x.z), __float2half(x.w)};
    ((uint2*)dst)[off] = *(uint2*)h;
}

// ---------------- rope cos/sin table ----------------------------------------
__global__ void __launch_bounds__(256) k_rope_table(const int* __restrict__ pos) {
    int idx = blockIdx.x * 256 + threadIdx.x;
    int bt = idx >> 5, d = idx & 31;
    float p = (float)pos[bt];
    float inv = exp2f(-(float)d * 0.4152410118609203f);
    float sn, cs;
    sincosf(p * inv, &sn, &cs);
    g_ct[idx] = cs;
    g_st[idx] = sn;
}

// ---------------- pass A: per (b,h,c): att(masked), intra = att@v, U ---------
#define QK_P 68
__global__ void __launch_bounds__(256, 1) k_chunk_local() {
    extern __shared__ __align__(16) float sm[];
    float* qsT = sm;
    float* ksT = qsT + 128 * QK_P;
    float* vs = ksT + 128 * QK_P;
    float* att = vs + 64 * 128;
    float* kdec = att + 64 * 65;

    const int tid = threadIdx.x;
    const int c = blockIdx.x & (NCH - 1);
    const int bh = blockIdx.x >> 6;
    const int h = bh & (HH - 1);
    const float slope = head_slope(h);
    const size_t tbase = ((size_t)bh * TT + c * CH) * DD;

#pragma unroll
    for (int l = 0; l < 8; l++) {
        int idx = tid + l * 256;
        int row = idx >> 5;
        int c0 = (idx & 31) << 2;
        float4 a = *(const float4*)(g_q + tbase + row * DD + c0);
        float4 b = *(const float4*)(g_k + tbase + row * DD + c0);
        float4 vv = *(const float4*)(g_v + tbase + row * DD + c0);
        qsT[(c0 + 0) * QK_P + row] = a.x;
        qsT[(c0 + 1) * QK_P + row] = a.y;
        qsT[(c0 + 2) * QK_P + row] = a.z;
        qsT[(c0 + 3) * QK_P + row] = a.w;
        ksT[(c0 + 0) * QK_P + row] = b.x;
        ksT[(c0 + 1) * QK_P + row] = b.y;
        ksT[(c0 + 2) * QK_P + row] = b.z;
        ksT[(c0 + 3) * QK_P + row] = b.w;
        *(float4*)&vs[row * DD + c0] = vv;
    }
    if (tid < 64) kdec[tid] = expf(slope * (float)(63 - tid));
    __syncthreads();

    const int tx = tid & 15, ty = tid >> 4;

    {
        ull acc2[4][2] = {};
#pragma unroll 4
        for (int d = 0; d < 128; d++) {
            float a[4], b[4];
            *(float4*)a = *(const float4*)&qsT[d * QK_P + 4 * ty];
            *(float4*)b = *(const float4*)&ksT[d * QK_P + 4 * tx];
            ull b01 = pk2(b[0], b[1]), b23 = pk2(b[2], b[3]);
#pragma unroll
            for (int i = 0; i < 4; i++) {
                ull ai = pk2(a[i], a[i]);
                fma2(acc2[i][0], ai, b01);
                fma2(acc2[i][1], ai, b23);
            }
        }
#pragma unroll
        for (int i = 0; i < 4; i++)
#pragma unroll
            for (int jp = 0; jp < 2; jp++) {
                float2 p = upk(acc2[i][jp]);
                int ri = 4 * ty + i, cj = 4 * tx + jp * 2;
                float m0 = (ri >= cj) ? expf(slope * (float)(ri - cj)) : 0.f;
                float m1 = (ri >= cj + 1) ? expf(slope * (float)(ri - cj - 1)) : 0.f;
                att[ri * 65 + cj] = p.x * m0;
                att[ri * 65 + cj + 1] = p.y * m1;
            }
    }
    __syncthreads();

    {
        ull acc2[4][4] = {};
#pragma unroll 2
        for (int j = 0; j < 64; j++) {
            float a[4];
#pragma unroll
            for (int r = 0; r < 4; r++) a[r] = att[(4 * ty + r) * 65 + j];
            float b[8];
            *(float4*)(b) = *(const float4*)&vs[j * DD + 8 * tx];
            *(float4*)(b + 4) = *(const float4*)&vs[j * DD + 8 * tx + 4];
            ull b2[4] = {pk2(b[0], b[1]), pk2(b[2], b[3]), pk2(b[4], b[5]), pk2(b[6], b[7])};
#pragma unroll
            for (int r = 0; r < 4; r++) {
                ull ar = pk2(a[r], a[r]);
#pragma unroll
                for (int e = 0; e < 4; e++) fma2(acc2[r][e], ar, b2[e]);
            }
        }
#pragma unroll
        for (int r = 0; r < 4; r++) {
            float2 p0 = upk(acc2[r][0]), p1 = upk(acc2[r][1]);
            float2 p2 = upk(acc2[r][2]), p3 = upk(acc2[r][3]);
            float* dst = g_o + tbase + (size_t)(4 * ty + r) * DD + 8 * tx;
            *(float4*)(dst) = make_float4(p0.x, p0.y, p1.x, p1.y);
            *(float4*)(dst + 4) = make_float4(p2.x, p2.y, p3.x, p3.y);
        }
    }

    {
        ull acc2[8][4] = {};
#pragma unroll 2
        for (int i = 0; i < 64; i++) {
            float kd = kdec[i];
            ull kd2 = pk2(kd, kd);
            float a[8];
#pragma unroll
            for (int r = 0; r < 8; r++) a[r] = ksT[(8 * ty + r) * QK_P + i];
            float b[8];
            *(float4*)(b) = *(const float4*)&vs[i * DD + 8 * tx];
            *(float4*)(b + 4) = *(const float4*)&vs[i * DD + 8 * tx + 4];
            ull b2[4];
            b2[0] = mul2(pk2(b[0], b[1]), kd2);
            b2[1] = mul2(pk2(b[2], b[3]), kd2);
            b2[2] = mul2(pk2(b[4], b[5]), kd2);
            b2[3] = mul2(pk2(b[6], b[7]), kd2);
#pragma unroll
            for (int r = 0; r < 8; r++) {
                ull ar = pk2(a[r], a[r]);
#pragma unroll
                for (int e = 0; e < 4; e++) fma2(acc2[r][e], ar, b2[e]);
            }
        }
        size_t ub = ((size_t)bh * NCH + c) * (DD * DD);
#pragma unroll
        for (int r = 0; r < 8; r++) {
            float2 p0 = upk(acc2[r][0]), p1 = upk(acc2[r][1]);
            float2 p2 = upk(acc2[r][2]), p3 = upk(acc2[r][3]);
            float* dst = g_U + ub + (size_t)(8 * ty + r) * DD + 8 * tx;
            *(float4*)(dst) = make_float4(p0.x, p0.y, p1.x, p1.y);
            *(float4*)(dst + 4) = make_float4(p2.x, p2.y, p3.x, p3.y);
        }
    }
}

// ---------------- pass B: decayed prefix scan (float4) -----------------------
__global__ void __launch_bounds__(256) k_scan() {
    int g = blockIdx.x * 256 + threadIdx.x;
    int bh = g >> 12;
    int de4 = g & 4095;
    float chdec = expf(head_slope(bh & (HH - 1)) * 64.f);
    size_t base = (size_t)bh * NCH * (DD * DD) + (size_t)de4 * 4;
    float4 s = make_float4(0.f, 0.f, 0.f, 0.f);
    for (int c = 0; c < NCH; c++) {
        size_t idx = base + (size_t)c * (DD * DD);
        *(float4*)(g_S + idx) = s;
        float4 u = *(const float4*)(g_U + idx);
        s.x = s.x * chdec + u.x;
        s.y = s.y * chdec + u.y;
        s.z = s.z * chdec + u.z;
        s.w = s.w * chdec + u.w;
    }
}

// ---- pass C: inter = (q*qdec)@S + intra, fused gnorm*gate -> onh fp16 -------
__global__ void __launch_bounds__(256, 1) k_inter(const float* __restrict__ gnw) {
    extern __shared__ __align__(16) float sm2[];
    float* qs = sm2;
    float* Ss = qs + 64 * 132;
    const int tid = threadIdx.x;
    const int c = blockIdx.x & (NCH - 1);
    const int bh = blockIdx.x >> 6;
    const int b = bh >> 4, h = bh & (HH - 1);
    const float slope = head_slope(h);
    const size_t tbase = ((size_t)bh * TT + c * CH) * DD;
    const size_t sbase = ((size_t)bh * NCH + c) * (DD * DD);

#pragma unroll
    for (int l = 0; l < 8; l++) {
        int idx = tid + l * 256;
        int row = idx >> 5;
        int c0 = (idx & 31) << 2;
        *(float4*)&qs[row * 132 + c0] = *(const float4*)(g_q + tbase + row * DD + c0);
    }
#pragma unroll
    for (int l = 0; l < 16; l++) {
        int idx = tid + l * 256;
        *(float4*)&Ss[idx * 4] = *(const float4*)(g_S + sbase + (size_t)idx * 4);
    }
    __syncthreads();

    const int tx = tid & 15, ty = tid >> 4;
    ull acc2[4][4] = {};
#pragma unroll 2
    for (int d = 0; d < 128; d++) {
        float a[4];
#pragma unroll
        for (int r = 0; r < 4; r++) a[r] = qs[(4 * ty + r) * 132 + d];
        float b[8];
        *(float4*)(b) = *(const float4*)&Ss[d * DD + 8 * tx];
        *(float4*)(b + 4) = *(const float4*)&Ss[d * DD + 8 * tx + 4];
        ull b2[4] = {pk2(b[0], b[1]), pk2(b[2], b[3]), pk2(b[4], b[5]), pk2(b[6], b[7])};
#pragma unroll
        for (int r = 0; r < 4; r++) {
            ull ar = pk2(a[r], a[r]);
#pragma unroll
            for (int e = 0; e < 4; e++) fma2(acc2[r][e], ar, b2[e]);
        }
    }

    const float4 w0 = *(const float4*)&gnw[h * DD + 8 * tx];
    const float4 w1 = *(const float4*)&gnw[h * DD + 8 * tx + 4];
#pragma unroll
    for (int r = 0; r < 4; r++) {
        int i = 4 * ty + r;
        float qd = expf(slope * (float)(i + 1));
        float acc[8];
        float2 p0 = upk(acc2[r][0]), p1 = upk(acc2[r][1]);
        float2 p2 = upk(acc2[r][2]), p3 = upk(acc2[r][3]);
        acc[0] = p0.x; acc[1] = p0.y; acc[2] = p1.x; acc[3] = p1.y;
        acc[4] = p2.x; acc[5] = p2.y; acc[6] = p3.x; acc[7] = p3.y;

        const float* osrc = g_o + tbase + (size_t)i * DD + 8 * tx;
        float4 c0 = *(const float4*)osrc;
        float4 c1 = *(const float4*)(osrc + 4);
        float v[8];
        v[0] = c0.x + acc[0] * qd;
        v[1] = c0.y + acc[1] * qd;
        v[2] = c0.z + acc[2] * qd;
        v[3] = c0.w + acc[3] * qd;
        v[4] = c1.x + acc[4] * qd;
        v[5] = c1.y + acc[5] * qd;
        v[6] = c1.z + acc[6] * qd;
        v[7] = c1.w + acc[7] * qd;
        float ss = 0.f;
#pragma unroll
        for (int e = 0; e < 8; e++) ss += v[e] * v[e];
        ss += __shfl_xor_sync(0xffffffffu, ss, 1);
        ss += __shfl_xor_sync(0xffffffffu, ss, 2);
        ss += __shfl_xor_sync(0xffffffffu, ss, 4);
        ss += __shfl_xor_sync(0xffffffffu, ss, 8);
        float rq = rsqrtf(ss * (1.f / 128.f) + 1e-6f);

        size_t bt = (size_t)b * TT + c * CH + i;
        const float* gp = g_gate + bt * HDIM + h * DD + 8 * tx;
        float4 g0 = *(const float4*)gp;
        float4 g1 = *(const float4*)(gp + 4);
        __half hb[8];
        hb[0] = __float2half(v[0] * rq * w0.x * g0.x);
        hb[1] = __float2half(v[1] * rq * w0.y * g0.y);
        hb[2] = __float2half(v[2] * rq * w0.z * g0.z);
        hb[3] = __float2half(v[3] * rq * w0.w * g0.w);
        hb[4] = __float2half(v[4] * rq * w1.x * g1.x);
        hb[5] = __float2half(v[5] * rq * w1.y * g1.y);
        hb[6] = __float2half(v[6] * rq * w1.z * g1.z);
        hb[7] = __float2half(v[7] * rq * w1.w * g1.w);
        *(uint4*)(g_onh + bt * HDIM + h * DD + 8 * tx) = *(uint4*)hb;
    }
}

// -----------------------------------------------------------------------------
extern "C" void kernel_launch(void* const* d_in, const int* in_sizes, int n_in,
                              void* d_out, int out_size) {
    const float* hidden = (const float*)d_in[0];
    const float* w_qkv = (const float*)d_in[1];
    const float* q_ln_w = (const float*)d_in[2];
    const float* k_ln_w = (const float*)d_in[3];
    const float* g_norm_w = (const float*)d_in[4];
    const float* w_g_proj = (const float*)d_in[5];
    const float* w_dense = (const float*)d_in[6];
    const int* pos = (const int*)d_in[7];
    float* out = (float*)d_out;

    void *p_gate, *p_hh, *p_wqh, *p_wgh, *p_wdh, *p_onh, *p_q, *p_k, *p_v;
    cudaGetSymbolAddress(&p_gate, g_gate);
    cudaGetSymbolAddress(&p_hh, g_hh);
    cudaGetSymbolAddress(&p_wqh, g_wqh);
    cudaGetSymbolAddress(&p_wgh, g_wgh);
    cudaGetSymbolAddress(&p_wdh, g_wdh);
    cudaGetSymbolAddress(&p_onh, g_onh);
    cudaGetSymbolAddress(&p_q, g_q);
    cudaGetSymbolAddress(&p_k, g_k);
    cudaGetSymbolAddress(&p_v, g_v);

    const int smem3 = (128 * QK_P * 2 + 64 * 128 + 64 * 65 + 64) * 4;  // 119296
    const int smem5 = (64 * 132 + 128 * 128) * 4;                      // 99328
    const int smemG = GNSTG * GSTG;                                    // 221184
    cudaFuncSetAttribute(k_chunk_local, cudaFuncAttributeMaxDynamicSharedMemorySize, smem3);
    cudaFuncSetAttribute(k_inter, cudaFuncAttributeMaxDynamicSharedMemorySize, smem5);
    cudaFuncSetAttribute(gemm_f16, cudaFuncAttributeMaxDynamicSharedMemorySize, smemG);

    // 0: all fp32->fp16 conversions (hidden + 3 weights)
    k_cvt_all<<<(CV_H + CV_Q + 2 * CV_G) / 256, 256>>>(hidden, w_qkv, w_g_proj, w_dense);
    // 1: rope table
    k_rope_table<<<(BB * TT * 32) / 256, 256>>>(pos);
    // 2: merged qkv+gate GEMM (fused rmsnorm+rope / sigmoid epilogues)
    gemm_f16<<<dim3(NQG / 128, (BB * TT) / 256), 256, smemG>>>(
        (const __half*)p_hh, (const __half*)p_wqh, (const __half*)p_wgh,
        (float*)p_gate, HDIM, 2,
        q_ln_w, k_ln_w, (float*)p_q, (float*)p_k, (float*)p_v);
    // 3: per-chunk local (att, intra, U)  [ncu profile slot]
    k_chunk_local<<<BB * HH * NCH, 256, smem3>>>();
    // 4: decayed prefix scan
    k_scan<<<(BB * HH * DD * DD / 4) / 256, 256>>>();
    // 5: inter + fused group-rmsnorm * gate -> onh fp16
    k_inter<<<BB * HH * NCH, 256, smem5>>>(g_norm_w);
    // 6: out = on @ w_dense^T
    gemm_f16<<<dim3(HDIM / 128, (BB * TT) / 256), 256, smemG>>>(
        (const __half*)p_onh, (const __half*)p_wdh, nullptr, out, HDIM, 0,
        nullptr, nullptr, nullptr, nullptr, nullptr);
}

// round 10
// speedup vs baseline: 4.7975x; 1.0520x over previous
#include <cuda_runtime.h>
#include <cuda_fp16.h>
#include <cstdint>

#define BB 2
#define TT 4096
#define HH 16
#define DD 128
#define HDIM 2048
#define O3 6144
#define NQG 8192
#define NCH 64
#define CH 64

typedef unsigned long long ull;

// ---------------- scratch (static device globals; no runtime allocation) ----
static __device__ float g_q[(size_t)BB * HH * TT * DD];       // (b,h,t,d)
static __device__ float g_k[(size_t)BB * HH * TT * DD];
static __device__ float g_v[(size_t)BB * HH * TT * DD];
static __device__ float g_o[(size_t)BB * HH * TT * DD];       // intra term
static __device__ float g_gate[(size_t)BB * TT * HDIM];       // sigmoid'ed, fp32
static __device__ float g_U[(size_t)BB * HH * NCH * DD * DD];
static __device__ float g_S[(size_t)BB * HH * NCH * DD * DD];
static __device__ float g_ct[(size_t)BB * TT * 32];
static __device__ float g_st[(size_t)BB * TT * 32];

// fp16 operands
static __device__ __half g_hh[(size_t)BB * TT * HDIM];
static __device__ __half g_wqh[(size_t)O3 * HDIM];
static __device__ __half g_wgh[(size_t)HDIM * HDIM];
static __device__ __half g_wdh[(size_t)HDIM * HDIM];
static __device__ __half g_onh[(size_t)BB * TT * HDIM];

__device__ __forceinline__ float head_slope(int h) {
    float a = (float)exp2(-0.5 * (double)(h + 1));
    return (float)(-(double)a * (1.0 - 11.0 / 31.0 + 1e-5));
}

__device__ __forceinline__ uint32_t s2u(const void* p) {
    uint32_t a;
    asm("{ .reg .u64 t; cvta.to.shared.u64 t, %1; cvt.u32.u64 %0, t; }" : "=r"(a) : "l"(p));
    return a;
}

// ---- packed f32x2 helpers (exact fp32 rn math) ----
__device__ __forceinline__ ull pk2(float lo, float hi) {
    ull d;
    asm("mov.b64 %0, {%1, %2};" : "=l"(d) : "f"(lo), "f"(hi));
    return d;
}
__device__ __forceinline__ void fma2(ull& c, ull a, ull b) {
    asm("fma.rn.f32x2 %0, %1, %2, %3;" : "=l"(c) : "l"(a), "l"(b), "l"(c));
}
__device__ __forceinline__ ull mul2(ull a, ull b) {
    ull d;
    asm("mul.rn.f32x2 %0, %1, %2;" : "=l"(d) : "l"(a), "l"(b));
    return d;
}
__device__ __forceinline__ float2 upk(ull d) {
    float2 f;
    asm("mov.b64 {%0, %1}, %2;" : "=f"(f.x), "=f"(f.y) : "l"(d));
    return f;
}

__device__ __forceinline__ void cp16(uint32_t dst, const void* src) {
    asm volatile("cp.async.cg.shared.global [%0], [%1], 16;" :: "r"(dst), "l"(src));
}

__device__ __forceinline__ void ldsm4(uint32_t& r0, uint32_t& r1, uint32_t& r2, uint32_t& r3,
                                      uint32_t addr) {
    asm volatile("ldmatrix.sync.aligned.m8n8.x4.shared.b16 {%0,%1,%2,%3}, [%4];"
                 : "=r"(r0), "=r"(r1), "=r"(r2), "=r"(r3) : "r"(addr));
}

__device__ __forceinline__ void mma16816(float* c, const uint32_t* a, const uint32_t* b) {
    asm volatile(
        "mma.sync.aligned.m16n8k16.row.col.f32.f16.f16.f32 "
        "{%0,%1,%2,%3}, {%4,%5,%6,%7}, {%8,%9}, {%0,%1,%2,%3};"
        : "+f"(c[0]), "+f"(c[1]), "+f"(c[2]), "+f"(c[3])
        : "r"(a[0]), "r"(a[1]), "r"(a[2]), "r"(a[3]), "r"(b[0]), "r"(b[1]));
}

// ======================= fp16 mma.sync GEMM, 512 threads =====================
// tile 256x128, BK=64 -> 32 chunks; 16 warps (wy 0..7 x 32 rows, wx 0..1 x 64 cols)
// mode 0: plain fp32 out. mode 2: merged qkv+gate, segs 0=q,1=k,2=v,3=gate.
#define GPITCH 144
#define GA_BYTES (256 * GPITCH)
#define GB_BYTES (128 * GPITCH)
#define GSTG (GA_BYTES + GB_BYTES)
#define GNSTG 4
#define GCHUNKS 32

__global__ void __launch_bounds__(512, 1) gemm_f16(
    const __half* __restrict__ Am, const __half* __restrict__ Bm,
    const __half* __restrict__ Bm2,
    float* __restrict__ C, int Ntot, int mode,
    const float* __restrict__ qlnw, const float* __restrict__ klnw,
    float* __restrict__ outq, float* __restrict__ outk, float* __restrict__ outv) {
    extern __shared__ __align__(128) char smem[];
    const uint32_t sbase = s2u(smem);
    const int tid = threadIdx.x;
    const int lane = tid & 31;
    const int warp = tid >> 5;
    const int wy = warp & 7;     // 8 x 32 rows
    const int wx = warp >> 3;    // 2 x 64 cols
    const int m0 = blockIdx.y * 256;
    const int n0 = blockIdx.x * 128;

    const __half* Bbase = (mode == 2 && n0 >= O3)
                              ? Bm2 + (size_t)(n0 - O3) * 2048
                              : Bm + (size_t)n0 * 2048;

    float acc[2][8][4];
#pragma unroll
    for (int i = 0; i < 2; i++)
#pragma unroll
        for (int j = 0; j < 8; j++)
#pragma unroll
            for (int q = 0; q < 4; q++) acc[i][j][q] = 0.f;

#define LOAD_CHUNK(c, s)                                                                \
    do {                                                                                \
        int _kk = (c) << 6;                                                             \
        const __half* _Ab = Am + (size_t)m0 * 2048 + _kk;                               \
        const __half* _Bb = Bbase + _kk;                                                \
        uint32_t _sa = sbase + (s) * GSTG;                                              \
        uint32_t _sb = _sa + GA_BYTES;                                                  \
        _Pragma("unroll") for (int t = 0; t < 4; t++) {                                 \
            int idx = tid + t * 512;                                                    \
            int row = idx >> 3, ch = idx & 7;                                           \
            cp16(_sa + row * GPITCH + ch * 16, _Ab + (size_t)row * 2048 + ch * 8);      \
        }                                                                               \
        _Pragma("unroll") for (int t = 0; t < 2; t++) {                                 \
            int idx = tid + t * 512;                                                    \
            int row = idx >> 3, ch = idx & 7;                                           \
            cp16(_sb + row * GPITCH + ch * 16, _Bb + (size_t)row * 2048 + ch * 8);      \
        }                                                                               \
    } while (0)

    for (int c = 0; c < 3; c++) {
        LOAD_CHUNK(c, c);
        asm volatile("cp.async.commit_group;" ::: "memory");
    }

    const uint32_t aoff = (uint32_t)(wy * 32 + (lane & 15)) * GPITCH + (lane >> 4) * 16;
    const int brow = (lane & 7) + ((lane >> 4) << 3);
    const uint32_t boff0 = GA_BYTES + (uint32_t)(wx * 64 + brow) * GPITCH + ((lane >> 3) & 1) * 16;

    for (int i = 0; i < GCHUNKS; i++) {
        const int s = i & 3;
        asm volatile("cp.async.wait_group 2;" ::: "memory");
        __syncthreads();
        {
            const int j = i + 3;
            if (j < GCHUNKS) LOAD_CHUNK(j, j & 3);
        }
        asm volatile("cp.async.commit_group;" ::: "memory");
        const uint32_t sa = sbase + s * GSTG;

#pragma unroll
        for (int ks = 0; ks < 4; ks++) {
            uint32_t a[2][4], b[4][2];
#pragma unroll
            for (int mt = 0; mt < 2; mt++)
                ldsm4(a[mt][0], a[mt][1], a[mt][2], a[mt][3],
                      sa + aoff + mt * 16 * GPITCH + ks * 32);
            ldsm4(b[0][0], b[0][1], b[1][0], b[1][1], sa + boff0 + ks * 32);
            ldsm4(b[2][0], b[2][1], b[3][0], b[3][1], sa + boff0 + 16 * GPITCH + ks * 32);
#pragma unroll
            for (int mt = 0; mt < 2; mt++)
#pragma unroll
                for (int nt = 0; nt < 4; nt++)
                    mma16816(acc[mt][nt * 2 + 0], a[mt], b[nt]);
            ldsm4(b[0][0], b[0][1], b[1][0], b[1][1], sa + boff0 + 32 * GPITCH + ks * 32);
            ldsm4(b[2][0], b[2][1], b[3][0], b[3][1], sa + boff0 + 48 * GPITCH + ks * 32);
#pragma unroll
            for (int mt = 0; mt < 2; mt++)
#pragma unroll
                for (int nt = 0; nt < 4; nt++)
                    mma16816(acc[mt][nt * 2 + 1], a[mt], b[nt]);
        }
    }

    asm volatile("cp.async.wait_group 0;" ::: "memory");
    __syncthreads();

    const int seg = (mode == 2) ? (n0 >> 11) : -1;

    if (mode == 2 && seg < 3) {
        // ---- fused qkv epilogue: rmsnorm + rope + qscale ----
        const int h = (n0 >> 7) & 15;
        float* rbuf = (float*)smem;   // 512 floats

        if (seg < 2) {
#pragma unroll
            for (int mt = 0; mt < 2; mt++)
#pragma unroll
                for (int rh = 0; rh < 2; rh++) {
                    float p = 0.f;
#pragma unroll
                    for (int j = 0; j < 8; j++) {
                        float a0 = acc[mt][j][rh * 2], a1 = acc[mt][j][rh * 2 + 1];
                        p += a0 * a0 + a1 * a1;
                    }
                    p += __shfl_xor_sync(0xffffffffu, p, 1);
                    p += __shfl_xor_sync(0xffffffffu, p, 2);
                    if ((lane & 3) == 0)
                        rbuf[wx * 256 + wy * 32 + (lane >> 2) + mt * 16 + rh * 8] = p;
                }
            __syncthreads();
        }

        const float* lnw = (seg == 0) ? qlnw : klnw;
        float* dstbase = (seg == 0) ? outq : ((seg == 1) ? outk : outv);
        const float segscale = (seg == 0) ? 0.08838834764831845f : 1.0f;

#pragma unroll
        for (int mt = 0; mt < 2; mt++) {
#pragma unroll
            for (int rh = 0; rh < 2; rh++) {
                const int rloc = wy * 32 + (lane >> 2) + mt * 16 + rh * 8;
                const int r = m0 + rloc;
                const int b = r >> 12, t = r & 4095;
                float rq = 1.f;
                if (seg < 2)
                    rq = rsqrtf((rbuf[rloc] + rbuf[256 + rloc]) * (1.f / 128.f) + 1e-6f);

                float vals[16];
#pragma unroll
                for (int j = 0; j < 8; j++) {
                    int ld = wx * 64 + (j & 1) * 32 + (j >> 1) * 8 + (lane & 3) * 2;
                    float v0 = acc[mt][j][rh * 2], v1 = acc[mt][j][rh * 2 + 1];
                    if (seg < 2) {
                        v0 *= rq * lnw[ld];
                        v1 *= rq * lnw[ld + 1];
                    }
                    vals[j * 2] = v0;
                    vals[j * 2 + 1] = v1;
                }
                if (seg < 2 && wx == 0) {
#pragma unroll
                    for (int nt = 0; nt < 4; nt++) {
                        int d = nt * 8 + (lane & 3) * 2;
                        float2 c2 = *(const float2*)&g_ct[(size_t)r * 32 + d];
                        float2 s2 = *(const float2*)&g_st[(size_t)r * 32 + d];
                        float e0 = vals[nt * 4 + 0], e1 = vals[nt * 4 + 1];
                        float o0 = vals[nt * 4 + 2], o1 = vals[nt * 4 + 3];
                        vals[nt * 4 + 0] = e0 * c2.x - o0 * s2.x;
                        vals[nt * 4 + 1] = e1 * c2.y - o1 * s2.y;
                        vals[nt * 4 + 2] = o0 * c2.x + e0 * s2.x;
                        vals[nt * 4 + 3] = o1 * c2.y + e1 * s2.y;
                    }
                }
                size_t obase = ((size_t)(b * HH + h) * TT + t) * DD;
#pragma unroll
                for (int j = 0; j < 8; j++) {
                    int ld = wx * 64 + (j & 1) * 32 + (j >> 1) * 8 + (lane & 3) * 2;
                    *(float2*)(dstbase + obase + ld) =
                        make_float2(vals[j * 2] * segscale, vals[j * 2 + 1] * segscale);
                }
            }
        }
    } else {
        const int act = (seg == 3);
        const int ncol0 = (seg == 3) ? (n0 - O3) : n0;
        const int rbase = m0 + wy * 32 + (lane >> 2);
        const int cbase = ncol0 + wx * 64 + (lane & 3) * 2;
#pragma unroll
        for (int mt = 0; mt < 2; mt++) {
#pragma unroll
            for (int j = 0; j < 8; j++) {
                int nt = j >> 1, half = j & 1;
                int col = cbase + half * 32 + nt * 8;
                float v[4];
#pragma unroll
                for (int q = 0; q < 4; q++) {
                    float x = acc[mt][j][q];
                    v[q] = act ? (1.f / (1.f + expf(-x))) : x;
                }
                float* d0 = C + (size_t)(rbase + mt * 16) * Ntot + col;
                float* d1 = C + (size_t)(rbase + mt * 16 + 8) * Ntot + col;
                *(float2*)d0 = make_float2(v[0], v[1]);
                *(float2*)d1 = make_float2(v[2], v[3]);
            }
        }
    }
}

// ---------------- fp32 -> fp16 conversions (base-offset form) ----------------
#define CV_H (BB * TT * HDIM / 4)
#define CV_Q (O3 * HDIM / 4)
#define CV_G (HDIM * HDIM / 4)
#define CV_TOT (CV_H + CV_Q + 2 * CV_G)
__global__ void __launch_bounds__(256) k_cvt_all(const float* __restrict__ hidden,
                                                 const float* __restrict__ wq,
                                                 const float* __restrict__ wg,
                                                 const float* __restrict__ wd, int base) {
    int i = base + blockIdx.x * 256 + threadIdx.x;
    const float* src;
    __half* dst;
    int off;
    if (i < CV_H) {
        src = hidden; dst = g_hh; off = i;
    } else if (i < CV_H + CV_Q) {
        src = wq; dst = g_wqh; off = i - CV_H;
    } else if (i < CV_H + CV_Q + CV_G) {
        src = wg; dst = g_wgh; off = i - CV_H - CV_Q;
    } else {
        src = wd; dst = g_wdh; off = i - CV_H - CV_Q - CV_G;
    }
    float4 x = ((const float4*)src)[off];
    __half h[4] = {__float2half(x.x), __float2half(x.y), __float2half(x.z), __float2half(x.w)};
    ((uint2*)dst)[off] = *(uint2*)h;
}

// ---------------- rope cos/sin table ----------------------------------------
__global__ void __launch_bounds__(256) k_rope_table(const int* __restrict__ pos) {
    int idx = blockIdx.x * 256 + threadIdx.x;
    int bt = idx >> 5, d = idx & 31;
    float p = (float)pos[bt];
    float inv = exp2f(-(float)d * 0.4152410118609203f);
    float sn, cs;
    sincosf(p * inv, &sn, &cs);
    g_ct[idx] = cs;
    g_st[idx] = sn;
}

// ---------------- pass A: per (b,h,c): att(masked), intra = att@v, U ---------
#define QK_P 68
__global__ void __launch_bounds__(256, 1) k_chunk_local() {
    extern __shared__ __align__(16) float sm[];
    float* qsT = sm;
    float* ksT = qsT + 128 * QK_P;
    float* vs = ksT + 128 * QK_P;
    float* att = vs + 64 * 128;
    float* kdec = att + 64 * 65;

    const int tid = threadIdx.x;
    const int c = blockIdx.x & (NCH - 1);
    const int bh = blockIdx.x >> 6;
    const int h = bh & (HH - 1);
    const float slope = head_slope(h);
    const size_t tbase = ((size_t)bh * TT + c * CH) * DD;

#pragma unroll
    for (int l = 0; l < 8; l++) {
        int idx = tid + l * 256;
        int row = idx >> 5;
        int c0 = (idx & 31) << 2;
        float4 a = *(const float4*)(g_q + tbase + row * DD + c0);
        float4 b = *(const float4*)(g_k + tbase + row * DD + c0);
        float4 vv = *(const float4*)(g_v + tbase + row * DD + c0);
        qsT[(c0 + 0) * QK_P + row] = a.x;
        qsT[(c0 + 1) * QK_P + row] = a.y;
        qsT[(c0 + 2) * QK_P + row] = a.z;
        qsT[(c0 + 3) * QK_P + row] = a.w;
        ksT[(c0 + 0) * QK_P + row] = b.x;
        ksT[(c0 + 1) * QK_P + row] = b.y;
        ksT[(c0 + 2) * QK_P + row] = b.z;
        ksT[(c0 + 3) * QK_P + row] = b.w;
        *(float4*)&vs[row * DD + c0] = vv;
    }
    if (tid < 64) kdec[tid] = expf(slope * (float)(63 - tid));
    __syncthreads();

    const int tx = tid & 15, ty = tid >> 4;

    {
        ull acc2[4][2] = {};
#pragma unroll 4
        for (int d = 0; d < 128; d++) {
            float a[4], b[4];
            *(float4*)a = *(const float4*)&qsT[d * QK_P + 4 * ty];
            *(float4*)b = *(const float4*)&ksT[d * QK_P + 4 * tx];
            ull b01 = pk2(b[0], b[1]), b23 = pk2(b[2], b[3]);
#pragma unroll
            for (int i = 0; i < 4; i++) {
                ull ai = pk2(a[i], a[i]);
                fma2(acc2[i][0], ai, b01);
                fma2(acc2[i][1], ai, b23);
            }
        }
#pragma unroll
        for (int i = 0; i < 4; i++)
#pragma unroll
            for (int jp = 0; jp < 2; jp++) {
                float2 p = upk(acc2[i][jp]);
                int ri = 4 * ty + i, cj = 4 * tx + jp * 2;
                float m0 = (ri >= cj) ? expf(slope * (float)(ri - cj)) : 0.f;
                float m1 = (ri >= cj + 1) ? expf(slope * (float)(ri - cj - 1)) : 0.f;
                att[ri * 65 + cj] = p.x * m0;
                att[ri * 65 + cj + 1] = p.y * m1;
            }
    }
    __syncthreads();

    {
        ull acc2[4][4] = {};
#pragma unroll 2
        for (int j = 0; j < 64; j++) {
            float a[4];
#pragma unroll
            for (int r = 0; r < 4; r++) a[r] = att[(4 * ty + r) * 65 + j];
            float b[8];
            *(float4*)(b) = *(const float4*)&vs[j * DD + 8 * tx];
            *(float4*)(b + 4) = *(const float4*)&vs[j * DD + 8 * tx + 4];
            ull b2[4] = {pk2(b[0], b[1]), pk2(b[2], b[3]), pk2(b[4], b[5]), pk2(b[6], b[7])};
#pragma unroll
            for (int r = 0; r < 4; r++) {
                ull ar = pk2(a[r], a[r]);
#pragma unroll
                for (int e = 0; e < 4; e++) fma2(acc2[r][e], ar, b2[e]);
            }
        }
#pragma unroll
        for (int r = 0; r < 4; r++) {
            float2 p0 = upk(acc2[r][0]), p1 = upk(acc2[r][1]);
            float2 p2 = upk(acc2[r][2]), p3 = upk(acc2[r][3]);
            float* dst = g_o + tbase + (size_t)(4 * ty + r) * DD + 8 * tx;
            *(float4*)(dst) = make_float4(p0.x, p0.y, p1.x, p1.y);
            *(float4*)(dst + 4) = make_float4(p2.x, p2.y, p3.x, p3.y);
        }
    }

    {
        ull acc2[8][4] = {};
#pragma unroll 2
        for (int i = 0; i < 64; i++) {
            float kd = kdec[i];
            ull kd2 = pk2(kd, kd);
            float a[8];
#pragma unroll
            for (int r = 0; r < 8; r++) a[r] = ksT[(8 * ty + r) * QK_P + i];
            float b[8];
            *(float4*)(b) = *(const float4*)&vs[i * DD + 8 * tx];
            *(float4*)(b + 4) = *(const float4*)&vs[i * DD + 8 * tx + 4];
            ull b2[4];
            b2[0] = mul2(pk2(b[0], b[1]), kd2);
            b2[1] = mul2(pk2(b[2], b[3]), kd2);
            b2[2] = mul2(pk2(b[4], b[5]), kd2);
            b2[3] = mul2(pk2(b[6], b[7]), kd2);
#pragma unroll
            for (int r = 0; r < 8; r++) {
                ull ar = pk2(a[r], a[r]);
#pragma unroll
                for (int e = 0; e < 4; e++) fma2(acc2[r][e], ar, b2[e]);
            }
        }
        size_t ub = ((size_t)bh * NCH + c) * (DD * DD);
#pragma unroll
        for (int r = 0; r < 8; r++) {
            float2 p0 = upk(acc2[r][0]), p1 = upk(acc2[r][1]);
            float2 p2 = upk(acc2[r][2]), p3 = upk(acc2[r][3]);
            float* dst = g_U + ub + (size_t)(8 * ty + r) * DD + 8 * tx;
            *(float4*)(dst) = make_float4(p0.x, p0.y, p1.x, p1.y);
            *(float4*)(dst + 4) = make_float4(p2.x, p2.y, p3.x, p3.y);
        }
    }
}

// ---------------- pass B: decayed prefix scan (float4) -----------------------
__global__ void __launch_bounds__(256) k_scan() {
    int g = blockIdx.x * 256 + threadIdx.x;
    int bh = g >> 12;
    int de4 = g & 4095;
    float chdec = expf(head_slope(bh & (HH - 1)) * 64.f);
    size_t base = (size_t)bh * NCH * (DD * DD) + (size_t)de4 * 4;
    float4 s = make_float4(0.f, 0.f, 0.f, 0.f);
    for (int c = 0; c < NCH; c++) {
        size_t idx = base + (size_t)c * (DD * DD);
        *(float4*)(g_S + idx) = s;
        float4 u = *(const float4*)(g_U + idx);
        s.x = s.x * chdec + u.x;
        s.y = s.y * chdec + u.y;
        s.z = s.z * chdec + u.z;
        s.w = s.w * chdec + u.w;
    }
}

// ---- pass C: inter = (q*qdec)@S + intra, fused gnorm*gate -> onh fp16 -------
__global__ void __launch_bounds__(256, 1) k_inter(const float* __restrict__ gnw) {
    extern __shared__ __align__(16) float sm2[];
    float* qs = sm2;
    float* Ss = qs + 64 * 132;
    const int tid = threadIdx.x;
    const int c = blockIdx.x & (NCH - 1);
    const int bh = blockIdx.x >> 6;
    const int b = bh >> 4, h = bh & (HH - 1);
    const float slope = head_slope(h);
    const size_t tbase = ((size_t)bh * TT + c * CH) * DD;
    const size_t sbase = ((size_t)bh * NCH + c) * (DD * DD);

#pragma unroll
    for (int l = 0; l < 8; l++) {
        int idx = tid + l * 256;
        int row = idx >> 5;
        int c0 = (idx & 31) << 2;
        *(float4*)&qs[row * 132 + c0] = *(const float4*)(g_q + tbase + row * DD + c0);
    }
#pragma unroll
    for (int l = 0; l < 16; l++) {
        int idx = tid + l * 256;
        *(float4*)&Ss[idx * 4] = *(const float4*)(g_S + sbase + (size_t)idx * 4);
    }
    __syncthreads();

    const int tx = tid & 15, ty = tid >> 4;
    ull acc2[4][4] = {};
#pragma unroll 2
    for (int d = 0; d < 128; d++) {
        float a[4];
#pragma unroll
        for (int r = 0; r < 4; r++) a[r] = qs[(4 * ty + r) * 132 + d];
        float b[8];
        *(float4*)(b) = *(const float4*)&Ss[d * DD + 8 * tx];
        *(float4*)(b + 4) = *(const float4*)&Ss[d * DD + 8 * tx + 4];
        ull b2[4] = {pk2(b[0], b[1]), pk2(b[2], b[3]), pk2(b[4], b[5]), pk2(b[6], b[7])};
#pragma unroll
        for (int r = 0; r < 4; r++) {
            ull ar = pk2(a[r], a[r]);
#pragma unroll
            for (int e = 0; e < 4; e++) fma2(acc2[r][e], ar, b2[e]);
        }
    }

    const float4 w0 = *(const float4*)&gnw[h * DD + 8 * tx];
    const float4 w1 = *(const float4*)&gnw[h * DD + 8 * tx + 4];
#pragma unroll
    for (int r = 0; r < 4; r++) {
        int i = 4 * ty + r;
        float qd = expf(slope * (float)(i + 1));
        float acc[8];
        float2 p0 = upk(acc2[r][0]), p1 = upk(acc2[r][1]);
        float2 p2 = upk(acc2[r][2]), p3 = upk(acc2[r][3]);
        acc[0] = p0.x; acc[1] = p0.y; acc[2] = p1.x; acc[3] = p1.y;
        acc[4] = p2.x; acc[5] = p2.y; acc[6] = p3.x; acc[7] = p3.y;

        const float* osrc = g_o + tbase + (size_t)i * DD + 8 * tx;
        float4 c0 = *(const float4*)osrc;
        float4 c1 = *(const float4*)(osrc + 4);
        float v[8];
        v[0] = c0.x + acc[0] * qd;
        v[1] = c0.y + acc[1] * qd;
        v[2] = c0.z + acc[2] * qd;
        v[3] = c0.w + acc[3] * qd;
        v[4] = c1.x + acc[4] * qd;
        v[5] = c1.y + acc[5] * qd;
        v[6] = c1.z + acc[6] * qd;
        v[7] = c1.w + acc[7] * qd;
        float ss = 0.f;
#pragma unroll
        for (int e = 0; e < 8; e++) ss += v[e] * v[e];
        ss += __shfl_xor_sync(0xffffffffu, ss, 1);
        ss += __shfl_xor_sync(0xffffffffu, ss, 2);
        ss += __shfl_xor_sync(0xffffffffu, ss, 4);
        ss += __shfl_xor_sync(0xffffffffu, ss, 8);
        float rq = rsqrtf(ss * (1.f / 128.f) + 1e-6f);

        size_t bt = (size_t)b * TT + c * CH + i;
        const float* gp = g_gate + bt * HDIM + h * DD + 8 * tx;
        float4 g0 = *(const float4*)gp;
        float4 g1 = *(const float4*)(gp + 4);
        __half hb[8];
        hb[0] = __float2half(v[0] * rq * w0.x * g0.x);
        hb[1] = __float2half(v[1] * rq * w0.y * g0.y);
        hb[2] = __float2half(v[2] * rq * w0.z * g0.z);
        hb[3] = __float2half(v[3] * rq * w0.w * g0.w);
        hb[4] = __float2half(v[4] * rq * w1.x * g1.x);
        hb[5] = __float2half(v[5] * rq * w1.y * g1.y);
        hb[6] = __float2half(v[6] * rq * w1.z * g1.z);
        hb[7] = __float2half(v[7] * rq * w1.w * g1.w);
        *(uint4*)(g_onh + bt * HDIM + h * DD + 8 * tx) = *(uint4*)hb;
    }
}

// -----------------------------------------------------------------------------
extern "C" void kernel_launch(void* const* d_in, const int* in_sizes, int n_in,
                              void* d_out, int out_size) {
    const float* hidden = (const float*)d_in[0];
    const float* w_qkv = (const float*)d_in[1];
    const float* q_ln_w = (const float*)d_in[2];
    const float* k_ln_w = (const float*)d_in[3];
    const float* g_norm_w = (const float*)d_in[4];
    const float* w_g_proj = (const float*)d_in[5];
    const float* w_dense = (const float*)d_in[6];
    const int* pos = (const int*)d_in[7];
    float* out = (float*)d_out;

    void *p_gate, *p_hh, *p_wqh, *p_wgh, *p_wdh, *p_onh, *p_q, *p_k, *p_v;
    cudaGetSymbolAddress(&p_gate, g_gate);
    cudaGetSymbolAddress(&p_hh, g_hh);
    cudaGetSymbolAddress(&p_wqh, g_wqh);
    cudaGetSymbolAddress(&p_wgh, g_wgh);
    cudaGetSymbolAddress(&p_wdh, g_wdh);
    cudaGetSymbolAddress(&p_onh, g_onh);
    cudaGetSymbolAddress(&p_q, g_q);
    cudaGetSymbolAddress(&p_k, g_k);
    cudaGetSymbolAddress(&p_v, g_v);

    const int smem3 = (128 * QK_P * 2 + 64 * 128 + 64 * 65 + 64) * 4;  // 119296
    const int smem5 = (64 * 132 + 128 * 128) * 4;                      // 99328
    const int smemG = GNSTG * GSTG;                                    // 221184
    cudaFuncSetAttribute(k_chunk_local, cudaFuncAttributeMaxDynamicSharedMemorySize, smem3);
    cudaFuncSetAttribute(k_inter, cudaFuncAttributeMaxDynamicSharedMemorySize, smem5);
    cudaFuncSetAttribute(gemm_f16, cudaFuncAttributeMaxDynamicSharedMemorySize, smemG);

    const int cv_half = CV_TOT / 2;   // CV_TOT = 9437184/... even split (multiple of 256)
    // 0: conversions part 1
    k_cvt_all<<<cv_half / 256, 256>>>(hidden, w_qkv, w_g_proj, w_dense, 0);
    // 1: conversions part 2
    k_cvt_all<<<(CV_TOT - cv_half) / 256, 256>>>(hidden, w_qkv, w_g_proj, w_dense, cv_half);
    // 2: rope table
    k_rope_table<<<(BB * TT * 32) / 256, 256>>>(pos);
    // 3: merged qkv+gate GEMM (512 threads)  [ncu profile slot]
    gemm_f16<<<dim3(NQG / 128, (BB * TT) / 256), 512, smemG>>>(
        (const __half*)p_hh, (const __half*)p_wqh, (const __half*)p_wgh,
        (float*)p_gate, HDIM, 2,
        q_ln_w, k_ln_w, (float*)p_q, (float*)p_k, (float*)p_v);
    // 4: per-chunk local (att, intra, U)
    k_chunk_local<<<BB * HH * NCH, 256, smem3>>>();
    // 5: decayed prefix scan
    k_scan<<<(BB * HH * DD * DD / 4) / 256, 256>>>();
    // 6: inter + fused group-rmsnorm * gate -> onh fp16
    k_inter<<<BB * HH * NCH, 256, smem5>>>(g_norm_w);
    // 7: out = on @ w_dense^T (512 threads)
    gemm_f16<<<dim3(HDIM / 128, (BB * TT) / 256), 512, smemG>>>(
        (const __half*)p_onh, (const __half*)p_wdh, nullptr, out, HDIM, 0,
        nullptr, nullptr, nullptr, nullptr, nullptr);
}

// round 12
// speedup vs baseline: 5.1892x; 1.0817x over previous
#include <cuda_runtime.h>
#include <cuda_fp16.h>
#include <cstdint>

#define BB 2
#define TT 4096
#define HH 16
#define DD 128
#define HDIM 2048
#define O3 6144
#define NQG 8192
#define NCH 64
#define CH 64

typedef unsigned long long ull;

// ---------------- scratch (static device globals; no runtime allocation) ----
static __device__ float g_q[(size_t)BB * HH * TT * DD];       // (b,h,t,d)
static __device__ float g_k[(size_t)BB * HH * TT * DD];
static __device__ float g_v[(size_t)BB * HH * TT * DD];
static __device__ float g_o[(size_t)BB * HH * TT * DD];       // intra term
static __device__ float g_gate[(size_t)BB * TT * HDIM];       // sigmoid'ed, fp32
static __device__ float g_U[(size_t)BB * HH * NCH * DD * DD];
static __device__ float g_S[(size_t)BB * HH * NCH * DD * DD];
static __device__ float g_ct[(size_t)BB * TT * 32];
static __device__ float g_st[(size_t)BB * TT * 32];

// fp16 operands
static __device__ __half g_hh[(size_t)BB * TT * HDIM];
static __device__ __half g_wqh[(size_t)O3 * HDIM];
static __device__ __half g_wgh[(size_t)HDIM * HDIM];
static __device__ __half g_wdh[(size_t)HDIM * HDIM];
static __device__ __half g_onh[(size_t)BB * TT * HDIM];

__device__ __forceinline__ float head_slope(int h) {
    float a = (float)exp2(-0.5 * (double)(h + 1));
    return (float)(-(double)a * (1.0 - 11.0 / 31.0 + 1e-5));
}

__device__ __forceinline__ uint32_t s2u(const void* p) {
    uint32_t a;
    asm("{ .reg .u64 t; cvta.to.shared.u64 t, %1; cvt.u32.u64 %0, t; }" : "=r"(a) : "l"(p));
    return a;
}

// ---- packed f32x2 helpers ----
__device__ __forceinline__ ull pk2(float lo, float hi) {
    ull d;
    asm("mov.b64 %0, {%1, %2};" : "=l"(d) : "f"(lo), "f"(hi));
    return d;
}
__device__ __forceinline__ void fma2(ull& c, ull a, ull b) {
    asm("fma.rn.f32x2 %0, %1, %2, %3;" : "=l"(c) : "l"(a), "l"(b), "l"(c));
}
__device__ __forceinline__ float2 upk(ull d) {
    float2 f;
    asm("mov.b64 {%0, %1}, %2;" : "=f"(f.x), "=f"(f.y) : "l"(d));
    return f;
}

__device__ __forceinline__ void cp16(uint32_t dst, const void* src) {
    asm volatile("cp.async.cg.shared.global [%0], [%1], 16;" :: "r"(dst), "l"(src));
}

__device__ __forceinline__ void ldsm4(uint32_t& r0, uint32_t& r1, uint32_t& r2, uint32_t& r3,
                                      uint32_t addr) {
    asm volatile("ldmatrix.sync.aligned.m8n8.x4.shared.b16 {%0,%1,%2,%3}, [%4];"
                 : "=r"(r0), "=r"(r1), "=r"(r2), "=r"(r3) : "r"(addr));
}

__device__ __forceinline__ void mma16816(float* c, const uint32_t* a, const uint32_t* b) {
    asm volatile(
        "mma.sync.aligned.m16n8k16.row.col.f32.f16.f16.f32 "
        "{%0,%1,%2,%3}, {%4,%5,%6,%7}, {%8,%9}, {%0,%1,%2,%3};"
        : "+f"(c[0]), "+f"(c[1]), "+f"(c[2]), "+f"(c[3])
        : "r"(a[0]), "r"(a[1]), "r"(a[2]), "r"(a[3]), "r"(b[0]), "r"(b[1]));
}

// ======================= fp16 mma.sync GEMM, 512 threads =====================
#define GPITCH 144
#define GA_BYTES (256 * GPITCH)
#define GB_BYTES (128 * GPITCH)
#define GSTG (GA_BYTES + GB_BYTES)
#define GNSTG 4
#define GCHUNKS 32

__global__ void __launch_bounds__(512, 1) gemm_f16(
    const __half* __restrict__ Am, const __half* __restrict__ Bm,
    const __half* __restrict__ Bm2,
    float* __restrict__ C, int Ntot, int mode,
    const float* __restrict__ qlnw, const float* __restrict__ klnw,
    float* __restrict__ outq, float* __restrict__ outk, float* __restrict__ outv) {
    extern __shared__ __align__(128) char smem[];
    const uint32_t sbase = s2u(smem);
    const int tid = threadIdx.x;
    const int lane = tid & 31;
    const int warp = tid >> 5;
    const int wy = warp & 7;
    const int wx = warp >> 3;
    const int m0 = blockIdx.y * 256;
    const int n0 = blockIdx.x * 128;

    const __half* Bbase = (mode == 2 && n0 >= O3)
                              ? Bm2 + (size_t)(n0 - O3) * 2048
                              : Bm + (size_t)n0 * 2048;

    float acc[2][8][4];
#pragma unroll
    for (int i = 0; i < 2; i++)
#pragma unroll
        for (int j = 0; j < 8; j++)
#pragma unroll
            for (int q = 0; q < 4; q++) acc[i][j][q] = 0.f;

#define LOAD_CHUNK(c, s)                                                                \
    do {                                                                                \
        int _kk = (c) << 6;                                                             \
        const __half* _Ab = Am + (size_t)m0 * 2048 + _kk;                               \
        const __half* _Bb = Bbase + _kk;                                                \
        uint32_t _sa = sbase + (s) * GSTG;                                              \
        uint32_t _sb = _sa + GA_BYTES;                                                  \
        _Pragma("unroll") for (int t = 0; t < 4; t++) {                                 \
            int idx = tid + t * 512;                                                    \
            int row = idx >> 3, ch = idx & 7;                                           \
            cp16(_sa + row * GPITCH + ch * 16, _Ab + (size_t)row * 2048 + ch * 8);      \
        }                                                                               \
        _Pragma("unroll") for (int t = 0; t < 2; t++) {                                 \
            int idx = tid + t * 512;                                                    \
            int row = idx >> 3, ch = idx & 7;                                           \
            cp16(_sb + row * GPITCH + ch * 16, _Bb + (size_t)row * 2048 + ch * 8);      \
        }                                                                               \
    } while (0)

    for (int c = 0; c < 3; c++) {
        LOAD_CHUNK(c, c);
        asm volatile("cp.async.commit_group;" ::: "memory");
    }

    const uint32_t aoff = (uint32_t)(wy * 32 + (lane & 15)) * GPITCH + (lane >> 4) * 16;
    const int brow = (lane & 7) + ((lane >> 4) << 3);
    const uint32_t boff0 = GA_BYTES + (uint32_t)(wx * 64 + brow) * GPITCH + ((lane >> 3) & 1) * 16;

    for (int i = 0; i < GCHUNKS; i++) {
        const int s = i & 3;
        asm volatile("cp.async.wait_group 2;" ::: "memory");
        __syncthreads();
        {
            const int j = i + 3;
            if (j < GCHUNKS) LOAD_CHUNK(j, j & 3);
        }
        asm volatile("cp.async.commit_group;" ::: "memory");
        const uint32_t sa = sbase + s * GSTG;

#pragma unroll
        for (int ks = 0; ks < 4; ks++) {
            uint32_t a[2][4], b[4][2];
#pragma unroll
            for (int mt = 0; mt < 2; mt++)
                ldsm4(a[mt][0], a[mt][1], a[mt][2], a[mt][3],
                      sa + aoff + mt * 16 * GPITCH + ks * 32);
            ldsm4(b[0][0], b[0][1], b[1][0], b[1][1], sa + boff0 + ks * 32);
            ldsm4(b[2][0], b[2][1], b[3][0], b[3][1], sa + boff0 + 16 * GPITCH + ks * 32);
#pragma unroll
            for (int mt = 0; mt < 2; mt++)
#pragma unroll
                for (int nt = 0; nt < 4; nt++)
                    mma16816(acc[mt][nt * 2 + 0], a[mt], b[nt]);
            ldsm4(b[0][0], b[0][1], b[1][0], b[1][1], sa + boff0 + 32 * GPITCH + ks * 32);
            ldsm4(b[2][0], b[2][1], b[3][0], b[3][1], sa + boff0 + 48 * GPITCH + ks * 32);
#pragma unroll
            for (int mt = 0; mt < 2; mt++)
#pragma unroll
                for (int nt = 0; nt < 4; nt++)
                    mma16816(acc[mt][nt * 2 + 1], a[mt], b[nt]);
        }
    }

    asm volatile("cp.async.wait_group 0;" ::: "memory");
    __syncthreads();

    const int seg = (mode == 2) ? (n0 >> 11) : -1;

    if (mode == 2 && seg < 3) {
        const int h = (n0 >> 7) & 15;
        float* rbuf = (float*)smem;

        if (seg < 2) {
#pragma unroll
            for (int mt = 0; mt < 2; mt++)
#pragma unroll
                for (int rh = 0; rh < 2; rh++) {
                    float p = 0.f;
#pragma unroll
                    for (int j = 0; j < 8; j++) {
                        float a0 = acc[mt][j][rh * 2], a1 = acc[mt][j][rh * 2 + 1];
                        p += a0 * a0 + a1 * a1;
                    }
                    p += __shfl_xor_sync(0xffffffffu, p, 1);
                    p += __shfl_xor_sync(0xffffffffu, p, 2);
                    if ((lane & 3) == 0)
                        rbuf[wx * 256 + wy * 32 + (lane >> 2) + mt * 16 + rh * 8] = p;
                }
            __syncthreads();
        }

        const float* lnw = (seg == 0) ? qlnw : klnw;
        float* dstbase = (seg == 0) ? outq : ((seg == 1) ? outk : outv);
        const float segscale = (seg == 0) ? 0.08838834764831845f : 1.0f;

#pragma unroll
        for (int mt = 0; mt < 2; mt++) {
#pragma unroll
            for (int rh = 0; rh < 2; rh++) {
                const int rloc = wy * 32 + (lane >> 2) + mt * 16 + rh * 8;
                const int r = m0 + rloc;
                const int b = r >> 12, t = r & 4095;
                float rq = 1.f;
                if (seg < 2)
                    rq = rsqrtf((rbuf[rloc] + rbuf[256 + rloc]) * (1.f / 128.f) + 1e-6f);

                float vals[16];
#pragma unroll
                for (int j = 0; j < 8; j++) {
                    int ld = wx * 64 + (j & 1) * 32 + (j >> 1) * 8 + (lane & 3) * 2;
                    float v0 = acc[mt][j][rh * 2], v1 = acc[mt][j][rh * 2 + 1];
                    if (seg < 2) {
                        v0 *= rq * lnw[ld];
                        v1 *= rq * lnw[ld + 1];
                    }
                    vals[j * 2] = v0;
                    vals[j * 2 + 1] = v1;
                }
                if (seg < 2 && wx == 0) {
#pragma unroll
                    for (int nt = 0; nt < 4; nt++) {
                        int d = nt * 8 + (lane & 3) * 2;
                        float2 c2 = *(const float2*)&g_ct[(size_t)r * 32 + d];
                        float2 s2 = *(const float2*)&g_st[(size_t)r * 32 + d];
                        float e0 = vals[nt * 4 + 0], e1 = vals[nt * 4 + 1];
                        float o0 = vals[nt * 4 + 2], o1 = vals[nt * 4 + 3];
                        vals[nt * 4 + 0] = e0 * c2.x - o0 * s2.x;
                        vals[nt * 4 + 1] = e1 * c2.y - o1 * s2.y;
                        vals[nt * 4 + 2] = o0 * c2.x + e0 * s2.x;
                        vals[nt * 4 + 3] = o1 * c2.y + e1 * s2.y;
                    }
                }
                size_t obase = ((size_t)(b * HH + h) * TT + t) * DD;
#pragma unroll
                for (int j = 0; j < 8; j++) {
                    int ld = wx * 64 + (j & 1) * 32 + (j >> 1) * 8 + (lane & 3) * 2;
                    *(float2*)(dstbase + obase + ld) =
                        make_float2(vals[j * 2] * segscale, vals[j * 2 + 1] * segscale);
                }
            }
        }
    } else {
        const int act = (seg == 3);
        const int ncol0 = (seg == 3) ? (n0 - O3) : n0;
        const int rbase = m0 + wy * 32 + (lane >> 2);
        const int cbase = ncol0 + wx * 64 + (lane & 3) * 2;
#pragma unroll
        for (int mt = 0; mt < 2; mt++) {
#pragma unroll
            for (int j = 0; j < 8; j++) {
                int nt = j >> 1, half = j & 1;
                int col = cbase + half * 32 + nt * 8;
                float v[4];
#pragma unroll
                for (int q = 0; q < 4; q++) {
                    float x = acc[mt][j][q];
                    v[q] = act ? (1.f / (1.f + expf(-x))) : x;
                }
                float* d0 = C + (size_t)(rbase + mt * 16) * Ntot + col;
                float* d1 = C + (size_t)(rbase + mt * 16 + 8) * Ntot + col;
                *(float2*)d0 = make_float2(v[0], v[1]);
                *(float2*)d1 = make_float2(v[2], v[3]);
            }
        }
    }
}

// ---------------- fp32 -> fp16 conversions ----------------------------------
#define CV_H (BB * TT * HDIM / 4)
#define CV_Q (O3 * HDIM / 4)
#define CV_G (HDIM * HDIM / 4)
#define CV_TOT (CV_H + CV_Q + 2 * CV_G)
__global__ void __launch_bounds__(256) k_cvt_all(const float* __restrict__ hidden,
                                                 const float* __restrict__ wq,
                                                 const float* __restrict__ wg,
                                                 const float* __restrict__ wd) {
    int i = blockIdx.x * 256 + threadIdx.x;
    const float* src;
    __half* dst;
    int off;
    if (i < CV_H) {
        src = hidden; dst = g_hh; off = i;
    } else if (i < CV_H + CV_Q) {
        src = wq; dst = g_wqh; off = i - CV_H;
    } else if (i < CV_H + CV_Q + CV_G) {
        src = wg; dst = g_wgh; off = i - CV_H - CV_Q;
    } else {
        src = wd; dst = g_wdh; off = i - CV_H - CV_Q - CV_G;
    }
    float4 x = ((const float4*)src)[off];
    __half h[4] = {__float2half(x.x), __float2half(x.y), __float2half(x.z), __float2half(x.w)};
    ((uint2*)dst)[off] = *(uint2*)h;
}

// ---------------- rope cos/sin table ----------------------------------------
__global__ void __launch_bounds__(256) k_rope_table(const int* __restrict__ pos) {
    int idx = blockIdx.x * 256 + threadIdx.x;
    int bt = idx >> 5, d = idx & 31;
    float p = (float)pos[bt];
    float inv = exp2f(-(float)d * 0.4152410118609203f);
    float sn, cs;
    sincosf(p * inv, &sn, &cs);
    g_ct[idx] = cs;
    g_st[idx] = sn;
}

// ========== pass A (HMMA): att(masked) / intra=att@v / U=(k*kdec)^T v ========
// smem planes (fp16 hi/lo): q[64][QP], k[64][QP], vT[128][VP], kdT[128][VP],
// att[64][AP]. 3-term split per GEMM: hi*hi + lo*hi + hi*lo (error ~2^-22).
#define QP 136
#define VP 72
#define AP 72
// half-offsets of planes
#define HQ_H 0
#define HQ_L 8704
#define HK_H 17408
#define HK_L 26112
#define HV_H 34816
#define HV_L 44032
#define HD_H 53248
#define HD_L 62464
#define HA_H 71680
#define HA_L 76288
#define SMEM_CL (80896 * 2)

__global__ void __launch_bounds__(256, 1) k_chunk_local() {
    extern __shared__ __align__(128) char sm[];
    const uint32_t sb = s2u(sm);
    __half* hp = (__half*)sm;
    const int tid = threadIdx.x;
    const int lane = tid & 31, warp = tid >> 5;
    const int c = blockIdx.x & (NCH - 1);
    const int bh = blockIdx.x >> 6;
    const int h = bh & (HH - 1);
    const float slope = head_slope(h);
    const size_t tbase = ((size_t)bh * TT + c * CH) * DD;

    // ---- stage: fp32 global -> hi/lo fp16 planes (vT, kdT transposed) ----
#pragma unroll
    for (int l = 0; l < 8; l++) {
        int idx = tid + l * 256;
        int row = idx >> 5;          // t (0..63)
        int c0 = (idx & 31) << 2;    // d
        float4 qa = *(const float4*)(g_q + tbase + row * DD + c0);
        float4 ka = *(const float4*)(g_k + tbase + row * DD + c0);
        float4 va = *(const float4*)(g_v + tbase + row * DD + c0);
        float kd = expf(slope * (float)(63 - row));
        float qf[4] = {qa.x, qa.y, qa.z, qa.w};
        float kf[4] = {ka.x, ka.y, ka.z, ka.w};
        float vf[4] = {va.x, va.y, va.z, va.w};
        __half hh[4], ll[4];
#pragma unroll
        for (int j = 0; j < 4; j++) {
            hh[j] = __float2half(qf[j]);
            ll[j] = __float2half(qf[j] - __half2float(hh[j]));
        }
        *(__half2*)(hp + HQ_H + row * QP + c0) = *(__half2*)&hh[0];
        *(__half2*)(hp + HQ_H + row * QP + c0 + 2) = *(__half2*)&hh[2];
        *(__half2*)(hp + HQ_L + row * QP + c0) = *(__half2*)&ll[0];
        *(__half2*)(hp + HQ_L + row * QP + c0 + 2) = *(__half2*)&ll[2];
#pragma unroll
        for (int j = 0; j < 4; j++) {
            hh[j] = __float2half(kf[j]);
            ll[j] = __float2half(kf[j] - __half2float(hh[j]));
        }
        *(__half2*)(hp + HK_H + row * QP + c0) = *(__half2*)&hh[0];
        *(__half2*)(hp + HK_H + row * QP + c0 + 2) = *(__half2*)&hh[2];
        *(__half2*)(hp + HK_L + row * QP + c0) = *(__half2*)&ll[0];
        *(__half2*)(hp + HK_L + row * QP + c0 + 2) = *(__half2*)&ll[2];
#pragma unroll
        for (int j = 0; j < 4; j++) {
            int d = c0 + j;
            __half vh = __float2half(vf[j]);
            hp[HV_H + d * VP + row] = vh;
            hp[HV_L + d * VP + row] = __float2half(vf[j] - __half2float(vh));
            float kv = kf[j] * kd;
            __half dh = __float2half(kv);
            hp[HD_H + d * VP + row] = dh;
            hp[HD_L + d * VP + row] = __float2half(kv - __half2float(dh));
        }
    }
    __syncthreads();

    const int wy = warp & 3, wx = warp >> 2;
    const int brow = (lane & 7) + ((lane >> 4) << 3);
    const uint32_t acol = (uint32_t)(lane >> 4) * 16;        // A k-group byte offset
    const uint32_t bcol = (uint32_t)((lane >> 3) & 1) * 16;  // B k-group byte offset

    // ---- att = q @ k^T, masked-decayed, -> att hi/lo planes ----
    {
        const uint32_t aqh = sb + HQ_H * 2 + ((wy * 16 + (lane & 15)) * QP) * 2 + acol;
        const uint32_t aql = aqh + (HQ_L - HQ_H) * 2;
        const uint32_t bkh0 = sb + HK_H * 2 + ((wx * 32 + brow) * QP) * 2 + bcol;
        const uint32_t bkh1 = bkh0 + 16 * QP * 2;
        const uint32_t bkl0 = bkh0 + (HK_L - HK_H) * 2;
        const uint32_t bkl1 = bkl0 + 16 * QP * 2;

        float ca[4][4];
#pragma unroll
        for (int j = 0; j < 4; j++)
#pragma unroll
            for (int q = 0; q < 4; q++) ca[j][q] = 0.f;

#pragma unroll
        for (int ks = 0; ks < 8; ks++) {
            const uint32_t ko = ks * 32;
            uint32_t Ah[4], Al[4], BH[4][2], BL[4][2];
            ldsm4(Ah[0], Ah[1], Ah[2], Ah[3], aqh + ko);
            ldsm4(Al[0], Al[1], Al[2], Al[3], aql + ko);
            ldsm4(BH[0][0], BH[0][1], BH[1][0], BH[1][1], bkh0 + ko);
            ldsm4(BH[2][0], BH[2][1], BH[3][0], BH[3][1], bkh1 + ko);
            ldsm4(BL[0][0], BL[0][1], BL[1][0], BL[1][1], bkl0 + ko);
            ldsm4(BL[2][0], BL[2][1], BL[3][0], BL[3][1], bkl1 + ko);
#pragma unroll
            for (int j = 0; j < 4; j++) {
                mma16816(ca[j], Ah, BH[j]);
                mma16816(ca[j], Al, BH[j]);
                mma16816(ca[j], Ah, BL[j]);
            }
        }

        const int r0 = wy * 16 + (lane >> 2);
#pragma unroll
        for (int j = 0; j < 4; j++) {
            int cj = wx * 32 + j * 8 + (lane & 3) * 2;
            float v00 = (r0 >= cj) ? ca[j][0] * expf(slope * (float)(r0 - cj)) : 0.f;
            float v01 = (r0 >= cj + 1) ? ca[j][1] * expf(slope * (float)(r0 - cj - 1)) : 0.f;
            int r1 = r0 + 8;
            float v10 = (r1 >= cj) ? ca[j][2] * expf(slope * (float)(r1 - cj)) : 0.f;
            float v11 = (r1 >= cj + 1) ? ca[j][3] * expf(slope * (float)(r1 - cj - 1)) : 0.f;
            __half h00 = __float2half(v00), h01 = __float2half(v01);
            __half h10 = __float2half(v10), h11 = __float2half(v11);
            __half l00 = __float2half(v00 - __half2float(h00));
            __half l01 = __float2half(v01 - __half2float(h01));
            __half l10 = __float2half(v10 - __half2float(h10));
            __half l11 = __float2half(v11 - __half2float(h11));
            __half ph0[2] = {h00, h01}, ph1[2] = {h10, h11};
            __half pl0[2] = {l00, l01}, pl1[2] = {l10, l11};
            *(__half2*)(hp + HA_H + r0 * AP + cj) = *(__half2*)ph0;
            *(__half2*)(hp + HA_H + r1 * AP + cj) = *(__half2*)ph1;
            *(__half2*)(hp + HA_L + r0 * AP + cj) = *(__half2*)pl0;
            *(__half2*)(hp + HA_L + r1 * AP + cj) = *(__half2*)pl1;
        }
    }
    __syncthreads();

    // ---- intra = att @ vT^T  and  U = kdT @ vT^T  (shared B fragments) ----
    {
        const uint32_t aah = sb + HA_H * 2 + ((wy * 16 + (lane & 15)) * AP) * 2 + acol;
        const uint32_t aal = aah + (HA_L - HA_H) * 2;
        uint32_t adh[2], adl[2], bvh[4], bvl[4];
#pragma unroll
        for (int mb = 0; mb < 2; mb++) {
            adh[mb] = sb + HD_H * 2 + ((wy * 32 + mb * 16 + (lane & 15)) * VP) * 2 + acol;
            adl[mb] = adh[mb] + (HD_L - HD_H) * 2;
        }
#pragma unroll
        for (int g = 0; g < 4; g++) {
            bvh[g] = sb + HV_H * 2 + ((wx * 64 + g * 16 + brow) * VP) * 2 + bcol;
            bvl[g] = bvh[g] + (HV_L - HV_H) * 2;
        }

        float ci[8][4], cu[2][8][4];
#pragma unroll
        for (int j = 0; j < 8; j++)
#pragma unroll
            for (int q = 0; q < 4; q++) {
                ci[j][q] = 0.f;
                cu[0][j][q] = 0.f;
                cu[1][j][q] = 0.f;
            }

#pragma unroll
        for (int ks = 0; ks < 4; ks++) {
            const uint32_t ko = ks * 32;
            uint32_t BH[8][2], BL[8][2];
#pragma unroll
            for (int g = 0; g < 4; g++) {
                ldsm4(BH[2 * g][0], BH[2 * g][1], BH[2 * g + 1][0], BH[2 * g + 1][1],
                      bvh[g] + ko);
                ldsm4(BL[2 * g][0], BL[2 * g][1], BL[2 * g + 1][0], BL[2 * g + 1][1],
                      bvl[g] + ko);
            }
            uint32_t Aah[4], Aal[4], Dh[2][4], Dl[2][4];
            ldsm4(Aah[0], Aah[1], Aah[2], Aah[3], aah + ko);
            ldsm4(Aal[0], Aal[1], Aal[2], Aal[3], aal + ko);
#pragma unroll
            for (int mb = 0; mb < 2; mb++) {
                ldsm4(Dh[mb][0], Dh[mb][1], Dh[mb][2], Dh[mb][3], adh[mb] + ko);
                ldsm4(Dl[mb][0], Dl[mb][1], Dl[mb][2], Dl[mb][3], adl[mb] + ko);
            }
#pragma unroll
            for (int j = 0; j < 8; j++) {
                mma16816(ci[j], Aah, BH[j]);
                mma16816(ci[j], Aal, BH[j]);
                mma16816(ci[j], Aah, BL[j]);
#pragma unroll
                for (int mb = 0; mb < 2; mb++) {
                    mma16816(cu[mb][j], Dh[mb], BH[j]);
                    mma16816(cu[mb][j], Dl[mb], BH[j]);
                    mma16816(cu[mb][j], Dh[mb], BL[j]);
                }
            }
        }

        // intra -> g_o
        const int r0 = wy * 16 + (lane >> 2);
#pragma unroll
        for (int j = 0; j < 8; j++) {
            int d = wx * 64 + j * 8 + (lane & 3) * 2;
            *(float2*)(g_o + tbase + (size_t)r0 * DD + d) = make_float2(ci[j][0], ci[j][1]);
            *(float2*)(g_o + tbase + (size_t)(r0 + 8) * DD + d) = make_float2(ci[j][2], ci[j][3]);
        }
        // U -> g_U
        const size_t ub = ((size_t)bh * NCH + c) * (DD * DD);
#pragma unroll
        for (int mb = 0; mb < 2; mb++) {
            int m0r = wy * 32 + mb * 16 + (lane >> 2);
#pragma unroll
            for (int j = 0; j < 8; j++) {
                int d = wx * 64 + j * 8 + (lane & 3) * 2;
                *(float2*)(g_U + ub + (size_t)m0r * DD + d) =
                    make_float2(cu[mb][j][0], cu[mb][j][1]);
                *(float2*)(g_U + ub + (size_t)(m0r + 8) * DD + d) =
                    make_float2(cu[mb][j][2], cu[mb][j][3]);
            }
        }
    }
}

// ---------------- pass B: decayed prefix scan (float4) -----------------------
__global__ void __launch_bounds__(256) k_scan() {
    int g = blockIdx.x * 256 + threadIdx.x;
    int bh = g >> 12;
    int de4 = g & 4095;
    float chdec = expf(head_slope(bh & (HH - 1)) * 64.f);
    size_t base = (size_t)bh * NCH * (DD * DD) + (size_t)de4 * 4;
    float4 s = make_float4(0.f, 0.f, 0.f, 0.f);
    for (int c = 0; c < NCH; c++) {
        size_t idx = base + (size_t)c * (DD * DD);
        *(float4*)(g_S + idx) = s;
        float4 u = *(const float4*)(g_U + idx);
        s.x = s.x * chdec + u.x;
        s.y = s.y * chdec + u.y;
        s.z = s.z * chdec + u.z;
        s.w = s.w * chdec + u.w;
    }
}

// ---- pass C: inter = (q*qdec)@S + intra, fused gnorm*gate -> onh fp16 -------
__global__ void __launch_bounds__(256, 1) k_inter(const float* __restrict__ gnw) {
    extern __shared__ __align__(16) float sm2[];
    float* qs = sm2;
    float* Ss = qs + 64 * 132;
    const int tid = threadIdx.x;
    const int c = blockIdx.x & (NCH - 1);
    const int bh = blockIdx.x >> 6;
    const int b = bh >> 4, h = bh & (HH - 1);
    const float slope = head_slope(h);
    const size_t tbase = ((size_t)bh * TT + c * CH) * DD;
    const size_t sbase = ((size_t)bh * NCH + c) * (DD * DD);

#pragma unroll
    for (int l = 0; l < 8; l++) {
        int idx = tid + l * 256;
        int row = idx >> 5;
        int c0 = (idx & 31) << 2;
        *(float4*)&qs[row * 132 + c0] = *(const float4*)(g_q + tbase + row * DD + c0);
    }
#pragma unroll
    for (int l = 0; l < 16; l++) {
        int idx = tid + l * 256;
        *(float4*)&Ss[idx * 4] = *(const float4*)(g_S + sbase + (size_t)idx * 4);
    }
    __syncthreads();

    const int tx = tid & 15, ty = tid >> 4;
    ull acc2[4][4] = {};
#pragma unroll 2
    for (int d = 0; d < 128; d++) {
        float a[4];
#pragma unroll
        for (int r = 0; r < 4; r++) a[r] = qs[(4 * ty + r) * 132 + d];
        float b[8];
        *(float4*)(b) = *(const float4*)&Ss[d * DD + 8 * tx];
        *(float4*)(b + 4) = *(const float4*)&Ss[d * DD + 8 * tx + 4];
        ull b2[4] = {pk2(b[0], b[1]), pk2(b[2], b[3]), pk2(b[4], b[5]), pk2(b[6], b[7])};
#pragma unroll
        for (int r = 0; r < 4; r++) {
            ull ar = pk2(a[r], a[r]);
#pragma unroll
            for (int e = 0; e < 4; e++) fma2(acc2[r][e], ar, b2[e]);
        }
    }

    const float4 w0 = *(const float4*)&gnw[h * DD + 8 * tx];
    const float4 w1 = *(const float4*)&gnw[h * DD + 8 * tx + 4];
#pragma unroll
    for (int r = 0; r < 4; r++) {
        int i = 4 * ty + r;
        float qd = expf(slope * (float)(i + 1));
        float acc[8];
        float2 p0 = upk(acc2[r][0]), p1 = upk(acc2[r][1]);
        float2 p2 = upk(acc2[r][2]), p3 = upk(acc2[r][3]);
        acc[0] = p0.x; acc[1] = p0.y; acc[2] = p1.x; acc[3] = p1.y;
        acc[4] = p2.x; acc[5] = p2.y; acc[6] = p3.x; acc[7] = p3.y;

        const float* osrc = g_o + tbase + (size_t)i * DD + 8 * tx;
        float4 c0 = *(const float4*)osrc;
        float4 c1 = *(const float4*)(osrc + 4);
        float v[8];
        v[0] = c0.x + acc[0] * qd;
        v[1] = c0.y + acc[1] * qd;
        v[2] = c0.z + acc[2] * qd;
        v[3] = c0.w + acc[3] * qd;
        v[4] = c1.x + acc[4] * qd;
        v[5] = c1.y + acc[5] * qd;
        v[6] = c1.z + acc[6] * qd;
        v[7] = c1.w + acc[7] * qd;
        float ss = 0.f;
#pragma unroll
        for (int e = 0; e < 8; e++) ss += v[e] * v[e];
        ss += __shfl_xor_sync(0xffffffffu, ss, 1);
        ss += __shfl_xor_sync(0xffffffffu, ss, 2);
        ss += __shfl_xor_sync(0xffffffffu, ss, 4);
        ss += __shfl_xor_sync(0xffffffffu, ss, 8);
        float rq = rsqrtf(ss * (1.f / 128.f) + 1e-6f);

        size_t bt = (size_t)b * TT + c * CH + i;
        const float* gp = g_gate + bt * HDIM + h * DD + 8 * tx;
        float4 g0 = *(const float4*)gp;
        float4 g1 = *(const float4*)(gp + 4);
        __half hb[8];
        hb[0] = __float2half(v[0] * rq * w0.x * g0.x);
        hb[1] = __float2half(v[1] * rq * w0.y * g0.y);
        hb[2] = __float2half(v[2] * rq * w0.z * g0.z);
        hb[3] = __float2half(v[3] * rq * w0.w * g0.w);
        hb[4] = __float2half(v[4] * rq * w1.x * g1.x);
        hb[5] = __float2half(v[5] * rq * w1.y * g1.y);
        hb[6] = __float2half(v[6] * rq * w1.z * g1.z);
        hb[7] = __float2half(v[7] * rq * w1.w * g1.w);
        *(uint4*)(g_onh + bt * HDIM + h * DD + 8 * tx) = *(uint4*)hb;
    }
}

// -----------------------------------------------------------------------------
extern "C" void kernel_launch(void* const* d_in, const int* in_sizes, int n_in,
                              void* d_out, int out_size) {
    const float* hidden = (const float*)d_in[0];
    const float* w_qkv = (const float*)d_in[1];
    const float* q_ln_w = (const float*)d_in[2];
    const float* k_ln_w = (const float*)d_in[3];
    const float* g_norm_w = (const float*)d_in[4];
    const float* w_g_proj = (const float*)d_in[5];
    const float* w_dense = (const float*)d_in[6];
    const int* pos = (const int*)d_in[7];
    float* out = (float*)d_out;

    void *p_gate, *p_hh, *p_wqh, *p_wgh, *p_wdh, *p_onh, *p_q, *p_k, *p_v;
    cudaGetSymbolAddress(&p_gate, g_gate);
    cudaGetSymbolAddress(&p_hh, g_hh);
    cudaGetSymbolAddress(&p_wqh, g_wqh);
    cudaGetSymbolAddress(&p_wgh, g_wgh);
    cudaGetSymbolAddress(&p_wdh, g_wdh);
    cudaGetSymbolAddress(&p_onh, g_onh);
    cudaGetSymbolAddress(&p_q, g_q);
    cudaGetSymbolAddress(&p_k, g_k);
    cudaGetSymbolAddress(&p_v, g_v);

    const int smem5 = (64 * 132 + 128 * 128) * 4;  // 99328
    const int smemG = GNSTG * GSTG;                // 221184
    cudaFuncSetAttribute(k_chunk_local, cudaFuncAttributeMaxDynamicSharedMemorySize, SMEM_CL);
    cudaFuncSetAttribute(k_inter, cudaFuncAttributeMaxDynamicSharedMemorySize, smem5);
    cudaFuncSetAttribute(gemm_f16, cudaFuncAttributeMaxDynamicSharedMemorySize, smemG);

    // 0: all fp32->fp16 conversions
    k_cvt_all<<<CV_TOT / 256, 256>>>(hidden, w_qkv, w_g_proj, w_dense);
    // 1: rope table
    k_rope_table<<<(BB * TT * 32) / 256, 256>>>(pos);
    // 2: merged qkv+gate GEMM
    gemm_f16<<<dim3(NQG / 128, (BB * TT) / 256), 512, smemG>>>(
        (const __half*)p_hh, (const __half*)p_wqh, (const __half*)p_wgh,
        (float*)p_gate, HDIM, 2,
        q_ln_w, k_ln_w, (float*)p_q, (float*)p_k, (float*)p_v);
    // 3: per-chunk local (HMMA att/intra/U)  [ncu profile slot]
    k_chunk_local<<<BB * HH * NCH, 256, SMEM_CL>>>();
    // 4: decayed prefix scan
    k_scan<<<(BB * HH * DD * DD / 4) / 256, 256>>>();
    // 5: inter + fused group-rmsnorm * gate -> onh fp16
    k_inter<<<BB * HH * NCH, 256, smem5>>>(g_norm_w);
    // 6: out = on @ w_dense^T
    gemm_f16<<<dim3(HDIM / 128, (BB * TT) / 256), 512, smemG>>>(
        (const __half*)p_onh, (const __half*)p_wdh, nullptr, out, HDIM, 0,
        nullptr, nullptr, nullptr, nullptr, nullptr);
}